// round 1
// baseline (speedup 1.0000x reference)
#include <cuda_runtime.h>
#include <cuda_bf16.h>
#include <math.h>

// Problem constants
constexpr int NB = 16;      // batch
constexpr int C  = 512;     // CIO == CHID
constexpr int L  = 384;     // seq len
constexpr int H  = 8;       // heads
constexpr int D  = 64;      // dim head
constexpr int ME = 384;     // MAXEMBED

// Scratch (device globals — no allocation allowed)
__device__ float g_x0[NB * C * L];
__device__ float g_x1[NB * C * L];
__device__ float g_q [NB * C * L];
__device__ float g_k [NB * C * L];
__device__ float g_v [NB * C * L];
__device__ float g_att[NB * C * L];
__device__ float g_gate[NB * H * L];
__device__ float g_scores[(size_t)NB * H * L * L];   // 75.5 MB, reused for attn

// ---------------------------------------------------------------------------
// 1) Preprocess: x0 = x + xorg*vorg_res[g];  x1 = x + xorg*qkorg[g] + abspos*qkpos[g]
// ---------------------------------------------------------------------------
__global__ void prep_kernel(const float* __restrict__ x,
                            const float* __restrict__ xorg,
                            const float* __restrict__ abspos,
                            const float* __restrict__ qkpos,
                            const float* __restrict__ qkorg,
                            const float* __restrict__ vorg) {
    int i = blockIdx.x * blockDim.x + threadIdx.x;
    if (i >= NB * C * L) return;
    int c = (i / L) % C;
    int g = c >> 3;                       // DIMGROUP = 8
    float xv = x[i], xo = xorg[i], ap = abspos[i];
    g_x0[i] = xv + xo * vorg[g];
    g_x1[i] = xv + xo * qkorg[g] + ap * qkpos[g];
}

// ---------------------------------------------------------------------------
// 2) Weight GEMM: Out[b][o][l] = sum_c W[o][c] * X[b][c][l] (+ bias[o])
//    M = 512, K = 512, N_cols = L = 384.  Tile 64x64x16, 256 threads, 4x4/thread.
// ---------------------------------------------------------------------------
template <bool BIAS>
__global__ void gemm_wx_kernel(const float* __restrict__ W,
                               const float* __restrict__ X,
                               float* __restrict__ Out,
                               const float* __restrict__ bias) {
    constexpr int KK = 512;
    __shared__ float As[16][68];   // [k][m], padded
    __shared__ float Bs[16][68];   // [k][n]
    int b = blockIdx.z;
    const float* Xb = X + (size_t)b * KK * L;
    float* Ob = Out + (size_t)b * 512 * L;
    int m0 = blockIdx.x * 64, n0 = blockIdx.y * 64;
    int tid = threadIdx.x;

    int lr  = tid >> 2;           // A loader: m row 0..63
    int lc4 = (tid & 3) << 2;     // A loader: k chunk 0,4,8,12
    int br  = tid >> 4;           // B loader: k row 0..15
    int bc4 = (tid & 15) << 2;    // B loader: n chunk
    int tm  = (tid >> 4) << 2;
    int tn  = (tid & 15) << 2;

    float acc[4][4] = {};
    for (int k0 = 0; k0 < KK; k0 += 16) {
        float4 a = *(const float4*)(W + (size_t)(m0 + lr) * KK + k0 + lc4);
        As[lc4 + 0][lr] = a.x; As[lc4 + 1][lr] = a.y;
        As[lc4 + 2][lr] = a.z; As[lc4 + 3][lr] = a.w;
        float4 bb = *(const float4*)(Xb + (size_t)(k0 + br) * L + n0 + bc4);
        *(float4*)&Bs[br][bc4] = bb;
        __syncthreads();
#pragma unroll
        for (int kk = 0; kk < 16; kk++) {
            float4 av = *(const float4*)&As[kk][tm];
            float4 bv = *(const float4*)&Bs[kk][tn];
            float ar[4] = {av.x, av.y, av.z, av.w};
            float brr[4] = {bv.x, bv.y, bv.z, bv.w};
#pragma unroll
            for (int ii = 0; ii < 4; ii++)
#pragma unroll
                for (int jj = 0; jj < 4; jj++)
                    acc[ii][jj] += ar[ii] * brr[jj];
        }
        __syncthreads();
    }
#pragma unroll
    for (int ii = 0; ii < 4; ii++) {
        float bval = BIAS ? bias[m0 + tm + ii] : 0.0f;
#pragma unroll
        for (int jj = 0; jj < 4; jj++)
            Ob[(size_t)(m0 + tm + ii) * L + n0 + tn + jj] = acc[ii][jj] + bval;
    }
}

// ---------------------------------------------------------------------------
// 3) Gate: gate[n][h][l] = sum_c gate_w[h][c] * x[n][c][l] + gate_b[h]
// ---------------------------------------------------------------------------
__global__ void gate_kernel(const float* __restrict__ x,
                            const float* __restrict__ gate_w,
                            const float* __restrict__ gate_b) {
    int z = blockIdx.x;            // n*H + h
    int n = z / H, h = z % H;
    int l = threadIdx.x;           // 384 threads
    const float* xb = x + (size_t)n * C * L + l;
    const float* w = gate_w + h * C;
    float acc = gate_b[h];
    for (int c = 0; c < C; c++)
        acc = fmaf(w[c], xb[(size_t)c * L], acc);
    g_gate[(size_t)z * L + l] = acc;
}

// ---------------------------------------------------------------------------
// 4) Scores: S[z][i][j] = sum_d Q[z][d][i] * K[z][d][j]   (z = n*H + h, K-dim = 64)
// ---------------------------------------------------------------------------
__global__ void scores_kernel() {
    __shared__ float Qs[16][68];
    __shared__ float Ks[16][68];
    int z = blockIdx.z;
    const float* Qb = g_q + (size_t)z * D * L;
    const float* Kb = g_k + (size_t)z * D * L;
    float* Sb = g_scores + (size_t)z * L * L;
    int m0 = blockIdx.x * 64, n0 = blockIdx.y * 64;
    int tid = threadIdx.x;
    int br = tid >> 4, bc4 = (tid & 15) << 2;
    int tm = (tid >> 4) << 2, tn = (tid & 15) << 2;

    float acc[4][4] = {};
    for (int k0 = 0; k0 < D; k0 += 16) {
        *(float4*)&Qs[br][bc4] = *(const float4*)(Qb + (size_t)(k0 + br) * L + m0 + bc4);
        *(float4*)&Ks[br][bc4] = *(const float4*)(Kb + (size_t)(k0 + br) * L + n0 + bc4);
        __syncthreads();
#pragma unroll
        for (int kk = 0; kk < 16; kk++) {
            float4 av = *(const float4*)&Qs[kk][tm];
            float4 bv = *(const float4*)&Ks[kk][tn];
            float ar[4] = {av.x, av.y, av.z, av.w};
            float brr[4] = {bv.x, bv.y, bv.z, bv.w};
#pragma unroll
            for (int ii = 0; ii < 4; ii++)
#pragma unroll
                for (int jj = 0; jj < 4; jj++)
                    acc[ii][jj] += ar[ii] * brr[jj];
        }
        __syncthreads();
    }
#pragma unroll
    for (int ii = 0; ii < 4; ii++)
#pragma unroll
        for (int jj = 0; jj < 4; jj++)
            Sb[(size_t)(m0 + tm + ii) * L + n0 + tn + jj] = acc[ii][jj];
}

// ---------------------------------------------------------------------------
// 5) Softmax with fused bias terms. One 128-thread block per score row.
//    s = (S + relpos[min(ME-i+j, 2*ME-2)] + gate[n,h,j] + mask[n,j]) / norm[n]
// ---------------------------------------------------------------------------
__global__ void softmax_kernel(const float* __restrict__ relpos,
                               const float* __restrict__ mask,
                               const float* __restrict__ norm) {
    __shared__ float red[128];
    int row = blockIdx.x;                 // (n*H + h)*L + i
    int i  = row % L;
    int nh = row / L;
    int n  = nh / H;
    float* S = g_scores + (size_t)row * L;
    const float* gt = g_gate + (size_t)nh * L;
    const float* mk = mask + (size_t)n * L;
    float inv = 1.0f / norm[n];
    int t = threadIdx.x;

    int j0 = t, j1 = t + 128, j2 = t + 256;
    float v0 = (S[j0] + relpos[min(ME - i + j0, 2 * ME - 2)] + gt[j0] + mk[j0]) * inv;
    float v1 = (S[j1] + relpos[min(ME - i + j1, 2 * ME - 2)] + gt[j1] + mk[j1]) * inv;
    float v2 = (S[j2] + relpos[min(ME - i + j2, 2 * ME - 2)] + gt[j2] + mk[j2]) * inv;

    float mx = fmaxf(v0, fmaxf(v1, v2));
    red[t] = mx;
    __syncthreads();
    for (int s = 64; s > 0; s >>= 1) {
        if (t < s) red[t] = fmaxf(red[t], red[t + s]);
        __syncthreads();
    }
    mx = red[0];
    __syncthreads();

    v0 = __expf(v0 - mx); v1 = __expf(v1 - mx); v2 = __expf(v2 - mx);
    red[t] = v0 + v1 + v2;
    __syncthreads();
    for (int s = 64; s > 0; s >>= 1) {
        if (t < s) red[t] += red[t + s];
        __syncthreads();
    }
    float r = 1.0f / red[0];
    S[j0] = v0 * r;
    S[j1] = v1 * r;
    S[j2] = v2 * r;
}

// ---------------------------------------------------------------------------
// 6) PV: out[z][d][i] = sum_j attn[z][i][j] * v[z][d][j]
//    M = 64 (d), N = 384 (i), K = 384 (j).  B (attn) accessed transposed.
// ---------------------------------------------------------------------------
__global__ void pv_kernel() {
    __shared__ float Vs[16][68];   // [k][m]
    __shared__ float Ps[16][68];   // [k][n]
    int z = blockIdx.z;
    const float* Vb = g_v + (size_t)z * D * L;
    const float* Pb = g_scores + (size_t)z * L * L;
    float* Ob = g_att + (size_t)z * D * L;
    int n0 = blockIdx.y * 64;      // i tile; m0 = 0 (D = 64)
    int tid = threadIdx.x;
    int lr  = tid >> 2;            // 0..63
    int lc4 = (tid & 3) << 2;      // k chunk 0,4,8,12
    int tm  = (tid >> 4) << 2;
    int tn  = (tid & 15) << 2;

    float acc[4][4] = {};
    for (int k0 = 0; k0 < L; k0 += 16) {
        // V: Vs[k][m] <- Vb[m*L + k]
        float4 a = *(const float4*)(Vb + (size_t)lr * L + k0 + lc4);
        Vs[lc4 + 0][lr] = a.x; Vs[lc4 + 1][lr] = a.y;
        Vs[lc4 + 2][lr] = a.z; Vs[lc4 + 3][lr] = a.w;
        // attn: Ps[k][n] <- Pb[(n0+n)*L + k]
        float4 p = *(const float4*)(Pb + (size_t)(n0 + lr) * L + k0 + lc4);
        Ps[lc4 + 0][lr] = p.x; Ps[lc4 + 1][lr] = p.y;
        Ps[lc4 + 2][lr] = p.z; Ps[lc4 + 3][lr] = p.w;
        __syncthreads();
#pragma unroll
        for (int kk = 0; kk < 16; kk++) {
            float4 av = *(const float4*)&Vs[kk][tm];
            float4 bv = *(const float4*)&Ps[kk][tn];
            float ar[4] = {av.x, av.y, av.z, av.w};
            float brr[4] = {bv.x, bv.y, bv.z, bv.w};
#pragma unroll
            for (int ii = 0; ii < 4; ii++)
#pragma unroll
                for (int jj = 0; jj < 4; jj++)
                    acc[ii][jj] += ar[ii] * brr[jj];
        }
        __syncthreads();
    }
#pragma unroll
    for (int ii = 0; ii < 4; ii++)
#pragma unroll
        for (int jj = 0; jj < 4; jj++)
            Ob[(size_t)(tm + ii) * L + n0 + tn + jj] = acc[ii][jj];
}

// ---------------------------------------------------------------------------
// Launch
// ---------------------------------------------------------------------------
extern "C" void kernel_launch(void* const* d_in, const int* in_sizes, int n_in,
                              void* d_out, int out_size) {
    const float* x        = (const float*)d_in[0];
    const float* xorg     = (const float*)d_in[1];
    const float* abspos   = (const float*)d_in[2];
    const float* mask     = (const float*)d_in[3];
    const float* norm     = (const float*)d_in[4];
    const float* qkpos    = (const float*)d_in[5];
    const float* qkorg    = (const float*)d_in[6];
    const float* vorg     = (const float*)d_in[7];
    const float* relpos   = (const float*)d_in[8];
    const float* gate_w   = (const float*)d_in[9];
    const float* gate_b   = (const float*)d_in[10];
    const float* q_w      = (const float*)d_in[11];
    const float* k_w      = (const float*)d_in[12];
    const float* v_w      = (const float*)d_in[13];
    const float* dense_w  = (const float*)d_in[14];
    const float* dense_b  = (const float*)d_in[15];
    float* out = (float*)d_out;

    float *px0, *px1, *pq, *pk, *pv, *patt;
    cudaGetSymbolAddress((void**)&px0, g_x0);
    cudaGetSymbolAddress((void**)&px1, g_x1);
    cudaGetSymbolAddress((void**)&pq,  g_q);
    cudaGetSymbolAddress((void**)&pk,  g_k);
    cudaGetSymbolAddress((void**)&pv,  g_v);
    cudaGetSymbolAddress((void**)&patt, g_att);

    int total = NB * C * L;
    prep_kernel<<<(total + 255) / 256, 256>>>(x, xorg, abspos, qkpos, qkorg, vorg);

    dim3 gw(8, 6, NB);
    gemm_wx_kernel<false><<<gw, 256>>>(q_w, px1, pq, nullptr);
    gemm_wx_kernel<false><<<gw, 256>>>(k_w, px1, pk, nullptr);
    gemm_wx_kernel<false><<<gw, 256>>>(v_w, px0, pv, nullptr);

    gate_kernel<<<NB * H, L>>>(x, gate_w, gate_b);

    dim3 gs(6, 6, NB * H);
    scores_kernel<<<gs, 256>>>();

    softmax_kernel<<<NB * H * L, 128>>>(relpos, mask, norm);

    dim3 gp(1, 6, NB * H);
    pv_kernel<<<gp, 256>>>();

    gemm_wx_kernel<true><<<gw, 256>>>(dense_w, patt, out, dense_b);
}

// round 2
// speedup vs baseline: 1.0840x; 1.0840x over previous
#include <cuda_runtime.h>
#include <math.h>

constexpr int NB = 16, C = 512, L = 384, H = 8, D = 64, ME = 384;

__device__ float g_x0[NB * C * L];
__device__ float g_x1[NB * C * L];
__device__ float g_q [NB * C * L];
__device__ float g_k [NB * C * L];
__device__ float g_v [NB * C * L];
__device__ float g_att[NB * C * L];
__device__ float g_gate[NB * H * L];
__device__ float g_scores[(size_t)NB * H * L * L];

// ---------------------------------------------------------------------------
// 1) Preprocess
// ---------------------------------------------------------------------------
__global__ void prep_kernel(const float* __restrict__ x,
                            const float* __restrict__ xorg,
                            const float* __restrict__ abspos,
                            const float* __restrict__ qkpos,
                            const float* __restrict__ qkorg,
                            const float* __restrict__ vorg) {
    int i = blockIdx.x * blockDim.x + threadIdx.x;
    if (i >= NB * C * L) return;
    int c = (i / L) % C;
    int g = c >> 3;
    float xv = x[i], xo = xorg[i], ap = abspos[i];
    g_x0[i] = xv + xo * vorg[g];
    g_x1[i] = xv + xo * qkorg[g] + ap * qkpos[g];
}

// ---------------------------------------------------------------------------
// 2) Weight GEMM: Out[b][m][l] = sum_c W[m][c] X[b][c][l] (+bias)
//    BM=64, BN=128, BK=16, 128 threads, 8x8 per thread, double-buffered.
// ---------------------------------------------------------------------------
template <bool BIAS>
__global__ void __launch_bounds__(128) gemm64x128(
    const float* __restrict__ W, const float* __restrict__ X,
    float* __restrict__ Out, const float* __restrict__ bias) {
    constexpr int KK = C;
    __shared__ float As[2][16][64];
    __shared__ float Bs[2][16][128];
    int bz = blockIdx.z;
    const float* Xb = X + (size_t)bz * KK * L;
    float* Ob = Out + (size_t)bz * C * L;
    int m0 = blockIdx.x * 64, n0 = blockIdx.y * 128;
    int t = threadIdx.x;
    int tx = t & 15, ty = t >> 4;        // ty 0..7
    int ar = t >> 1, ak = (t & 1) * 8;   // A loader: row, k-chunk
    int bk = t >> 3, bc = (t & 7) * 16;  // B loader: k-row, col chunk
    const float* Ap = W + (size_t)(m0 + ar) * KK + ak;
    const float* Bp = Xb + (size_t)bk * L + n0 + bc;

    float4 a0, a1, b0, b1, b2, b3;
    a0 = *(const float4*)Ap;       a1 = *(const float4*)(Ap + 4);
    b0 = *(const float4*)Bp;       b1 = *(const float4*)(Bp + 4);
    b2 = *(const float4*)(Bp + 8); b3 = *(const float4*)(Bp + 12);

    float acc[8][8] = {};
    int buf = 0;
    As[0][ak+0][ar]=a0.x; As[0][ak+1][ar]=a0.y; As[0][ak+2][ar]=a0.z; As[0][ak+3][ar]=a0.w;
    As[0][ak+4][ar]=a1.x; As[0][ak+5][ar]=a1.y; As[0][ak+6][ar]=a1.z; As[0][ak+7][ar]=a1.w;
    *(float4*)&Bs[0][bk][bc]    = b0; *(float4*)&Bs[0][bk][bc+4]  = b1;
    *(float4*)&Bs[0][bk][bc+8]  = b2; *(float4*)&Bs[0][bk][bc+12] = b3;
    __syncthreads();

    for (int k0 = 0; k0 < KK; k0 += 16) {
        bool nxt = (k0 + 16) < KK;
        if (nxt) {
            const float* An = Ap + k0 + 16;
            a0 = *(const float4*)An;       a1 = *(const float4*)(An + 4);
            const float* Bn = Bp + (size_t)(k0 + 16) * L;
            b0 = *(const float4*)Bn;       b1 = *(const float4*)(Bn + 4);
            b2 = *(const float4*)(Bn + 8); b3 = *(const float4*)(Bn + 12);
        }
#pragma unroll
        for (int kk = 0; kk < 16; kk++) {
            float av[8], bv[8];
            *(float4*)&av[0] = *(const float4*)&As[buf][kk][ty * 4];
            *(float4*)&av[4] = *(const float4*)&As[buf][kk][32 + ty * 4];
            *(float4*)&bv[0] = *(const float4*)&Bs[buf][kk][tx * 4];
            *(float4*)&bv[4] = *(const float4*)&Bs[buf][kk][64 + tx * 4];
#pragma unroll
            for (int i = 0; i < 8; i++)
#pragma unroll
                for (int j = 0; j < 8; j++)
                    acc[i][j] = fmaf(av[i], bv[j], acc[i][j]);
        }
        if (nxt) {
            buf ^= 1;
            As[buf][ak+0][ar]=a0.x; As[buf][ak+1][ar]=a0.y; As[buf][ak+2][ar]=a0.z; As[buf][ak+3][ar]=a0.w;
            As[buf][ak+4][ar]=a1.x; As[buf][ak+5][ar]=a1.y; As[buf][ak+6][ar]=a1.z; As[buf][ak+7][ar]=a1.w;
            *(float4*)&Bs[buf][bk][bc]    = b0; *(float4*)&Bs[buf][bk][bc+4]  = b1;
            *(float4*)&Bs[buf][bk][bc+8]  = b2; *(float4*)&Bs[buf][bk][bc+12] = b3;
            __syncthreads();
        }
    }
#pragma unroll
    for (int i = 0; i < 8; i++) {
        int m = m0 + (i < 4 ? ty * 4 + i : 32 + ty * 4 + i - 4);
        float bv = BIAS ? bias[m] : 0.0f;
        float* r = Ob + (size_t)m * L + n0;
        float4 o0 = {acc[i][0]+bv, acc[i][1]+bv, acc[i][2]+bv, acc[i][3]+bv};
        float4 o1 = {acc[i][4]+bv, acc[i][5]+bv, acc[i][6]+bv, acc[i][7]+bv};
        *(float4*)(r + tx * 4)      = o0;
        *(float4*)(r + 64 + tx * 4) = o1;
    }
}

// ---------------------------------------------------------------------------
// 3) Gate
// ---------------------------------------------------------------------------
__global__ void gate_kernel(const float* __restrict__ x,
                            const float* __restrict__ gate_w,
                            const float* __restrict__ gate_b) {
    int z = blockIdx.x;
    int n = z / H, h = z % H;
    int l = threadIdx.x;
    const float* xb = x + (size_t)n * C * L + l;
    const float* w = gate_w + h * C;
    float acc = gate_b[h];
    for (int c = 0; c < C; c++)
        acc = fmaf(w[c], xb[(size_t)c * L], acc);
    g_gate[(size_t)z * L + l] = acc;
}

// ---------------------------------------------------------------------------
// 4) Scores: S[z][i][j] = sum_d Q[z][d][i] K[z][d][j].
//    BM=128, BN=128, BK=16, 256 threads, 8x8 per thread, K=64.
// ---------------------------------------------------------------------------
__global__ void __launch_bounds__(256) scores128() {
    __shared__ float Qs[2][16][128];
    __shared__ float Ks[2][16][128];
    int z = blockIdx.z;
    const float* Qb = g_q + (size_t)z * D * L;
    const float* Kb = g_k + (size_t)z * D * L;
    float* Sb = g_scores + (size_t)z * L * L;
    int m0 = blockIdx.x * 128, n0 = blockIdx.y * 128;
    int t = threadIdx.x;
    int tx = t & 15, ty = t >> 4;           // both 0..15
    int lr = t >> 4, lc = (t & 15) * 8;     // loader: k-row, col chunk
    const float* Qp = Qb + (size_t)lr * L + m0 + lc;
    const float* Kp = Kb + (size_t)lr * L + n0 + lc;

    float4 qa0, qa1, ka0, ka1;
    qa0 = *(const float4*)Qp; qa1 = *(const float4*)(Qp + 4);
    ka0 = *(const float4*)Kp; ka1 = *(const float4*)(Kp + 4);

    float acc[8][8] = {};
    int buf = 0;
    *(float4*)&Qs[0][lr][lc]   = qa0; *(float4*)&Qs[0][lr][lc+4] = qa1;
    *(float4*)&Ks[0][lr][lc]   = ka0; *(float4*)&Ks[0][lr][lc+4] = ka1;
    __syncthreads();

    for (int k0 = 0; k0 < D; k0 += 16) {
        bool nxt = (k0 + 16) < D;
        if (nxt) {
            const float* Qn = Qp + (size_t)(k0 + 16) * L;
            const float* Kn = Kp + (size_t)(k0 + 16) * L;
            qa0 = *(const float4*)Qn; qa1 = *(const float4*)(Qn + 4);
            ka0 = *(const float4*)Kn; ka1 = *(const float4*)(Kn + 4);
        }
#pragma unroll
        for (int kk = 0; kk < 16; kk++) {
            float av[8], bv[8];
            *(float4*)&av[0] = *(const float4*)&Qs[buf][kk][ty * 4];
            *(float4*)&av[4] = *(const float4*)&Qs[buf][kk][64 + ty * 4];
            *(float4*)&bv[0] = *(const float4*)&Ks[buf][kk][tx * 4];
            *(float4*)&bv[4] = *(const float4*)&Ks[buf][kk][64 + tx * 4];
#pragma unroll
            for (int i = 0; i < 8; i++)
#pragma unroll
                for (int j = 0; j < 8; j++)
                    acc[i][j] = fmaf(av[i], bv[j], acc[i][j]);
        }
        if (nxt) {
            buf ^= 1;
            *(float4*)&Qs[buf][lr][lc]   = qa0; *(float4*)&Qs[buf][lr][lc+4] = qa1;
            *(float4*)&Ks[buf][lr][lc]   = ka0; *(float4*)&Ks[buf][lr][lc+4] = ka1;
            __syncthreads();
        }
    }
#pragma unroll
    for (int i = 0; i < 8; i++) {
        int m = m0 + (i < 4 ? ty * 4 + i : 64 + ty * 4 + i - 4);
        float* r = Sb + (size_t)m * L + n0;
        float4 o0 = {acc[i][0], acc[i][1], acc[i][2], acc[i][3]};
        float4 o1 = {acc[i][4], acc[i][5], acc[i][6], acc[i][7]};
        *(float4*)(r + tx * 4)      = o0;
        *(float4*)(r + 64 + tx * 4) = o1;
    }
}

// ---------------------------------------------------------------------------
// 5) Softmax with fused bias terms (one 128-thread block per row)
// ---------------------------------------------------------------------------
__global__ void softmax_kernel(const float* __restrict__ relpos,
                               const float* __restrict__ mask,
                               const float* __restrict__ norm) {
    __shared__ float red[128];
    int row = blockIdx.x;
    int i  = row % L;
    int nh = row / L;
    int n  = nh / H;
    float* S = g_scores + (size_t)row * L;
    const float* gt = g_gate + (size_t)nh * L;
    const float* mk = mask + (size_t)n * L;
    float inv = 1.0f / norm[n];
    int t = threadIdx.x;

    int j0 = t, j1 = t + 128, j2 = t + 256;
    float v0 = (S[j0] + relpos[min(ME - i + j0, 2 * ME - 2)] + gt[j0] + mk[j0]) * inv;
    float v1 = (S[j1] + relpos[min(ME - i + j1, 2 * ME - 2)] + gt[j1] + mk[j1]) * inv;
    float v2 = (S[j2] + relpos[min(ME - i + j2, 2 * ME - 2)] + gt[j2] + mk[j2]) * inv;

    float mx = fmaxf(v0, fmaxf(v1, v2));
    red[t] = mx;
    __syncthreads();
    for (int s = 64; s > 0; s >>= 1) {
        if (t < s) red[t] = fmaxf(red[t], red[t + s]);
        __syncthreads();
    }
    mx = red[0];
    __syncthreads();

    v0 = __expf(v0 - mx); v1 = __expf(v1 - mx); v2 = __expf(v2 - mx);
    red[t] = v0 + v1 + v2;
    __syncthreads();
    for (int s = 64; s > 0; s >>= 1) {
        if (t < s) red[t] += red[t + s];
        __syncthreads();
    }
    float r = 1.0f / red[0];
    S[j0] = v0 * r;
    S[j1] = v1 * r;
    S[j2] = v2 * r;
}

// ---------------------------------------------------------------------------
// 6) PV: out[z][d][i] = sum_j P[z][i][j] V[z][d][j]
//    BM=64 (d), BN=128 (i), BK=16, 128 threads, 8x8 per thread.
// ---------------------------------------------------------------------------
__global__ void __launch_bounds__(128) pv64x128() {
    __shared__ float Vs[2][16][64];
    __shared__ float Ps[2][16][128];
    int z = blockIdx.z;
    const float* Vb = g_v + (size_t)z * D * L;
    const float* Pb = g_scores + (size_t)z * L * L;
    float* Ob = g_att + (size_t)z * D * L;
    int n0 = blockIdx.y * 128;
    int t = threadIdx.x;
    int tx = t & 15, ty = t >> 4;
    int ar = t >> 1, ak = (t & 1) * 8;
    const float* Ap = Vb + (size_t)ar * L + ak;
    const float* Pp = Pb + (size_t)(n0 + t) * L;   // one attn row per thread

    float4 a0, a1, p0, p1, p2, p3;
    a0 = *(const float4*)Ap;       a1 = *(const float4*)(Ap + 4);
    p0 = *(const float4*)Pp;       p1 = *(const float4*)(Pp + 4);
    p2 = *(const float4*)(Pp + 8); p3 = *(const float4*)(Pp + 12);

    float acc[8][8] = {};
    int buf = 0;
    Vs[0][ak+0][ar]=a0.x; Vs[0][ak+1][ar]=a0.y; Vs[0][ak+2][ar]=a0.z; Vs[0][ak+3][ar]=a0.w;
    Vs[0][ak+4][ar]=a1.x; Vs[0][ak+5][ar]=a1.y; Vs[0][ak+6][ar]=a1.z; Vs[0][ak+7][ar]=a1.w;
    Ps[0][0][t]=p0.x;  Ps[0][1][t]=p0.y;  Ps[0][2][t]=p0.z;  Ps[0][3][t]=p0.w;
    Ps[0][4][t]=p1.x;  Ps[0][5][t]=p1.y;  Ps[0][6][t]=p1.z;  Ps[0][7][t]=p1.w;
    Ps[0][8][t]=p2.x;  Ps[0][9][t]=p2.y;  Ps[0][10][t]=p2.z; Ps[0][11][t]=p2.w;
    Ps[0][12][t]=p3.x; Ps[0][13][t]=p3.y; Ps[0][14][t]=p3.z; Ps[0][15][t]=p3.w;
    __syncthreads();

    for (int k0 = 0; k0 < L; k0 += 16) {
        bool nxt = (k0 + 16) < L;
        if (nxt) {
            const float* An = Ap + k0 + 16;
            a0 = *(const float4*)An;       a1 = *(const float4*)(An + 4);
            const float* Pn = Pp + k0 + 16;
            p0 = *(const float4*)Pn;       p1 = *(const float4*)(Pn + 4);
            p2 = *(const float4*)(Pn + 8); p3 = *(const float4*)(Pn + 12);
        }
#pragma unroll
        for (int kk = 0; kk < 16; kk++) {
            float av[8], bv[8];
            *(float4*)&av[0] = *(const float4*)&Vs[buf][kk][ty * 4];
            *(float4*)&av[4] = *(const float4*)&Vs[buf][kk][32 + ty * 4];
            *(float4*)&bv[0] = *(const float4*)&Ps[buf][kk][tx * 4];
            *(float4*)&bv[4] = *(const float4*)&Ps[buf][kk][64 + tx * 4];
#pragma unroll
            for (int i = 0; i < 8; i++)
#pragma unroll
                for (int j = 0; j < 8; j++)
                    acc[i][j] = fmaf(av[i], bv[j], acc[i][j]);
        }
        if (nxt) {
            buf ^= 1;
            Vs[buf][ak+0][ar]=a0.x; Vs[buf][ak+1][ar]=a0.y; Vs[buf][ak+2][ar]=a0.z; Vs[buf][ak+3][ar]=a0.w;
            Vs[buf][ak+4][ar]=a1.x; Vs[buf][ak+5][ar]=a1.y; Vs[buf][ak+6][ar]=a1.z; Vs[buf][ak+7][ar]=a1.w;
            Ps[buf][0][t]=p0.x;  Ps[buf][1][t]=p0.y;  Ps[buf][2][t]=p0.z;  Ps[buf][3][t]=p0.w;
            Ps[buf][4][t]=p1.x;  Ps[buf][5][t]=p1.y;  Ps[buf][6][t]=p1.z;  Ps[buf][7][t]=p1.w;
            Ps[buf][8][t]=p2.x;  Ps[buf][9][t]=p2.y;  Ps[buf][10][t]=p2.z; Ps[buf][11][t]=p2.w;
            Ps[buf][12][t]=p3.x; Ps[buf][13][t]=p3.y; Ps[buf][14][t]=p3.z; Ps[buf][15][t]=p3.w;
            __syncthreads();
        }
    }
#pragma unroll
    for (int i = 0; i < 8; i++) {
        int m = (i < 4 ? ty * 4 + i : 32 + ty * 4 + i - 4);
        float* r = Ob + (size_t)m * L + n0;
        float4 o0 = {acc[i][0], acc[i][1], acc[i][2], acc[i][3]};
        float4 o1 = {acc[i][4], acc[i][5], acc[i][6], acc[i][7]};
        *(float4*)(r + tx * 4)      = o0;
        *(float4*)(r + 64 + tx * 4) = o1;
    }
}

// ---------------------------------------------------------------------------
// Launch
// ---------------------------------------------------------------------------
extern "C" void kernel_launch(void* const* d_in, const int* in_sizes, int n_in,
                              void* d_out, int out_size) {
    const float* x        = (const float*)d_in[0];
    const float* xorg     = (const float*)d_in[1];
    const float* abspos   = (const float*)d_in[2];
    const float* mask     = (const float*)d_in[3];
    const float* norm     = (const float*)d_in[4];
    const float* qkpos    = (const float*)d_in[5];
    const float* qkorg    = (const float*)d_in[6];
    const float* vorg     = (const float*)d_in[7];
    const float* relpos   = (const float*)d_in[8];
    const float* gate_w   = (const float*)d_in[9];
    const float* gate_b   = (const float*)d_in[10];
    const float* q_w      = (const float*)d_in[11];
    const float* k_w      = (const float*)d_in[12];
    const float* v_w      = (const float*)d_in[13];
    const float* dense_w  = (const float*)d_in[14];
    const float* dense_b  = (const float*)d_in[15];
    float* out = (float*)d_out;

    float *px0, *px1, *pq, *pk, *pv, *patt;
    cudaGetSymbolAddress((void**)&px0, g_x0);
    cudaGetSymbolAddress((void**)&px1, g_x1);
    cudaGetSymbolAddress((void**)&pq,  g_q);
    cudaGetSymbolAddress((void**)&pk,  g_k);
    cudaGetSymbolAddress((void**)&pv,  g_v);
    cudaGetSymbolAddress((void**)&patt, g_att);

    int total = NB * C * L;
    prep_kernel<<<(total + 255) / 256, 256>>>(x, xorg, abspos, qkpos, qkorg, vorg);

    dim3 gw(8, 3, NB);
    gemm64x128<false><<<gw, 128>>>(q_w, px1, pq, nullptr);
    gemm64x128<false><<<gw, 128>>>(k_w, px1, pk, nullptr);
    gemm64x128<false><<<gw, 128>>>(v_w, px0, pv, nullptr);

    gate_kernel<<<NB * H, L>>>(x, gate_w, gate_b);

    dim3 gs(3, 3, NB * H);
    scores128<<<gs, 256>>>();

    softmax_kernel<<<NB * H * L, 128>>>(relpos, mask, norm);

    dim3 gp(1, 3, NB * H);
    pv64x128<<<gp, 128>>>();

    gemm64x128<true><<<gw, 128>>>(dense_w, patt, out, dense_b);
}

// round 3
// speedup vs baseline: 1.4298x; 1.3190x over previous
#include <cuda_runtime.h>
#include <math.h>
#include <stdint.h>

constexpr int NB = 16, C = 512, L = 384, H = 8, D = 64, ME = 384;

__device__ float g_x0[NB * C * L];
__device__ float g_x1[NB * C * L];
__device__ float g_q [NB * C * L];
__device__ float g_k [NB * C * L];
__device__ float g_v [NB * C * L];
__device__ float g_att[NB * C * L];
__device__ float g_gate[NB * H * L];
__device__ float g_scores[(size_t)NB * H * L * L];

// ---------------------------------------------------------------------------
// helpers
// ---------------------------------------------------------------------------
__device__ __forceinline__ uint32_t f2tf32(float f) {
    uint32_t u;
    asm("cvt.rna.tf32.f32 %0, %1;" : "=r"(u) : "f"(f));
    return u;
}

__device__ __forceinline__ void mma8(float* c, const uint32_t* a, const uint32_t* b) {
    asm("mma.sync.aligned.m16n8k8.row.col.f32.tf32.tf32.f32 "
        "{%0,%1,%2,%3}, {%4,%5,%6,%7}, {%8,%9}, {%0,%1,%2,%3};"
        : "+f"(c[0]), "+f"(c[1]), "+f"(c[2]), "+f"(c[3])
        : "r"(a[0]), "r"(a[1]), "r"(a[2]), "r"(a[3]), "r"(b[0]), "r"(b[1]));
}

// ---------------------------------------------------------------------------
// 1) Preprocess
// ---------------------------------------------------------------------------
__global__ void prep_kernel(const float* __restrict__ x,
                            const float* __restrict__ xorg,
                            const float* __restrict__ abspos,
                            const float* __restrict__ qkpos,
                            const float* __restrict__ qkorg,
                            const float* __restrict__ vorg) {
    int i = blockIdx.x * blockDim.x + threadIdx.x;
    if (i >= NB * C * L) return;
    int c = (i / L) % C;
    int g = c >> 3;
    float xv = x[i], xo = xorg[i], ap = abspos[i];
    g_x0[i] = xv + xo * vorg[g];
    g_x1[i] = xv + xo * qkorg[g] + ap * qkpos[g];
}

// ---------------------------------------------------------------------------
// 2) Weight GEMM (tf32 MMA): Out[b][m][l] = sum_c W[m][c] X[b][c][l] (+bias)
//    BM=128, BN=128, BK=16, 256 threads (8 warps, 4x2), 32x64 per warp.
// ---------------------------------------------------------------------------
template <bool BIAS>
__global__ void __launch_bounds__(256) gemm_tc(
    const float* __restrict__ W, const float* __restrict__ X,
    float* __restrict__ Out, const float* __restrict__ bias) {
    constexpr int KK = C;
    __shared__ uint32_t As[2][16][132];
    __shared__ uint32_t Bs[2][16][132];
    int bz = blockIdx.z;
    const float* Xb = X + (size_t)bz * KK * L;
    float* Ob = Out + (size_t)bz * C * L;
    int m0 = blockIdx.x * 128, n0 = blockIdx.y * 128;
    int t = threadIdx.x;

    int am = t & 127, ac = t >> 7;          // A loader: row, k-quad base (0/1; +2)
    int br = t >> 4, bc = (t & 15) * 8;     // B loader
    const float* Ap = W + (size_t)(m0 + am) * KK;
    const float* Bp = Xb + (size_t)br * L + n0 + bc;

    int w = t >> 5, lane = t & 31;
    int wm = (w >> 1) * 32, wn = (w & 1) * 64;
    int g = lane >> 2, tig = lane & 3;

    float acc[2][8][4] = {};
    float4 a[2], b[2];
    a[0] = *(const float4*)(Ap + ac * 4);
    a[1] = *(const float4*)(Ap + (ac + 2) * 4);
    b[0] = *(const float4*)Bp;
    b[1] = *(const float4*)(Bp + 4);

    int buf = 0;
#pragma unroll
    for (int s = 0; s < 2; s++) {
        int kq = (ac + 2 * s) * 4;
        As[0][kq + 0][am] = f2tf32(a[s].x); As[0][kq + 1][am] = f2tf32(a[s].y);
        As[0][kq + 2][am] = f2tf32(a[s].z); As[0][kq + 3][am] = f2tf32(a[s].w);
    }
    Bs[0][br][bc + 0] = f2tf32(b[0].x); Bs[0][br][bc + 1] = f2tf32(b[0].y);
    Bs[0][br][bc + 2] = f2tf32(b[0].z); Bs[0][br][bc + 3] = f2tf32(b[0].w);
    Bs[0][br][bc + 4] = f2tf32(b[1].x); Bs[0][br][bc + 5] = f2tf32(b[1].y);
    Bs[0][br][bc + 6] = f2tf32(b[1].z); Bs[0][br][bc + 7] = f2tf32(b[1].w);
    __syncthreads();

    for (int k0 = 0; k0 < KK; k0 += 16) {
        bool nxt = (k0 + 16) < KK;
        if (nxt) {
            const float* An = Ap + k0 + 16;
            a[0] = *(const float4*)(An + ac * 4);
            a[1] = *(const float4*)(An + (ac + 2) * 4);
            const float* Bn = Bp + (size_t)(k0 + 16) * L;
            b[0] = *(const float4*)Bn;
            b[1] = *(const float4*)(Bn + 4);
        }
#pragma unroll
        for (int ks = 0; ks < 16; ks += 8) {
            uint32_t af[2][4], bf[8][2];
#pragma unroll
            for (int mt = 0; mt < 2; mt++) {
                int m = wm + mt * 16;
                af[mt][0] = As[buf][ks + tig][m + g];
                af[mt][1] = As[buf][ks + tig][m + g + 8];
                af[mt][2] = As[buf][ks + tig + 4][m + g];
                af[mt][3] = As[buf][ks + tig + 4][m + g + 8];
            }
#pragma unroll
            for (int nt = 0; nt < 8; nt++) {
                bf[nt][0] = Bs[buf][ks + tig][wn + nt * 8 + g];
                bf[nt][1] = Bs[buf][ks + tig + 4][wn + nt * 8 + g];
            }
#pragma unroll
            for (int mt = 0; mt < 2; mt++)
#pragma unroll
                for (int nt = 0; nt < 8; nt++)
                    mma8(acc[mt][nt], af[mt], bf[nt]);
        }
        if (nxt) {
            buf ^= 1;
#pragma unroll
            for (int s = 0; s < 2; s++) {
                int kq = (ac + 2 * s) * 4;
                As[buf][kq + 0][am] = f2tf32(a[s].x); As[buf][kq + 1][am] = f2tf32(a[s].y);
                As[buf][kq + 2][am] = f2tf32(a[s].z); As[buf][kq + 3][am] = f2tf32(a[s].w);
            }
            Bs[buf][br][bc + 0] = f2tf32(b[0].x); Bs[buf][br][bc + 1] = f2tf32(b[0].y);
            Bs[buf][br][bc + 2] = f2tf32(b[0].z); Bs[buf][br][bc + 3] = f2tf32(b[0].w);
            Bs[buf][br][bc + 4] = f2tf32(b[1].x); Bs[buf][br][bc + 5] = f2tf32(b[1].y);
            Bs[buf][br][bc + 6] = f2tf32(b[1].z); Bs[buf][br][bc + 7] = f2tf32(b[1].w);
            __syncthreads();
        }
    }
#pragma unroll
    for (int mt = 0; mt < 2; mt++) {
        int mrow = m0 + wm + mt * 16 + g;
        float bv0 = BIAS ? bias[mrow] : 0.0f;
        float bv1 = BIAS ? bias[mrow + 8] : 0.0f;
#pragma unroll
        for (int nt = 0; nt < 8; nt++) {
            int col = n0 + wn + nt * 8 + tig * 2;
            float2 o0 = {acc[mt][nt][0] + bv0, acc[mt][nt][1] + bv0};
            float2 o1 = {acc[mt][nt][2] + bv1, acc[mt][nt][3] + bv1};
            *(float2*)(Ob + (size_t)mrow * L + col) = o0;
            *(float2*)(Ob + (size_t)(mrow + 8) * L + col) = o1;
        }
    }
}

// ---------------------------------------------------------------------------
// 3) Gate
// ---------------------------------------------------------------------------
__global__ void gate_kernel(const float* __restrict__ x,
                            const float* __restrict__ gate_w,
                            const float* __restrict__ gate_b) {
    int z = blockIdx.x;
    int n = z / H, h = z % H;
    int l = threadIdx.x;
    const float* xb = x + (size_t)n * C * L + l;
    const float* wv = gate_w + h * C;
    float acc = gate_b[h];
    for (int c = 0; c < C; c++)
        acc = fmaf(wv[c], xb[(size_t)c * L], acc);
    g_gate[(size_t)z * L + l] = acc;
}

// ---------------------------------------------------------------------------
// 4) Scores (tf32 MMA): S[z][i][j] = sum_d Q[z][d][i] K[z][d][j]
//    Both operands already [k][n]-major in GMEM -> direct loads.
// ---------------------------------------------------------------------------
__global__ void __launch_bounds__(256) scores_tc() {
    __shared__ uint32_t As[2][16][132];
    __shared__ uint32_t Bs[2][16][132];
    int z = blockIdx.z;
    const float* Qb = g_q + (size_t)z * D * L;
    const float* Kb = g_k + (size_t)z * D * L;
    float* Sb = g_scores + (size_t)z * L * L;
    int m0 = blockIdx.x * 128, n0 = blockIdx.y * 128;
    int t = threadIdx.x;
    int br = t >> 4, bc = (t & 15) * 8;
    const float* Qp = Qb + (size_t)br * L + m0 + bc;
    const float* Kp = Kb + (size_t)br * L + n0 + bc;

    int w = t >> 5, lane = t & 31;
    int wm = (w >> 1) * 32, wn = (w & 1) * 64;
    int g = lane >> 2, tig = lane & 3;

    float acc[2][8][4] = {};
    float4 qa[2], ka[2];
    qa[0] = *(const float4*)Qp; qa[1] = *(const float4*)(Qp + 4);
    ka[0] = *(const float4*)Kp; ka[1] = *(const float4*)(Kp + 4);

    int buf = 0;
    As[0][br][bc+0]=f2tf32(qa[0].x); As[0][br][bc+1]=f2tf32(qa[0].y);
    As[0][br][bc+2]=f2tf32(qa[0].z); As[0][br][bc+3]=f2tf32(qa[0].w);
    As[0][br][bc+4]=f2tf32(qa[1].x); As[0][br][bc+5]=f2tf32(qa[1].y);
    As[0][br][bc+6]=f2tf32(qa[1].z); As[0][br][bc+7]=f2tf32(qa[1].w);
    Bs[0][br][bc+0]=f2tf32(ka[0].x); Bs[0][br][bc+1]=f2tf32(ka[0].y);
    Bs[0][br][bc+2]=f2tf32(ka[0].z); Bs[0][br][bc+3]=f2tf32(ka[0].w);
    Bs[0][br][bc+4]=f2tf32(ka[1].x); Bs[0][br][bc+5]=f2tf32(ka[1].y);
    Bs[0][br][bc+6]=f2tf32(ka[1].z); Bs[0][br][bc+7]=f2tf32(ka[1].w);
    __syncthreads();

    for (int k0 = 0; k0 < D; k0 += 16) {
        bool nxt = (k0 + 16) < D;
        if (nxt) {
            const float* Qn = Qp + (size_t)(k0 + 16) * L;
            const float* Kn = Kp + (size_t)(k0 + 16) * L;
            qa[0] = *(const float4*)Qn; qa[1] = *(const float4*)(Qn + 4);
            ka[0] = *(const float4*)Kn; ka[1] = *(const float4*)(Kn + 4);
        }
#pragma unroll
        for (int ks = 0; ks < 16; ks += 8) {
            uint32_t af[2][4], bf[8][2];
#pragma unroll
            for (int mt = 0; mt < 2; mt++) {
                int m = wm + mt * 16;
                af[mt][0] = As[buf][ks + tig][m + g];
                af[mt][1] = As[buf][ks + tig][m + g + 8];
                af[mt][2] = As[buf][ks + tig + 4][m + g];
                af[mt][3] = As[buf][ks + tig + 4][m + g + 8];
            }
#pragma unroll
            for (int nt = 0; nt < 8; nt++) {
                bf[nt][0] = Bs[buf][ks + tig][wn + nt * 8 + g];
                bf[nt][1] = Bs[buf][ks + tig + 4][wn + nt * 8 + g];
            }
#pragma unroll
            for (int mt = 0; mt < 2; mt++)
#pragma unroll
                for (int nt = 0; nt < 8; nt++)
                    mma8(acc[mt][nt], af[mt], bf[nt]);
        }
        if (nxt) {
            buf ^= 1;
            As[buf][br][bc+0]=f2tf32(qa[0].x); As[buf][br][bc+1]=f2tf32(qa[0].y);
            As[buf][br][bc+2]=f2tf32(qa[0].z); As[buf][br][bc+3]=f2tf32(qa[0].w);
            As[buf][br][bc+4]=f2tf32(qa[1].x); As[buf][br][bc+5]=f2tf32(qa[1].y);
            As[buf][br][bc+6]=f2tf32(qa[1].z); As[buf][br][bc+7]=f2tf32(qa[1].w);
            Bs[buf][br][bc+0]=f2tf32(ka[0].x); Bs[buf][br][bc+1]=f2tf32(ka[0].y);
            Bs[buf][br][bc+2]=f2tf32(ka[0].z); Bs[buf][br][bc+3]=f2tf32(ka[0].w);
            Bs[buf][br][bc+4]=f2tf32(ka[1].x); Bs[buf][br][bc+5]=f2tf32(ka[1].y);
            Bs[buf][br][bc+6]=f2tf32(ka[1].z); Bs[buf][br][bc+7]=f2tf32(ka[1].w);
            __syncthreads();
        }
    }
#pragma unroll
    for (int mt = 0; mt < 2; mt++) {
        int mrow = m0 + wm + mt * 16 + g;
#pragma unroll
        for (int nt = 0; nt < 8; nt++) {
            int col = n0 + wn + nt * 8 + tig * 2;
            float2 o0 = {acc[mt][nt][0], acc[mt][nt][1]};
            float2 o1 = {acc[mt][nt][2], acc[mt][nt][3]};
            *(float2*)(Sb + (size_t)mrow * L + col) = o0;
            *(float2*)(Sb + (size_t)(mrow + 8) * L + col) = o1;
        }
    }
}

// ---------------------------------------------------------------------------
// 5) Softmax with fused bias terms
// ---------------------------------------------------------------------------
__global__ void softmax_kernel(const float* __restrict__ relpos,
                               const float* __restrict__ mask,
                               const float* __restrict__ norm) {
    __shared__ float red[128];
    int row = blockIdx.x;
    int i  = row % L;
    int nh = row / L;
    int n  = nh / H;
    float* S = g_scores + (size_t)row * L;
    const float* gt = g_gate + (size_t)nh * L;
    const float* mk = mask + (size_t)n * L;
    float inv = 1.0f / norm[n];
    int t = threadIdx.x;

    int j0 = t, j1 = t + 128, j2 = t + 256;
    float v0 = (S[j0] + relpos[min(ME - i + j0, 2 * ME - 2)] + gt[j0] + mk[j0]) * inv;
    float v1 = (S[j1] + relpos[min(ME - i + j1, 2 * ME - 2)] + gt[j1] + mk[j1]) * inv;
    float v2 = (S[j2] + relpos[min(ME - i + j2, 2 * ME - 2)] + gt[j2] + mk[j2]) * inv;

    float mx = fmaxf(v0, fmaxf(v1, v2));
    red[t] = mx;
    __syncthreads();
    for (int s = 64; s > 0; s >>= 1) {
        if (t < s) red[t] = fmaxf(red[t], red[t + s]);
        __syncthreads();
    }
    mx = red[0];
    __syncthreads();

    v0 = __expf(v0 - mx); v1 = __expf(v1 - mx); v2 = __expf(v2 - mx);
    red[t] = v0 + v1 + v2;
    __syncthreads();
    for (int s = 64; s > 0; s >>= 1) {
        if (t < s) red[t] += red[t + s];
        __syncthreads();
    }
    float r = 1.0f / red[0];
    S[j0] = v0 * r;
    S[j1] = v1 * r;
    S[j2] = v2 * r;
}

// ---------------------------------------------------------------------------
// 6) PV (tf32 MMA): out[z][d][i] = sum_j P[z][i][j] V[z][d][j]
//    BM=64, BN=128, BK=16, 128 threads (4 warps, 2x2), 32x64 per warp.
// ---------------------------------------------------------------------------
__global__ void __launch_bounds__(128) pv_tc() {
    __shared__ uint32_t As[2][16][68];    // V^T slab: [k=j][m=d]
    __shared__ uint32_t Bs[2][16][132];   // P^T slab: [k=j][n=i]
    int z = blockIdx.z;
    const float* Vb = g_v + (size_t)z * D * L;
    const float* Pb = g_scores + (size_t)z * L * L;
    float* Ob = g_att + (size_t)z * D * L;
    int n0 = blockIdx.y * 128;
    int t = threadIdx.x;

    int am = t & 63, ac = t >> 6;          // V loader
    const float* Ap = Vb + (size_t)am * L;
    const float* Pp = Pb + (size_t)(n0 + t) * L;  // one P row per thread

    int w = t >> 5, lane = t & 31;
    int wm = (w >> 1) * 32, wn = (w & 1) * 64;
    int g = lane >> 2, tig = lane & 3;

    float acc[2][8][4] = {};
    float4 a[2], p[4];
    a[0] = *(const float4*)(Ap + ac * 4);
    a[1] = *(const float4*)(Ap + (ac + 2) * 4);
    p[0] = *(const float4*)Pp;       p[1] = *(const float4*)(Pp + 4);
    p[2] = *(const float4*)(Pp + 8); p[3] = *(const float4*)(Pp + 12);

    int buf = 0;
#pragma unroll
    for (int s = 0; s < 2; s++) {
        int kq = (ac + 2 * s) * 4;
        As[0][kq + 0][am] = f2tf32(a[s].x); As[0][kq + 1][am] = f2tf32(a[s].y);
        As[0][kq + 2][am] = f2tf32(a[s].z); As[0][kq + 3][am] = f2tf32(a[s].w);
    }
#pragma unroll
    for (int j = 0; j < 4; j++) {
        Bs[0][j*4+0][t] = f2tf32(p[j].x); Bs[0][j*4+1][t] = f2tf32(p[j].y);
        Bs[0][j*4+2][t] = f2tf32(p[j].z); Bs[0][j*4+3][t] = f2tf32(p[j].w);
    }
    __syncthreads();

    for (int k0 = 0; k0 < L; k0 += 16) {
        bool nxt = (k0 + 16) < L;
        if (nxt) {
            const float* An = Ap + k0 + 16;
            a[0] = *(const float4*)(An + ac * 4);
            a[1] = *(const float4*)(An + (ac + 2) * 4);
            const float* Pn = Pp + k0 + 16;
            p[0] = *(const float4*)Pn;       p[1] = *(const float4*)(Pn + 4);
            p[2] = *(const float4*)(Pn + 8); p[3] = *(const float4*)(Pn + 12);
        }
#pragma unroll
        for (int ks = 0; ks < 16; ks += 8) {
            uint32_t af[2][4], bf[8][2];
#pragma unroll
            for (int mt = 0; mt < 2; mt++) {
                int m = wm + mt * 16;
                af[mt][0] = As[buf][ks + tig][m + g];
                af[mt][1] = As[buf][ks + tig][m + g + 8];
                af[mt][2] = As[buf][ks + tig + 4][m + g];
                af[mt][3] = As[buf][ks + tig + 4][m + g + 8];
            }
#pragma unroll
            for (int nt = 0; nt < 8; nt++) {
                bf[nt][0] = Bs[buf][ks + tig][wn + nt * 8 + g];
                bf[nt][1] = Bs[buf][ks + tig + 4][wn + nt * 8 + g];
            }
#pragma unroll
            for (int mt = 0; mt < 2; mt++)
#pragma unroll
                for (int nt = 0; nt < 8; nt++)
                    mma8(acc[mt][nt], af[mt], bf[nt]);
        }
        if (nxt) {
            buf ^= 1;
#pragma unroll
            for (int s = 0; s < 2; s++) {
                int kq = (ac + 2 * s) * 4;
                As[buf][kq + 0][am] = f2tf32(a[s].x); As[buf][kq + 1][am] = f2tf32(a[s].y);
                As[buf][kq + 2][am] = f2tf32(a[s].z); As[buf][kq + 3][am] = f2tf32(a[s].w);
            }
#pragma unroll
            for (int j = 0; j < 4; j++) {
                Bs[buf][j*4+0][t] = f2tf32(p[j].x); Bs[buf][j*4+1][t] = f2tf32(p[j].y);
                Bs[buf][j*4+2][t] = f2tf32(p[j].z); Bs[buf][j*4+3][t] = f2tf32(p[j].w);
            }
            __syncthreads();
        }
    }
#pragma unroll
    for (int mt = 0; mt < 2; mt++) {
        int mrow = wm + mt * 16 + g;
#pragma unroll
        for (int nt = 0; nt < 8; nt++) {
            int col = n0 + wn + nt * 8 + tig * 2;
            float2 o0 = {acc[mt][nt][0], acc[mt][nt][1]};
            float2 o1 = {acc[mt][nt][2], acc[mt][nt][3]};
            *(float2*)(Ob + (size_t)mrow * L + col) = o0;
            *(float2*)(Ob + (size_t)(mrow + 8) * L + col) = o1;
        }
    }
}

// ---------------------------------------------------------------------------
// Launch
// ---------------------------------------------------------------------------
extern "C" void kernel_launch(void* const* d_in, const int* in_sizes, int n_in,
                              void* d_out, int out_size) {
    const float* x        = (const float*)d_in[0];
    const float* xorg     = (const float*)d_in[1];
    const float* abspos   = (const float*)d_in[2];
    const float* mask     = (const float*)d_in[3];
    const float* norm     = (const float*)d_in[4];
    const float* qkpos    = (const float*)d_in[5];
    const float* qkorg    = (const float*)d_in[6];
    const float* vorg     = (const float*)d_in[7];
    const float* relpos   = (const float*)d_in[8];
    const float* gate_w   = (const float*)d_in[9];
    const float* gate_b   = (const float*)d_in[10];
    const float* q_w      = (const float*)d_in[11];
    const float* k_w      = (const float*)d_in[12];
    const float* v_w      = (const float*)d_in[13];
    const float* dense_w  = (const float*)d_in[14];
    const float* dense_b  = (const float*)d_in[15];
    float* out = (float*)d_out;

    float *px0, *px1, *pq, *pk, *pv, *patt;
    cudaGetSymbolAddress((void**)&px0, g_x0);
    cudaGetSymbolAddress((void**)&px1, g_x1);
    cudaGetSymbolAddress((void**)&pq,  g_q);
    cudaGetSymbolAddress((void**)&pk,  g_k);
    cudaGetSymbolAddress((void**)&pv,  g_v);
    cudaGetSymbolAddress((void**)&patt, g_att);

    int total = NB * C * L;
    prep_kernel<<<(total + 255) / 256, 256>>>(x, xorg, abspos, qkpos, qkorg, vorg);

    dim3 gw(4, 3, NB);
    gemm_tc<false><<<gw, 256>>>(q_w, px1, pq, nullptr);
    gemm_tc<false><<<gw, 256>>>(k_w, px1, pk, nullptr);
    gemm_tc<false><<<gw, 256>>>(v_w, px0, pv, nullptr);

    gate_kernel<<<NB * H, L>>>(x, gate_w, gate_b);

    dim3 gs(3, 3, NB * H);
    scores_tc<<<gs, 256>>>();

    softmax_kernel<<<NB * H * L, 128>>>(relpos, mask, norm);

    dim3 gp(1, 3, NB * H);
    pv_tc<<<gp, 128>>>();

    gemm_tc<true><<<gw, 256>>>(dense_w, patt, out, dense_b);
}

// round 4
// speedup vs baseline: 1.9040x; 1.3317x over previous
#include <cuda_runtime.h>
#include <math.h>
#include <stdint.h>

constexpr int NB = 16, C = 512, L = 384, H = 8, D = 64, ME = 384;

__device__ float g_x0[NB * C * L];
__device__ float g_x1[NB * C * L];
__device__ float g_q [NB * C * L];
__device__ float g_k [NB * C * L];
__device__ float g_v [NB * C * L];
__device__ float g_att[NB * C * L];
__device__ float g_gate[NB * H * L];
__device__ float g_scores[(size_t)NB * H * L * L];
__device__ float g_wqT[C * C];
__device__ float g_wkT[C * C];
__device__ float g_wvT[C * C];
__device__ float g_wdT[C * C];

// ---------------------------------------------------------------------------
// helpers
// ---------------------------------------------------------------------------
__device__ __forceinline__ uint32_t f2tf32(float f) {
    uint32_t u;
    asm("cvt.rna.tf32.f32 %0, %1;" : "=r"(u) : "f"(f));
    return u;
}
__device__ __forceinline__ float tf32v(float f) { return __uint_as_float(f2tf32(f)); }

__device__ __forceinline__ void mma8(float* c, const uint32_t* a, const uint32_t* b) {
    asm("mma.sync.aligned.m16n8k8.row.col.f32.tf32.tf32.f32 "
        "{%0,%1,%2,%3}, {%4,%5,%6,%7}, {%8,%9}, {%0,%1,%2,%3};"
        : "+f"(c[0]), "+f"(c[1]), "+f"(c[2]), "+f"(c[3])
        : "r"(a[0]), "r"(a[1]), "r"(a[2]), "r"(a[3]), "r"(b[0]), "r"(b[1]));
}

// ---------------------------------------------------------------------------
// 1) Preprocess (outputs pre-rounded to tf32)
// ---------------------------------------------------------------------------
__global__ void prep_kernel(const float* __restrict__ x,
                            const float* __restrict__ xorg,
                            const float* __restrict__ abspos,
                            const float* __restrict__ qkpos,
                            const float* __restrict__ qkorg,
                            const float* __restrict__ vorg) {
    int i = blockIdx.x * blockDim.x + threadIdx.x;
    if (i >= NB * C * L) return;
    int c = (i / L) % C;
    int g = c >> 3;
    float xv = x[i], xo = xorg[i], ap = abspos[i];
    g_x0[i] = tf32v(xv + xo * vorg[g]);
    g_x1[i] = tf32v(xv + xo * qkorg[g] + ap * qkpos[g]);
}

// ---------------------------------------------------------------------------
// 1b) Batched weight transpose: Wt[k][m] = tf32(W[m][k]), 512x512 x4
// ---------------------------------------------------------------------------
__global__ void transpose4(const float* __restrict__ q_w, const float* __restrict__ k_w,
                           const float* __restrict__ v_w, const float* __restrict__ d_w) {
    __shared__ float tile[32][33];
    const float* src; float* dst;
    switch (blockIdx.z) {
        case 0: src = q_w; dst = g_wqT; break;
        case 1: src = k_w; dst = g_wkT; break;
        case 2: src = v_w; dst = g_wvT; break;
        default: src = d_w; dst = g_wdT; break;
    }
    int bm = blockIdx.x * 32, bk = blockIdx.y * 32;
    int tx = threadIdx.x, ty = threadIdx.y;
#pragma unroll
    for (int r = 0; r < 32; r += 8)
        tile[ty + r][tx] = src[(size_t)(bm + ty + r) * C + bk + tx];
    __syncthreads();
#pragma unroll
    for (int r = 0; r < 32; r += 8)
        dst[(size_t)(bk + ty + r) * C + bm + tx] = tf32v(tile[tx][ty + r]);
}

// ---------------------------------------------------------------------------
// Shared GEMM core: Out[m][l] = sum_k At[k][m] * B[k][l]
//   At row stride = C (512), B row stride = L. BM=BN=128, BK=16, 256 thr.
//   Operands must already be tf32-valued. Pure uint4 gmem->smem copies.
// ---------------------------------------------------------------------------
template <bool BIAS, bool ROUND>
__device__ __forceinline__ void gemm_core(
    const float* __restrict__ At, const float* __restrict__ B,
    float* __restrict__ Ob, const float* __restrict__ bias,
    int m0, int n0, uint32_t (*As)[16][132], uint32_t (*Bs)[16][132]) {
    int t = threadIdx.x;
    int br = t >> 4, bc = (t & 15) * 8;
    const uint4* Ap = (const uint4*)(At + (size_t)br * C + m0 + bc);
    const uint4* Bp = (const uint4*)(B + (size_t)br * L + n0 + bc);

    int w = t >> 5, lane = t & 31;
    int wm = (w >> 1) * 32, wn = (w & 1) * 64;
    int g = lane >> 2, tig = lane & 3;

    float acc[2][8][4] = {};
    uint4 a0, a1, b0, b1;
    a0 = Ap[0]; a1 = Ap[1];
    b0 = Bp[0]; b1 = Bp[1];

    int buf = 0;
    *(uint4*)&As[0][br][bc] = a0; *(uint4*)&As[0][br][bc + 4] = a1;
    *(uint4*)&Bs[0][br][bc] = b0; *(uint4*)&Bs[0][br][bc + 4] = b1;
    __syncthreads();

    for (int k0 = 0; k0 < C; k0 += 16) {
        bool nxt = (k0 + 16) < C;
        if (nxt) {
            const uint4* An = (const uint4*)((const float*)Ap + (size_t)(k0 + 16) * C);
            const uint4* Bn = (const uint4*)((const float*)Bp + (size_t)(k0 + 16) * L);
            a0 = An[0]; a1 = An[1];
            b0 = Bn[0]; b1 = Bn[1];
        }
#pragma unroll
        for (int ks = 0; ks < 16; ks += 8) {
            uint32_t af[2][4], bf[8][2];
#pragma unroll
            for (int mt = 0; mt < 2; mt++) {
                int m = wm + mt * 16;
                af[mt][0] = As[buf][ks + tig][m + g];
                af[mt][1] = As[buf][ks + tig][m + g + 8];
                af[mt][2] = As[buf][ks + tig + 4][m + g];
                af[mt][3] = As[buf][ks + tig + 4][m + g + 8];
            }
#pragma unroll
            for (int nt = 0; nt < 8; nt++) {
                bf[nt][0] = Bs[buf][ks + tig][wn + nt * 8 + g];
                bf[nt][1] = Bs[buf][ks + tig + 4][wn + nt * 8 + g];
            }
#pragma unroll
            for (int mt = 0; mt < 2; mt++)
#pragma unroll
                for (int nt = 0; nt < 8; nt++)
                    mma8(acc[mt][nt], af[mt], bf[nt]);
        }
        if (nxt) {
            buf ^= 1;
            *(uint4*)&As[buf][br][bc] = a0; *(uint4*)&As[buf][br][bc + 4] = a1;
            *(uint4*)&Bs[buf][br][bc] = b0; *(uint4*)&Bs[buf][br][bc + 4] = b1;
            __syncthreads();
        }
    }
#pragma unroll
    for (int mt = 0; mt < 2; mt++) {
        int mrow = m0 + wm + mt * 16 + g;
        float bv0 = BIAS ? bias[mrow] : 0.0f;
        float bv1 = BIAS ? bias[mrow + 8] : 0.0f;
#pragma unroll
        for (int nt = 0; nt < 8; nt++) {
            int col = n0 + wn + nt * 8 + tig * 2;
            float o00 = acc[mt][nt][0] + bv0, o01 = acc[mt][nt][1] + bv0;
            float o10 = acc[mt][nt][2] + bv1, o11 = acc[mt][nt][3] + bv1;
            if (ROUND) { o00 = tf32v(o00); o01 = tf32v(o01); o10 = tf32v(o10); o11 = tf32v(o11); }
            *(float2*)(Ob + (size_t)mrow * L + col) = make_float2(o00, o01);
            *(float2*)(Ob + (size_t)(mrow + 8) * L + col) = make_float2(o10, o11);
        }
    }
}

// 2a) Fused q/k/v GEMMs: z = b*3 + which
__global__ void __launch_bounds__(256) qkv_gemm() {
    __shared__ uint32_t As[2][16][132];
    __shared__ uint32_t Bs[2][16][132];
    int z = blockIdx.z;
    int b = z / 3, which = z - 3 * b;
    const float* At = (which == 0) ? g_wqT : (which == 1) ? g_wkT : g_wvT;
    const float* X = ((which == 2) ? g_x0 : g_x1) + (size_t)b * C * L;
    float* Ob = ((which == 0) ? g_q : (which == 1) ? g_k : g_v) + (size_t)b * C * L;
    gemm_core<false, true>(At, X, Ob, nullptr, blockIdx.x * 128, blockIdx.y * 128, As, Bs);
}

// 2b) Dense GEMM
__global__ void __launch_bounds__(256) dense_gemm(float* __restrict__ Out,
                                                  const float* __restrict__ bias) {
    __shared__ uint32_t As[2][16][132];
    __shared__ uint32_t Bs[2][16][132];
    int b = blockIdx.z;
    gemm_core<true, false>(g_wdT, g_att + (size_t)b * C * L, Out + (size_t)b * C * L,
                           bias, blockIdx.x * 128, blockIdx.y * 128, As, Bs);
}

// ---------------------------------------------------------------------------
// 3) Gate
// ---------------------------------------------------------------------------
__global__ void gate_kernel(const float* __restrict__ x,
                            const float* __restrict__ gate_w,
                            const float* __restrict__ gate_b) {
    int z = blockIdx.x;
    int n = z / H, h = z % H;
    int l = threadIdx.x;
    const float* xb = x + (size_t)n * C * L + l;
    const float* wv = gate_w + h * C;
    float acc = gate_b[h];
    for (int c = 0; c < C; c++)
        acc = fmaf(wv[c], xb[(size_t)c * L], acc);
    g_gate[(size_t)z * L + l] = acc;
}

// ---------------------------------------------------------------------------
// 4) Scores (tf32 MMA), operands pre-rounded -> direct uint4 copies
// ---------------------------------------------------------------------------
__global__ void __launch_bounds__(256) scores_tc() {
    __shared__ uint32_t As[2][16][132];
    __shared__ uint32_t Bs[2][16][132];
    int z = blockIdx.z;
    const float* Qb = g_q + (size_t)z * D * L;
    const float* Kb = g_k + (size_t)z * D * L;
    float* Sb = g_scores + (size_t)z * L * L;
    int m0 = blockIdx.x * 128, n0 = blockIdx.y * 128;
    int t = threadIdx.x;
    int br = t >> 4, bc = (t & 15) * 8;
    const uint4* Qp = (const uint4*)(Qb + (size_t)br * L + m0 + bc);
    const uint4* Kp = (const uint4*)(Kb + (size_t)br * L + n0 + bc);

    int w = t >> 5, lane = t & 31;
    int wm = (w >> 1) * 32, wn = (w & 1) * 64;
    int g = lane >> 2, tig = lane & 3;

    float acc[2][8][4] = {};
    uint4 qa0, qa1, ka0, ka1;
    qa0 = Qp[0]; qa1 = Qp[1];
    ka0 = Kp[0]; ka1 = Kp[1];

    int buf = 0;
    *(uint4*)&As[0][br][bc] = qa0; *(uint4*)&As[0][br][bc + 4] = qa1;
    *(uint4*)&Bs[0][br][bc] = ka0; *(uint4*)&Bs[0][br][bc + 4] = ka1;
    __syncthreads();

    for (int k0 = 0; k0 < D; k0 += 16) {
        bool nxt = (k0 + 16) < D;
        if (nxt) {
            const uint4* Qn = (const uint4*)((const float*)Qp + (size_t)(k0 + 16) * L);
            const uint4* Kn = (const uint4*)((const float*)Kp + (size_t)(k0 + 16) * L);
            qa0 = Qn[0]; qa1 = Qn[1];
            ka0 = Kn[0]; ka1 = Kn[1];
        }
#pragma unroll
        for (int ks = 0; ks < 16; ks += 8) {
            uint32_t af[2][4], bf[8][2];
#pragma unroll
            for (int mt = 0; mt < 2; mt++) {
                int m = wm + mt * 16;
                af[mt][0] = As[buf][ks + tig][m + g];
                af[mt][1] = As[buf][ks + tig][m + g + 8];
                af[mt][2] = As[buf][ks + tig + 4][m + g];
                af[mt][3] = As[buf][ks + tig + 4][m + g + 8];
            }
#pragma unroll
            for (int nt = 0; nt < 8; nt++) {
                bf[nt][0] = Bs[buf][ks + tig][wn + nt * 8 + g];
                bf[nt][1] = Bs[buf][ks + tig + 4][wn + nt * 8 + g];
            }
#pragma unroll
            for (int mt = 0; mt < 2; mt++)
#pragma unroll
                for (int nt = 0; nt < 8; nt++)
                    mma8(acc[mt][nt], af[mt], bf[nt]);
        }
        if (nxt) {
            buf ^= 1;
            *(uint4*)&As[buf][br][bc] = qa0; *(uint4*)&As[buf][br][bc + 4] = qa1;
            *(uint4*)&Bs[buf][br][bc] = ka0; *(uint4*)&Bs[buf][br][bc + 4] = ka1;
            __syncthreads();
        }
    }
#pragma unroll
    for (int mt = 0; mt < 2; mt++) {
        int mrow = m0 + wm + mt * 16 + g;
#pragma unroll
        for (int nt = 0; nt < 8; nt++) {
            int col = n0 + wn + nt * 8 + tig * 2;
            *(float2*)(Sb + (size_t)mrow * L + col) = make_float2(acc[mt][nt][0], acc[mt][nt][1]);
            *(float2*)(Sb + (size_t)(mrow + 8) * L + col) = make_float2(acc[mt][nt][2], acc[mt][nt][3]);
        }
    }
}

// ---------------------------------------------------------------------------
// 5) Softmax (stores tf32-rounded probabilities)
// ---------------------------------------------------------------------------
__global__ void softmax_kernel(const float* __restrict__ relpos,
                               const float* __restrict__ mask,
                               const float* __restrict__ norm) {
    __shared__ float red[128];
    int row = blockIdx.x;
    int i  = row % L;
    int nh = row / L;
    int n  = nh / H;
    float* S = g_scores + (size_t)row * L;
    const float* gt = g_gate + (size_t)nh * L;
    const float* mk = mask + (size_t)n * L;
    float inv = 1.0f / norm[n];
    int t = threadIdx.x;

    int j0 = t, j1 = t + 128, j2 = t + 256;
    float v0 = (S[j0] + relpos[min(ME - i + j0, 2 * ME - 2)] + gt[j0] + mk[j0]) * inv;
    float v1 = (S[j1] + relpos[min(ME - i + j1, 2 * ME - 2)] + gt[j1] + mk[j1]) * inv;
    float v2 = (S[j2] + relpos[min(ME - i + j2, 2 * ME - 2)] + gt[j2] + mk[j2]) * inv;

    float mx = fmaxf(v0, fmaxf(v1, v2));
    red[t] = mx;
    __syncthreads();
    for (int s = 64; s > 0; s >>= 1) {
        if (t < s) red[t] = fmaxf(red[t], red[t + s]);
        __syncthreads();
    }
    mx = red[0];
    __syncthreads();

    v0 = __expf(v0 - mx); v1 = __expf(v1 - mx); v2 = __expf(v2 - mx);
    red[t] = v0 + v1 + v2;
    __syncthreads();
    for (int s = 64; s > 0; s >>= 1) {
        if (t < s) red[t] += red[t + s];
        __syncthreads();
    }
    float r = 1.0f / red[0];
    S[j0] = tf32v(v0 * r);
    S[j1] = tf32v(v1 * r);
    S[j2] = tf32v(v2 * r);
}

// ---------------------------------------------------------------------------
// 6) PV (tf32 MMA): out[z][d][i] = sum_j P[z][i][j] V[z][d][j]
//    Operands pre-rounded; outputs tf32-rounded (consumed by dense).
// ---------------------------------------------------------------------------
__global__ void __launch_bounds__(128) pv_tc() {
    __shared__ uint32_t As[2][16][68];
    __shared__ uint32_t Bs[2][16][132];
    int z = blockIdx.z;
    const float* Vb = g_v + (size_t)z * D * L;
    const float* Pb = g_scores + (size_t)z * L * L;
    float* Ob = g_att + (size_t)z * D * L;
    int n0 = blockIdx.y * 128;
    int t = threadIdx.x;

    int am = t & 63, ac = t >> 6;
    const float* Ap = Vb + (size_t)am * L;
    const float* Pp = Pb + (size_t)(n0 + t) * L;

    int w = t >> 5, lane = t & 31;
    int wm = (w >> 1) * 32, wn = (w & 1) * 64;
    int g = lane >> 2, tig = lane & 3;

    float acc[2][8][4] = {};
    float4 a[2], p[4];
    a[0] = *(const float4*)(Ap + ac * 4);
    a[1] = *(const float4*)(Ap + (ac + 2) * 4);
    p[0] = *(const float4*)Pp;       p[1] = *(const float4*)(Pp + 4);
    p[2] = *(const float4*)(Pp + 8); p[3] = *(const float4*)(Pp + 12);

    int buf = 0;
#pragma unroll
    for (int s = 0; s < 2; s++) {
        int kq = (ac + 2 * s) * 4;
        As[0][kq + 0][am] = __float_as_uint(a[s].x); As[0][kq + 1][am] = __float_as_uint(a[s].y);
        As[0][kq + 2][am] = __float_as_uint(a[s].z); As[0][kq + 3][am] = __float_as_uint(a[s].w);
    }
#pragma unroll
    for (int j = 0; j < 4; j++) {
        Bs[0][j*4+0][t] = __float_as_uint(p[j].x); Bs[0][j*4+1][t] = __float_as_uint(p[j].y);
        Bs[0][j*4+2][t] = __float_as_uint(p[j].z); Bs[0][j*4+3][t] = __float_as_uint(p[j].w);
    }
    __syncthreads();

    for (int k0 = 0; k0 < L; k0 += 16) {
        bool nxt = (k0 + 16) < L;
        if (nxt) {
            const float* An = Ap + k0 + 16;
            a[0] = *(const float4*)(An + ac * 4);
            a[1] = *(const float4*)(An + (ac + 2) * 4);
            const float* Pn = Pp + k0 + 16;
            p[0] = *(const float4*)Pn;       p[1] = *(const float4*)(Pn + 4);
            p[2] = *(const float4*)(Pn + 8); p[3] = *(const float4*)(Pn + 12);
        }
#pragma unroll
        for (int ks = 0; ks < 16; ks += 8) {
            uint32_t af[2][4], bf[8][2];
#pragma unroll
            for (int mt = 0; mt < 2; mt++) {
                int m = wm + mt * 16;
                af[mt][0] = As[buf][ks + tig][m + g];
                af[mt][1] = As[buf][ks + tig][m + g + 8];
                af[mt][2] = As[buf][ks + tig + 4][m + g];
                af[mt][3] = As[buf][ks + tig + 4][m + g + 8];
            }
#pragma unroll
            for (int nt = 0; nt < 8; nt++) {
                bf[nt][0] = Bs[buf][ks + tig][wn + nt * 8 + g];
                bf[nt][1] = Bs[buf][ks + tig + 4][wn + nt * 8 + g];
            }
#pragma unroll
            for (int mt = 0; mt < 2; mt++)
#pragma unroll
                for (int nt = 0; nt < 8; nt++)
                    mma8(acc[mt][nt], af[mt], bf[nt]);
        }
        if (nxt) {
            buf ^= 1;
#pragma unroll
            for (int s = 0; s < 2; s++) {
                int kq = (ac + 2 * s) * 4;
                As[buf][kq + 0][am] = __float_as_uint(a[s].x); As[buf][kq + 1][am] = __float_as_uint(a[s].y);
                As[buf][kq + 2][am] = __float_as_uint(a[s].z); As[buf][kq + 3][am] = __float_as_uint(a[s].w);
            }
#pragma unroll
            for (int j = 0; j < 4; j++) {
                Bs[buf][j*4+0][t] = __float_as_uint(p[j].x); Bs[buf][j*4+1][t] = __float_as_uint(p[j].y);
                Bs[buf][j*4+2][t] = __float_as_uint(p[j].z); Bs[buf][j*4+3][t] = __float_as_uint(p[j].w);
            }
            __syncthreads();
        }
    }
#pragma unroll
    for (int mt = 0; mt < 2; mt++) {
        int mrow = wm + mt * 16 + g;
#pragma unroll
        for (int nt = 0; nt < 8; nt++) {
            int col = n0 + wn + nt * 8 + tig * 2;
            *(float2*)(Ob + (size_t)mrow * L + col) =
                make_float2(tf32v(acc[mt][nt][0]), tf32v(acc[mt][nt][1]));
            *(float2*)(Ob + (size_t)(mrow + 8) * L + col) =
                make_float2(tf32v(acc[mt][nt][2]), tf32v(acc[mt][nt][3]));
        }
    }
}

// ---------------------------------------------------------------------------
// Launch
// ---------------------------------------------------------------------------
extern "C" void kernel_launch(void* const* d_in, const int* in_sizes, int n_in,
                              void* d_out, int out_size) {
    const float* x        = (const float*)d_in[0];
    const float* xorg     = (const float*)d_in[1];
    const float* abspos   = (const float*)d_in[2];
    const float* mask     = (const float*)d_in[3];
    const float* norm     = (const float*)d_in[4];
    const float* qkpos    = (const float*)d_in[5];
    const float* qkorg    = (const float*)d_in[6];
    const float* vorg     = (const float*)d_in[7];
    const float* relpos   = (const float*)d_in[8];
    const float* gate_w   = (const float*)d_in[9];
    const float* gate_b   = (const float*)d_in[10];
    const float* q_w      = (const float*)d_in[11];
    const float* k_w      = (const float*)d_in[12];
    const float* v_w      = (const float*)d_in[13];
    const float* dense_w  = (const float*)d_in[14];
    const float* dense_b  = (const float*)d_in[15];
    float* out = (float*)d_out;

    int total = NB * C * L;
    prep_kernel<<<(total + 255) / 256, 256>>>(x, xorg, abspos, qkpos, qkorg, vorg);
    transpose4<<<dim3(16, 16, 4), dim3(32, 8)>>>(q_w, k_w, v_w, dense_w);

    qkv_gemm<<<dim3(4, 3, NB * 3), 256>>>();

    gate_kernel<<<NB * H, L>>>(x, gate_w, gate_b);

    scores_tc<<<dim3(3, 3, NB * H), 256>>>();

    softmax_kernel<<<NB * H * L, 128>>>(relpos, mask, norm);

    pv_tc<<<dim3(1, 3, NB * H), 128>>>();

    dense_gemm<<<dim3(4, 3, NB), 256>>>(out, dense_b);
}

// round 5
// speedup vs baseline: 1.9933x; 1.0469x over previous
#include <cuda_runtime.h>
#include <math.h>
#include <stdint.h>

constexpr int NB = 16, C = 512, L = 384, H = 8, D = 64, ME = 384;

__device__ float g_x0[NB * C * L];
__device__ float g_x1[NB * C * L];
__device__ float g_q [NB * C * L];
__device__ float g_k [NB * C * L];
__device__ float g_v [NB * C * L];
__device__ float g_att[NB * C * L];
__device__ float g_gate[NB * H * L];
__device__ float g_scores[(size_t)NB * H * L * L];
__device__ float g_wqT[C * C];
__device__ float g_wkT[C * C];
__device__ float g_wvT[C * C];
__device__ float g_wdT[C * C];

// ---------------------------------------------------------------------------
// helpers
// ---------------------------------------------------------------------------
__device__ __forceinline__ uint32_t f2tf32(float f) {
    uint32_t u;
    asm("cvt.rna.tf32.f32 %0, %1;" : "=r"(u) : "f"(f));
    return u;
}
__device__ __forceinline__ float tf32v(float f) { return __uint_as_float(f2tf32(f)); }

__device__ __forceinline__ void mma8(float* c, const uint32_t* a, const uint32_t* b) {
    asm("mma.sync.aligned.m16n8k8.row.col.f32.tf32.tf32.f32 "
        "{%0,%1,%2,%3}, {%4,%5,%6,%7}, {%8,%9}, {%0,%1,%2,%3};"
        : "+f"(c[0]), "+f"(c[1]), "+f"(c[2]), "+f"(c[3])
        : "r"(a[0]), "r"(a[1]), "r"(a[2]), "r"(a[3]), "r"(b[0]), "r"(b[1]));
}

// ---------------------------------------------------------------------------
// 1) Preprocess (outputs pre-rounded to tf32)
// ---------------------------------------------------------------------------
__global__ void prep_kernel(const float* __restrict__ x,
                            const float* __restrict__ xorg,
                            const float* __restrict__ abspos,
                            const float* __restrict__ qkpos,
                            const float* __restrict__ qkorg,
                            const float* __restrict__ vorg) {
    int i = blockIdx.x * blockDim.x + threadIdx.x;
    if (i >= NB * C * L) return;
    int c = (i / L) % C;
    int g = c >> 3;
    float xv = x[i], xo = xorg[i], ap = abspos[i];
    g_x0[i] = tf32v(xv + xo * vorg[g]);
    g_x1[i] = tf32v(xv + xo * qkorg[g] + ap * qkpos[g]);
}

// ---------------------------------------------------------------------------
// 1b) Batched weight transpose: Wt[k][m] = tf32(W[m][k]), 512x512 x4
// ---------------------------------------------------------------------------
__global__ void transpose4(const float* __restrict__ q_w, const float* __restrict__ k_w,
                           const float* __restrict__ v_w, const float* __restrict__ d_w) {
    __shared__ float tile[32][33];
    const float* src; float* dst;
    switch (blockIdx.z) {
        case 0: src = q_w; dst = g_wqT; break;
        case 1: src = k_w; dst = g_wkT; break;
        case 2: src = v_w; dst = g_wvT; break;
        default: src = d_w; dst = g_wdT; break;
    }
    int bm = blockIdx.x * 32, bk = blockIdx.y * 32;
    int tx = threadIdx.x, ty = threadIdx.y;
#pragma unroll
    for (int r = 0; r < 32; r += 8)
        tile[ty + r][tx] = src[(size_t)(bm + ty + r) * C + bk + tx];
    __syncthreads();
#pragma unroll
    for (int r = 0; r < 32; r += 8)
        dst[(size_t)(bk + ty + r) * C + bm + tx] = tf32v(tile[tx][ty + r]);
}

// ---------------------------------------------------------------------------
// Shared GEMM core: Out[m][l] = sum_k At[k][m] * B[k][l]
// ---------------------------------------------------------------------------
template <bool BIAS, bool ROUND>
__device__ __forceinline__ void gemm_core(
    const float* __restrict__ At, const float* __restrict__ B,
    float* __restrict__ Ob, const float* __restrict__ bias,
    int m0, int n0, uint32_t (*As)[16][132], uint32_t (*Bs)[16][132]) {
    int t = threadIdx.x;
    int br = t >> 4, bc = (t & 15) * 8;
    const uint4* Ap = (const uint4*)(At + (size_t)br * C + m0 + bc);
    const uint4* Bp = (const uint4*)(B + (size_t)br * L + n0 + bc);

    int w = t >> 5, lane = t & 31;
    int wm = (w >> 1) * 32, wn = (w & 1) * 64;
    int g = lane >> 2, tig = lane & 3;

    float acc[2][8][4] = {};
    uint4 a0, a1, b0, b1;
    a0 = Ap[0]; a1 = Ap[1];
    b0 = Bp[0]; b1 = Bp[1];

    int buf = 0;
    *(uint4*)&As[0][br][bc] = a0; *(uint4*)&As[0][br][bc + 4] = a1;
    *(uint4*)&Bs[0][br][bc] = b0; *(uint4*)&Bs[0][br][bc + 4] = b1;
    __syncthreads();

    for (int k0 = 0; k0 < C; k0 += 16) {
        bool nxt = (k0 + 16) < C;
        if (nxt) {
            const uint4* An = (const uint4*)((const float*)Ap + (size_t)(k0 + 16) * C);
            const uint4* Bn = (const uint4*)((const float*)Bp + (size_t)(k0 + 16) * L);
            a0 = An[0]; a1 = An[1];
            b0 = Bn[0]; b1 = Bn[1];
        }
#pragma unroll
        for (int ks = 0; ks < 16; ks += 8) {
            uint32_t af[2][4], bf[8][2];
#pragma unroll
            for (int mt = 0; mt < 2; mt++) {
                int m = wm + mt * 16;
                af[mt][0] = As[buf][ks + tig][m + g];
                af[mt][1] = As[buf][ks + tig][m + g + 8];
                af[mt][2] = As[buf][ks + tig + 4][m + g];
                af[mt][3] = As[buf][ks + tig + 4][m + g + 8];
            }
#pragma unroll
            for (int nt = 0; nt < 8; nt++) {
                bf[nt][0] = Bs[buf][ks + tig][wn + nt * 8 + g];
                bf[nt][1] = Bs[buf][ks + tig + 4][wn + nt * 8 + g];
            }
#pragma unroll
            for (int mt = 0; mt < 2; mt++)
#pragma unroll
                for (int nt = 0; nt < 8; nt++)
                    mma8(acc[mt][nt], af[mt], bf[nt]);
        }
        if (nxt) {
            buf ^= 1;
            *(uint4*)&As[buf][br][bc] = a0; *(uint4*)&As[buf][br][bc + 4] = a1;
            *(uint4*)&Bs[buf][br][bc] = b0; *(uint4*)&Bs[buf][br][bc + 4] = b1;
            __syncthreads();
        }
    }
#pragma unroll
    for (int mt = 0; mt < 2; mt++) {
        int mrow = m0 + wm + mt * 16 + g;
        float bv0 = BIAS ? bias[mrow] : 0.0f;
        float bv1 = BIAS ? bias[mrow + 8] : 0.0f;
#pragma unroll
        for (int nt = 0; nt < 8; nt++) {
            int col = n0 + wn + nt * 8 + tig * 2;
            float o00 = acc[mt][nt][0] + bv0, o01 = acc[mt][nt][1] + bv0;
            float o10 = acc[mt][nt][2] + bv1, o11 = acc[mt][nt][3] + bv1;
            if (ROUND) { o00 = tf32v(o00); o01 = tf32v(o01); o10 = tf32v(o10); o11 = tf32v(o11); }
            *(float2*)(Ob + (size_t)mrow * L + col) = make_float2(o00, o01);
            *(float2*)(Ob + (size_t)(mrow + 8) * L + col) = make_float2(o10, o11);
        }
    }
}

// 2a) Fused q/k/v GEMMs: z = b*3 + which
__global__ void __launch_bounds__(256) qkv_gemm() {
    __shared__ uint32_t As[2][16][132];
    __shared__ uint32_t Bs[2][16][132];
    int z = blockIdx.z;
    int b = z / 3, which = z - 3 * b;
    const float* At = (which == 0) ? g_wqT : (which == 1) ? g_wkT : g_wvT;
    const float* X = ((which == 2) ? g_x0 : g_x1) + (size_t)b * C * L;
    float* Ob = ((which == 0) ? g_q : (which == 1) ? g_k : g_v) + (size_t)b * C * L;
    gemm_core<false, true>(At, X, Ob, nullptr, blockIdx.x * 128, blockIdx.y * 128, As, Bs);
}

// 2b) Dense GEMM
__global__ void __launch_bounds__(256) dense_gemm(float* __restrict__ Out,
                                                  const float* __restrict__ bias) {
    __shared__ uint32_t As[2][16][132];
    __shared__ uint32_t Bs[2][16][132];
    int b = blockIdx.z;
    gemm_core<true, false>(g_wdT, g_att + (size_t)b * C * L, Out + (size_t)b * C * L,
                           bias, blockIdx.x * 128, blockIdx.y * 128, As, Bs);
}

// ---------------------------------------------------------------------------
// 3) Gate: gate[n][h][l] = sum_c gate_w[h][c] x[n][c][l] + gate_b[h]
//    Block = (n, 128-l tile); weights in smem; 8 accumulators per thread.
// ---------------------------------------------------------------------------
__global__ void __launch_bounds__(128) gate_kernel(const float* __restrict__ x,
                                                   const float* __restrict__ gate_w,
                                                   const float* __restrict__ gate_b) {
    __shared__ float ws[H * C];          // 16 KB
    int n = blockIdx.y;
    int l = blockIdx.x * 128 + threadIdx.x;
    int t = threadIdx.x;
#pragma unroll
    for (int i = 0; i < H * C / (128 * 4); i++)
        *(float4*)&ws[(i * 128 + t) * 4] = *(const float4*)&gate_w[(i * 128 + t) * 4];
    __syncthreads();

    const float* xb = x + (size_t)n * C * L + l;
    float acc[H];
#pragma unroll
    for (int h = 0; h < H; h++) acc[h] = gate_b[h];
    for (int c = 0; c < C; c++) {
        float xv = xb[(size_t)c * L];
#pragma unroll
        for (int h = 0; h < H; h++)
            acc[h] = fmaf(ws[h * C + c], xv, acc[h]);
    }
#pragma unroll
    for (int h = 0; h < H; h++)
        g_gate[((size_t)n * H + h) * L + l] = acc[h];
}

// ---------------------------------------------------------------------------
// 4) Scores (tf32 MMA)
// ---------------------------------------------------------------------------
__global__ void __launch_bounds__(256) scores_tc() {
    __shared__ uint32_t As[2][16][132];
    __shared__ uint32_t Bs[2][16][132];
    int z = blockIdx.z;
    const float* Qb = g_q + (size_t)z * D * L;
    const float* Kb = g_k + (size_t)z * D * L;
    float* Sb = g_scores + (size_t)z * L * L;
    int m0 = blockIdx.x * 128, n0 = blockIdx.y * 128;
    int t = threadIdx.x;
    int br = t >> 4, bc = (t & 15) * 8;
    const uint4* Qp = (const uint4*)(Qb + (size_t)br * L + m0 + bc);
    const uint4* Kp = (const uint4*)(Kb + (size_t)br * L + n0 + bc);

    int w = t >> 5, lane = t & 31;
    int wm = (w >> 1) * 32, wn = (w & 1) * 64;
    int g = lane >> 2, tig = lane & 3;

    float acc[2][8][4] = {};
    uint4 qa0, qa1, ka0, ka1;
    qa0 = Qp[0]; qa1 = Qp[1];
    ka0 = Kp[0]; ka1 = Kp[1];

    int buf = 0;
    *(uint4*)&As[0][br][bc] = qa0; *(uint4*)&As[0][br][bc + 4] = qa1;
    *(uint4*)&Bs[0][br][bc] = ka0; *(uint4*)&Bs[0][br][bc + 4] = ka1;
    __syncthreads();

    for (int k0 = 0; k0 < D; k0 += 16) {
        bool nxt = (k0 + 16) < D;
        if (nxt) {
            const uint4* Qn = (const uint4*)((const float*)Qp + (size_t)(k0 + 16) * L);
            const uint4* Kn = (const uint4*)((const float*)Kp + (size_t)(k0 + 16) * L);
            qa0 = Qn[0]; qa1 = Qn[1];
            ka0 = Kn[0]; ka1 = Kn[1];
        }
#pragma unroll
        for (int ks = 0; ks < 16; ks += 8) {
            uint32_t af[2][4], bf[8][2];
#pragma unroll
            for (int mt = 0; mt < 2; mt++) {
                int m = wm + mt * 16;
                af[mt][0] = As[buf][ks + tig][m + g];
                af[mt][1] = As[buf][ks + tig][m + g + 8];
                af[mt][2] = As[buf][ks + tig + 4][m + g];
                af[mt][3] = As[buf][ks + tig + 4][m + g + 8];
            }
#pragma unroll
            for (int nt = 0; nt < 8; nt++) {
                bf[nt][0] = Bs[buf][ks + tig][wn + nt * 8 + g];
                bf[nt][1] = Bs[buf][ks + tig + 4][wn + nt * 8 + g];
            }
#pragma unroll
            for (int mt = 0; mt < 2; mt++)
#pragma unroll
                for (int nt = 0; nt < 8; nt++)
                    mma8(acc[mt][nt], af[mt], bf[nt]);
        }
        if (nxt) {
            buf ^= 1;
            *(uint4*)&As[buf][br][bc] = qa0; *(uint4*)&As[buf][br][bc + 4] = qa1;
            *(uint4*)&Bs[buf][br][bc] = ka0; *(uint4*)&Bs[buf][br][bc + 4] = ka1;
            __syncthreads();
        }
    }
#pragma unroll
    for (int mt = 0; mt < 2; mt++) {
        int mrow = m0 + wm + mt * 16 + g;
#pragma unroll
        for (int nt = 0; nt < 8; nt++) {
            int col = n0 + wn + nt * 8 + tig * 2;
            *(float2*)(Sb + (size_t)mrow * L + col) = make_float2(acc[mt][nt][0], acc[mt][nt][1]);
            *(float2*)(Sb + (size_t)(mrow + 8) * L + col) = make_float2(acc[mt][nt][2], acc[mt][nt][3]);
        }
    }
}

// ---------------------------------------------------------------------------
// 5) Softmax: one warp per row, shuffle reductions, vectorized loads.
// ---------------------------------------------------------------------------
__global__ void __launch_bounds__(256) softmax_kernel(const float* __restrict__ relpos,
                                                      const float* __restrict__ mask,
                                                      const float* __restrict__ norm) {
    int wid = threadIdx.x >> 5, lane = threadIdx.x & 31;
    int row = blockIdx.x * 8 + wid;       // (n*H + h)*L + i
    int i  = row % L;
    int nh = row / L;
    int n  = nh / H;
    float* S = g_scores + (size_t)row * L;
    const float* gt = g_gate + (size_t)nh * L;
    const float* mk = mask + (size_t)n * L;
    float inv = 1.0f / norm[n];

    float v[12];
#pragma unroll
    for (int s = 0; s < 3; s++) {
        int j = s * 128 + lane * 4;
        float4 sv = *(const float4*)(S + j);
        float4 gv = *(const float4*)(gt + j);
        float4 mv = *(const float4*)(mk + j);
        int base = ME - i + j;
        v[s*4+0] = (sv.x + relpos[min(base + 0, 2*ME-2)] + gv.x + mv.x) * inv;
        v[s*4+1] = (sv.y + relpos[min(base + 1, 2*ME-2)] + gv.y + mv.y) * inv;
        v[s*4+2] = (sv.z + relpos[min(base + 2, 2*ME-2)] + gv.z + mv.z) * inv;
        v[s*4+3] = (sv.w + relpos[min(base + 3, 2*ME-2)] + gv.w + mv.w) * inv;
    }
    float mx = v[0];
#pragma unroll
    for (int q = 1; q < 12; q++) mx = fmaxf(mx, v[q]);
#pragma unroll
    for (int o = 16; o > 0; o >>= 1)
        mx = fmaxf(mx, __shfl_xor_sync(0xffffffff, mx, o));

    float sum = 0.0f;
#pragma unroll
    for (int q = 0; q < 12; q++) { v[q] = __expf(v[q] - mx); sum += v[q]; }
#pragma unroll
    for (int o = 16; o > 0; o >>= 1)
        sum += __shfl_xor_sync(0xffffffff, sum, o);
    float r = 1.0f / sum;

#pragma unroll
    for (int s = 0; s < 3; s++) {
        int j = s * 128 + lane * 4;
        float4 ov;
        ov.x = tf32v(v[s*4+0] * r); ov.y = tf32v(v[s*4+1] * r);
        ov.z = tf32v(v[s*4+2] * r); ov.w = tf32v(v[s*4+3] * r);
        *(float4*)(S + j) = ov;
    }
}

// ---------------------------------------------------------------------------
// 6) PV (tf32 MMA)
// ---------------------------------------------------------------------------
__global__ void __launch_bounds__(128) pv_tc() {
    __shared__ uint32_t As[2][16][68];
    __shared__ uint32_t Bs[2][16][132];
    int z = blockIdx.z;
    const float* Vb = g_v + (size_t)z * D * L;
    const float* Pb = g_scores + (size_t)z * L * L;
    float* Ob = g_att + (size_t)z * D * L;
    int n0 = blockIdx.y * 128;
    int t = threadIdx.x;

    int am = t & 63, ac = t >> 6;
    const float* Ap = Vb + (size_t)am * L;
    const float* Pp = Pb + (size_t)(n0 + t) * L;

    int w = t >> 5, lane = t & 31;
    int wm = (w >> 1) * 32, wn = (w & 1) * 64;
    int g = lane >> 2, tig = lane & 3;

    float acc[2][8][4] = {};
    float4 a[2], p[4];
    a[0] = *(const float4*)(Ap + ac * 4);
    a[1] = *(const float4*)(Ap + (ac + 2) * 4);
    p[0] = *(const float4*)Pp;       p[1] = *(const float4*)(Pp + 4);
    p[2] = *(const float4*)(Pp + 8); p[3] = *(const float4*)(Pp + 12);

    int buf = 0;
#pragma unroll
    for (int s = 0; s < 2; s++) {
        int kq = (ac + 2 * s) * 4;
        As[0][kq + 0][am] = __float_as_uint(a[s].x); As[0][kq + 1][am] = __float_as_uint(a[s].y);
        As[0][kq + 2][am] = __float_as_uint(a[s].z); As[0][kq + 3][am] = __float_as_uint(a[s].w);
    }
#pragma unroll
    for (int j = 0; j < 4; j++) {
        Bs[0][j*4+0][t] = __float_as_uint(p[j].x); Bs[0][j*4+1][t] = __float_as_uint(p[j].y);
        Bs[0][j*4+2][t] = __float_as_uint(p[j].z); Bs[0][j*4+3][t] = __float_as_uint(p[j].w);
    }
    __syncthreads();

    for (int k0 = 0; k0 < L; k0 += 16) {
        bool nxt = (k0 + 16) < L;
        if (nxt) {
            const float* An = Ap + k0 + 16;
            a[0] = *(const float4*)(An + ac * 4);
            a[1] = *(const float4*)(An + (ac + 2) * 4);
            const float* Pn = Pp + k0 + 16;
            p[0] = *(const float4*)Pn;       p[1] = *(const float4*)(Pn + 4);
            p[2] = *(const float4*)(Pn + 8); p[3] = *(const float4*)(Pn + 12);
        }
#pragma unroll
        for (int ks = 0; ks < 16; ks += 8) {
            uint32_t af[2][4], bf[8][2];
#pragma unroll
            for (int mt = 0; mt < 2; mt++) {
                int m = wm + mt * 16;
                af[mt][0] = As[buf][ks + tig][m + g];
                af[mt][1] = As[buf][ks + tig][m + g + 8];
                af[mt][2] = As[buf][ks + tig + 4][m + g];
                af[mt][3] = As[buf][ks + tig + 4][m + g + 8];
            }
#pragma unroll
            for (int nt = 0; nt < 8; nt++) {
                bf[nt][0] = Bs[buf][ks + tig][wn + nt * 8 + g];
                bf[nt][1] = Bs[buf][ks + tig + 4][wn + nt * 8 + g];
            }
#pragma unroll
            for (int mt = 0; mt < 2; mt++)
#pragma unroll
                for (int nt = 0; nt < 8; nt++)
                    mma8(acc[mt][nt], af[mt], bf[nt]);
        }
        if (nxt) {
            buf ^= 1;
#pragma unroll
            for (int s = 0; s < 2; s++) {
                int kq = (ac + 2 * s) * 4;
                As[buf][kq + 0][am] = __float_as_uint(a[s].x); As[buf][kq + 1][am] = __float_as_uint(a[s].y);
                As[buf][kq + 2][am] = __float_as_uint(a[s].z); As[buf][kq + 3][am] = __float_as_uint(a[s].w);
            }
#pragma unroll
            for (int j = 0; j < 4; j++) {
                Bs[buf][j*4+0][t] = __float_as_uint(p[j].x); Bs[buf][j*4+1][t] = __float_as_uint(p[j].y);
                Bs[buf][j*4+2][t] = __float_as_uint(p[j].z); Bs[buf][j*4+3][t] = __float_as_uint(p[j].w);
            }
            __syncthreads();
        }
    }
#pragma unroll
    for (int mt = 0; mt < 2; mt++) {
        int mrow = wm + mt * 16 + g;
#pragma unroll
        for (int nt = 0; nt < 8; nt++) {
            int col = n0 + wn + nt * 8 + tig * 2;
            *(float2*)(Ob + (size_t)mrow * L + col) =
                make_float2(tf32v(acc[mt][nt][0]), tf32v(acc[mt][nt][1]));
            *(float2*)(Ob + (size_t)(mrow + 8) * L + col) =
                make_float2(tf32v(acc[mt][nt][2]), tf32v(acc[mt][nt][3]));
        }
    }
}

// ---------------------------------------------------------------------------
// Launch
// ---------------------------------------------------------------------------
extern "C" void kernel_launch(void* const* d_in, const int* in_sizes, int n_in,
                              void* d_out, int out_size) {
    const float* x        = (const float*)d_in[0];
    const float* xorg     = (const float*)d_in[1];
    const float* abspos   = (const float*)d_in[2];
    const float* mask     = (const float*)d_in[3];
    const float* norm     = (const float*)d_in[4];
    const float* qkpos    = (const float*)d_in[5];
    const float* qkorg    = (const float*)d_in[6];
    const float* vorg     = (const float*)d_in[7];
    const float* relpos   = (const float*)d_in[8];
    const float* gate_w   = (const float*)d_in[9];
    const float* gate_b   = (const float*)d_in[10];
    const float* q_w      = (const float*)d_in[11];
    const float* k_w      = (const float*)d_in[12];
    const float* v_w      = (const float*)d_in[13];
    const float* dense_w  = (const float*)d_in[14];
    const float* dense_b  = (const float*)d_in[15];
    float* out = (float*)d_out;

    int total = NB * C * L;
    prep_kernel<<<(total + 255) / 256, 256>>>(x, xorg, abspos, qkpos, qkorg, vorg);
    transpose4<<<dim3(16, 16, 4), dim3(32, 8)>>>(q_w, k_w, v_w, dense_w);

    gate_kernel<<<dim3(3, NB), 128>>>(x, gate_w, gate_b);

    qkv_gemm<<<dim3(4, 3, NB * 3), 256>>>();

    scores_tc<<<dim3(3, 3, NB * H), 256>>>();

    softmax_kernel<<<NB * H * L / 8, 256>>>(relpos, mask, norm);

    pv_tc<<<dim3(1, 3, NB * H), 128>>>();

    dense_gemm<<<dim3(4, 3, NB), 256>>>(out, dense_b);
}

// round 7
// speedup vs baseline: 2.3165x; 1.1621x over previous
#include <cuda_runtime.h>
#include <math.h>
#include <stdint.h>

constexpr int NB = 16, C = 512, L = 384, H = 8, D = 64, ME = 384;

__device__ float g_x0[NB * C * L];
__device__ float g_x1[NB * C * L];
__device__ float g_q [NB * C * L];
__device__ float g_k [NB * C * L];
__device__ float g_v [NB * C * L];
__device__ float g_att[NB * C * L];
__device__ float g_gate[NB * H * L];
__device__ float g_wqT[C * C];
__device__ float g_wkT[C * C];
__device__ float g_wvT[C * C];
__device__ float g_wdT[C * C];

// ---------------------------------------------------------------------------
// helpers
// ---------------------------------------------------------------------------
__device__ __forceinline__ uint32_t f2tf32(float f) {
    uint32_t u;
    asm("cvt.rna.tf32.f32 %0, %1;" : "=r"(u) : "f"(f));
    return u;
}
__device__ __forceinline__ float tf32v(float f) { return __uint_as_float(f2tf32(f)); }

__device__ __forceinline__ void mma8(float* c, const uint32_t* a, const uint32_t* b) {
    asm("mma.sync.aligned.m16n8k8.row.col.f32.tf32.tf32.f32 "
        "{%0,%1,%2,%3}, {%4,%5,%6,%7}, {%8,%9}, {%0,%1,%2,%3};"
        : "+f"(c[0]), "+f"(c[1]), "+f"(c[2]), "+f"(c[3])
        : "r"(a[0]), "r"(a[1]), "r"(a[2]), "r"(a[3]), "r"(b[0]), "r"(b[1]));
}

// ---------------------------------------------------------------------------
// 1) Preprocess (outputs pre-rounded to tf32)
// ---------------------------------------------------------------------------
__global__ void prep_kernel(const float* __restrict__ x,
                            const float* __restrict__ xorg,
                            const float* __restrict__ abspos,
                            const float* __restrict__ qkpos,
                            const float* __restrict__ qkorg,
                            const float* __restrict__ vorg) {
    int i = blockIdx.x * blockDim.x + threadIdx.x;
    if (i >= NB * C * L) return;
    int c = (i / L) % C;
    int g = c >> 3;
    float xv = x[i], xo = xorg[i], ap = abspos[i];
    g_x0[i] = tf32v(xv + xo * vorg[g]);
    g_x1[i] = tf32v(xv + xo * qkorg[g] + ap * qkpos[g]);
}

// ---------------------------------------------------------------------------
// 1b) Batched weight transpose: Wt[k][m] = tf32(W[m][k])
// ---------------------------------------------------------------------------
__global__ void transpose4(const float* __restrict__ q_w, const float* __restrict__ k_w,
                           const float* __restrict__ v_w, const float* __restrict__ d_w) {
    __shared__ float tile[32][33];
    const float* src; float* dst;
    switch (blockIdx.z) {
        case 0: src = q_w; dst = g_wqT; break;
        case 1: src = k_w; dst = g_wkT; break;
        case 2: src = v_w; dst = g_wvT; break;
        default: src = d_w; dst = g_wdT; break;
    }
    int bm = blockIdx.x * 32, bk = blockIdx.y * 32;
    int tx = threadIdx.x, ty = threadIdx.y;
#pragma unroll
    for (int r = 0; r < 32; r += 8)
        tile[ty + r][tx] = src[(size_t)(bm + ty + r) * C + bk + tx];
    __syncthreads();
#pragma unroll
    for (int r = 0; r < 32; r += 8)
        dst[(size_t)(bk + ty + r) * C + bm + tx] = tf32v(tile[tx][ty + r]);
}

// ---------------------------------------------------------------------------
// Weight GEMM core (register tf32 MMA): Out[m][l] = sum_k At[k][m] * B[k][l]
// ---------------------------------------------------------------------------
template <bool BIAS, bool ROUND>
__device__ __forceinline__ void gemm_core(
    const float* __restrict__ At, const float* __restrict__ B,
    float* __restrict__ Ob, const float* __restrict__ bias,
    int m0, int n0, uint32_t (*As)[16][132], uint32_t (*Bs)[16][132]) {
    int t = threadIdx.x;
    int br = t >> 4, bc = (t & 15) * 8;
    const uint4* Ap = (const uint4*)(At + (size_t)br * C + m0 + bc);
    const uint4* Bp = (const uint4*)(B + (size_t)br * L + n0 + bc);

    int w = t >> 5, lane = t & 31;
    int wm = (w >> 1) * 32, wn = (w & 1) * 64;
    int g = lane >> 2, tig = lane & 3;

    float acc[2][8][4] = {};
    uint4 a0, a1, b0, b1;
    a0 = Ap[0]; a1 = Ap[1];
    b0 = Bp[0]; b1 = Bp[1];

    int buf = 0;
    *(uint4*)&As[0][br][bc] = a0; *(uint4*)&As[0][br][bc + 4] = a1;
    *(uint4*)&Bs[0][br][bc] = b0; *(uint4*)&Bs[0][br][bc + 4] = b1;
    __syncthreads();

    for (int k0 = 0; k0 < C; k0 += 16) {
        bool nxt = (k0 + 16) < C;
        if (nxt) {
            const uint4* An = (const uint4*)((const float*)Ap + (size_t)(k0 + 16) * C);
            const uint4* Bn = (const uint4*)((const float*)Bp + (size_t)(k0 + 16) * L);
            a0 = An[0]; a1 = An[1];
            b0 = Bn[0]; b1 = Bn[1];
        }
#pragma unroll
        for (int ks = 0; ks < 16; ks += 8) {
            uint32_t af[2][4], bf[8][2];
#pragma unroll
            for (int mt = 0; mt < 2; mt++) {
                int m = wm + mt * 16;
                af[mt][0] = As[buf][ks + tig][m + g];
                af[mt][1] = As[buf][ks + tig][m + g + 8];
                af[mt][2] = As[buf][ks + tig + 4][m + g];
                af[mt][3] = As[buf][ks + tig + 4][m + g + 8];
            }
#pragma unroll
            for (int nt = 0; nt < 8; nt++) {
                bf[nt][0] = Bs[buf][ks + tig][wn + nt * 8 + g];
                bf[nt][1] = Bs[buf][ks + tig + 4][wn + nt * 8 + g];
            }
#pragma unroll
            for (int mt = 0; mt < 2; mt++)
#pragma unroll
                for (int nt = 0; nt < 8; nt++)
                    mma8(acc[mt][nt], af[mt], bf[nt]);
        }
        if (nxt) {
            buf ^= 1;
            *(uint4*)&As[buf][br][bc] = a0; *(uint4*)&As[buf][br][bc + 4] = a1;
            *(uint4*)&Bs[buf][br][bc] = b0; *(uint4*)&Bs[buf][br][bc + 4] = b1;
            __syncthreads();
        }
    }
#pragma unroll
    for (int mt = 0; mt < 2; mt++) {
        int mrow = m0 + wm + mt * 16 + g;
        float bv0 = BIAS ? bias[mrow] : 0.0f;
        float bv1 = BIAS ? bias[mrow + 8] : 0.0f;
#pragma unroll
        for (int nt = 0; nt < 8; nt++) {
            int col = n0 + wn + nt * 8 + tig * 2;
            float o00 = acc[mt][nt][0] + bv0, o01 = acc[mt][nt][1] + bv0;
            float o10 = acc[mt][nt][2] + bv1, o11 = acc[mt][nt][3] + bv1;
            if (ROUND) { o00 = tf32v(o00); o01 = tf32v(o01); o10 = tf32v(o10); o11 = tf32v(o11); }
            *(float2*)(Ob + (size_t)mrow * L + col) = make_float2(o00, o01);
            *(float2*)(Ob + (size_t)(mrow + 8) * L + col) = make_float2(o10, o11);
        }
    }
}

__global__ void __launch_bounds__(256) qkv_gemm() {
    __shared__ uint32_t As[2][16][132];
    __shared__ uint32_t Bs[2][16][132];
    int z = blockIdx.z;
    int b = z / 3, which = z - 3 * b;
    const float* At = (which == 0) ? g_wqT : (which == 1) ? g_wkT : g_wvT;
    const float* X = ((which == 2) ? g_x0 : g_x1) + (size_t)b * C * L;
    float* Ob = ((which == 0) ? g_q : (which == 1) ? g_k : g_v) + (size_t)b * C * L;
    gemm_core<false, true>(At, X, Ob, nullptr, blockIdx.x * 128, blockIdx.y * 128, As, Bs);
}

__global__ void __launch_bounds__(256) dense_gemm(float* __restrict__ Out,
                                                  const float* __restrict__ bias) {
    __shared__ uint32_t As[2][16][132];
    __shared__ uint32_t Bs[2][16][132];
    int b = blockIdx.z;
    gemm_core<true, false>(g_wdT, g_att + (size_t)b * C * L, Out + (size_t)b * C * L,
                           bias, blockIdx.x * 128, blockIdx.y * 128, As, Bs);
}

// ---------------------------------------------------------------------------
// 3) Gate
// ---------------------------------------------------------------------------
__global__ void __launch_bounds__(128) gate_kernel(const float* __restrict__ x,
                                                   const float* __restrict__ gate_w,
                                                   const float* __restrict__ gate_b) {
    __shared__ float ws[H * C];
    int n = blockIdx.y;
    int l = blockIdx.x * 128 + threadIdx.x;
    int t = threadIdx.x;
#pragma unroll
    for (int i = 0; i < H * C / (128 * 4); i++)
        *(float4*)&ws[(i * 128 + t) * 4] = *(const float4*)&gate_w[(i * 128 + t) * 4];
    __syncthreads();

    const float* xb = x + (size_t)n * C * L + l;
    float acc[H];
#pragma unroll
    for (int h = 0; h < H; h++) acc[h] = gate_b[h];
    for (int c = 0; c < C; c++) {
        float xv = xb[(size_t)c * L];
#pragma unroll
        for (int h = 0; h < H; h++)
            acc[h] = fmaf(ws[h * C + c], xv, acc[h]);
    }
#pragma unroll
    for (int h = 0; h < H; h++)
        g_gate[((size_t)n * H + h) * L + l] = acc[h];
}

// ---------------------------------------------------------------------------
// 4) Fused flash attention: scores + bias + online softmax + PV.
//    Block = (i-tile of 128, z). 256 threads, 8 warps.
//    Warp map: wm=(w>>1)*32 rows (both phases); wn=(w&1)*64 (S cols); wd=(w&1)*32 (O cols).
// ---------------------------------------------------------------------------
constexpr int QS_OFF = 0;                 // [64][136]
constexpr int KS_OFF = 8704;              // [64][136]
constexpr int VS_OFF = 17408;             // [128][72]
constexpr int PS_OFF = 26624;             // [128][136]
constexpr int REL_OFF = 44032;            // [256]
constexpr int GM_OFF = 44288;             // [128]
constexpr int BUFM_OFF = 44416;           // [2][128]
constexpr int BUFS_OFF = 44672;           // [2][128]
constexpr int FA_FLOATS = 44928;
constexpr int FA_BYTES = FA_FLOATS * 4;   // 179712

__global__ void __launch_bounds__(256) flash_attn(const float* __restrict__ relpos,
                                                  const float* __restrict__ mask,
                                                  const float* __restrict__ norm) {
    extern __shared__ float fs[];
    float* Qs = fs + QS_OFF;
    float* Ks = fs + KS_OFF;
    float* Vs = fs + VS_OFF;
    float* Ps = fs + PS_OFF;
    float* rel_s = fs + REL_OFF;
    float* gm_s = fs + GM_OFF;
    float* bufM = fs + BUFM_OFF;
    float* bufS = fs + BUFS_OFF;

    int i0 = blockIdx.x * 128;
    int z = blockIdx.y;
    int n = z / H;
    const float* Qb = g_q + (size_t)z * D * L;
    const float* Kb = g_k + (size_t)z * D * L;
    const float* Vb = g_v + (size_t)z * D * L;
    float inv = 1.0f / norm[n];

    int t = threadIdx.x, w = t >> 5, lane = t & 31;
    int wm = (w >> 1) * 32, wn = (w & 1) * 64, wd = (w & 1) * 32;
    int g = lane >> 2, tig = lane & 3;
    int br = t >> 4, bc = (t & 15) * 8;

    // load Q tile [d=64][i=128]
#pragma unroll
    for (int s = 0; s < 4; s++) {
        const float4* src = (const float4*)(Qb + (size_t)(br + 16 * s) * L + i0 + bc);
        *(float4*)&Qs[(br + 16 * s) * 136 + bc] = src[0];
        *(float4*)&Qs[(br + 16 * s) * 136 + bc + 4] = src[1];
    }

    float Oacc[2][4][4] = {};
    float m_pr[2][2] = {{-1e30f, -1e30f}, {-1e30f, -1e30f}};
    float l_run[2][2] = {{0.f, 0.f}, {0.f, 0.f}};

    for (int jt = 0; jt < 3; jt++) {
        int j0 = jt * 128;
        // K tile [d][j]
#pragma unroll
        for (int s = 0; s < 4; s++) {
            const float4* src = (const float4*)(Kb + (size_t)(br + 16 * s) * L + j0 + bc);
            *(float4*)&Ks[(br + 16 * s) * 136 + bc] = src[0];
            *(float4*)&Ks[(br + 16 * s) * 136 + bc + 4] = src[1];
        }
        // V tile transposed: Vs[j][d]
        {
            int d = t >> 2, jb = (t & 3) * 32;
#pragma unroll
            for (int q = 0; q < 8; q++) {
                float4 v4 = *(const float4*)(Vb + (size_t)d * L + j0 + jb + q * 4);
                Vs[(jb + q * 4 + 0) * 72 + d] = v4.x;
                Vs[(jb + q * 4 + 1) * 72 + d] = v4.y;
                Vs[(jb + q * 4 + 2) * 72 + d] = v4.z;
                Vs[(jb + q * 4 + 3) * 72 + d] = v4.w;
            }
        }
        if (t < 128)
            gm_s[t] = g_gate[(size_t)z * L + j0 + t] + mask[(size_t)n * L + j0 + t];
        {
            int base = 257 + j0 - i0;
            rel_s[t] = relpos[min(base + t, 2 * ME - 2)];
        }
        __syncthreads();

        // ---- QK MMA ----
        float acc[2][8][4] = {};
#pragma unroll
        for (int ks = 0; ks < 64; ks += 8) {
            uint32_t af[2][4], bf[8][2];
#pragma unroll
            for (int mt = 0; mt < 2; mt++) {
                int m = wm + mt * 16;
                af[mt][0] = __float_as_uint(Qs[(ks + tig) * 136 + m + g]);
                af[mt][1] = __float_as_uint(Qs[(ks + tig) * 136 + m + g + 8]);
                af[mt][2] = __float_as_uint(Qs[(ks + tig + 4) * 136 + m + g]);
                af[mt][3] = __float_as_uint(Qs[(ks + tig + 4) * 136 + m + g + 8]);
            }
#pragma unroll
            for (int nt = 0; nt < 8; nt++) {
                bf[nt][0] = __float_as_uint(Ks[(ks + tig) * 136 + wn + nt * 8 + g]);
                bf[nt][1] = __float_as_uint(Ks[(ks + tig + 4) * 136 + wn + nt * 8 + g]);
            }
#pragma unroll
            for (int mt = 0; mt < 2; mt++)
#pragma unroll
                for (int nt = 0; nt < 8; nt++)
                    mma8(acc[mt][nt], af[mt], bf[nt]);
        }

        // ---- bias + per-slot max ----
        float rmax[2][2];
#pragma unroll
        for (int mt = 0; mt < 2; mt++) {
            rmax[mt][0] = -1e30f; rmax[mt][1] = -1e30f;
            int rbase = wm + mt * 16 + g;
            int idx0 = 127 - rbase;
#pragma unroll
            for (int nt = 0; nt < 8; nt++) {
                int c0 = wn + nt * 8 + tig * 2;
                float gm0 = gm_s[c0], gm1 = gm_s[c0 + 1];
                float s00 = (acc[mt][nt][0] + rel_s[idx0 + c0] + gm0) * inv;
                float s01 = (acc[mt][nt][1] + rel_s[idx0 + c0 + 1] + gm1) * inv;
                float s10 = (acc[mt][nt][2] + rel_s[idx0 - 8 + c0] + gm0) * inv;
                float s11 = (acc[mt][nt][3] + rel_s[idx0 - 8 + c0 + 1] + gm1) * inv;
                acc[mt][nt][0] = s00; acc[mt][nt][1] = s01;
                acc[mt][nt][2] = s10; acc[mt][nt][3] = s11;
                rmax[mt][0] = fmaxf(rmax[mt][0], fmaxf(s00, s01));
                rmax[mt][1] = fmaxf(rmax[mt][1], fmaxf(s10, s11));
            }
        }
#pragma unroll
        for (int mt = 0; mt < 2; mt++)
#pragma unroll
            for (int h = 0; h < 2; h++) {
                float v = rmax[mt][h];
                v = fmaxf(v, __shfl_xor_sync(0xffffffff, v, 1));
                v = fmaxf(v, __shfl_xor_sync(0xffffffff, v, 2));
                rmax[mt][h] = v;
            }
        if (tig == 0) {
#pragma unroll
            for (int mt = 0; mt < 2; mt++)
#pragma unroll
                for (int h = 0; h < 2; h++)
                    bufM[(w & 1) * 128 + wm + mt * 16 + g + h * 8] = rmax[mt][h];
        }
        __syncthreads();

        float fac[2][2], mnew[2][2];
#pragma unroll
        for (int mt = 0; mt < 2; mt++)
#pragma unroll
            for (int h = 0; h < 2; h++) {
                int r = wm + mt * 16 + g + h * 8;
                float tm = fmaxf(bufM[r], bufM[128 + r]);
                float mn = fmaxf(m_pr[mt][h], tm);
                fac[mt][h] = __expf(m_pr[mt][h] - mn);
                mnew[mt][h] = mn;
            }

        // ---- P = exp(S - m), write to Ps, partial sums ----
        float rsum[2][2] = {{0.f, 0.f}, {0.f, 0.f}};
#pragma unroll
        for (int mt = 0; mt < 2; mt++) {
            int rbase = wm + mt * 16 + g;
#pragma unroll
            for (int nt = 0; nt < 8; nt++) {
                int c0 = wn + nt * 8 + tig * 2;
                float p00 = __expf(acc[mt][nt][0] - mnew[mt][0]);
                float p01 = __expf(acc[mt][nt][1] - mnew[mt][0]);
                float p10 = __expf(acc[mt][nt][2] - mnew[mt][1]);
                float p11 = __expf(acc[mt][nt][3] - mnew[mt][1]);
                rsum[mt][0] += p00 + p01;
                rsum[mt][1] += p10 + p11;
                Ps[c0 * 136 + rbase] = tf32v(p00);
                Ps[(c0 + 1) * 136 + rbase] = tf32v(p01);
                Ps[c0 * 136 + rbase + 8] = tf32v(p10);
                Ps[(c0 + 1) * 136 + rbase + 8] = tf32v(p11);
            }
        }
#pragma unroll
        for (int mt = 0; mt < 2; mt++)
#pragma unroll
            for (int h = 0; h < 2; h++) {
                float v = rsum[mt][h];
                v += __shfl_xor_sync(0xffffffff, v, 1);
                v += __shfl_xor_sync(0xffffffff, v, 2);
                rsum[mt][h] = v;
            }
        if (tig == 0) {
#pragma unroll
            for (int mt = 0; mt < 2; mt++)
#pragma unroll
                for (int h = 0; h < 2; h++)
                    bufS[(w & 1) * 128 + wm + mt * 16 + g + h * 8] = rsum[mt][h];
        }
        __syncthreads();   // Ps + bufS visible

#pragma unroll
        for (int mt = 0; mt < 2; mt++)
#pragma unroll
            for (int h = 0; h < 2; h++) {
                int r = wm + mt * 16 + g + h * 8;
                float ts = bufS[r] + bufS[128 + r];
                l_run[mt][h] = l_run[mt][h] * fac[mt][h] + ts;
                m_pr[mt][h] = mnew[mt][h];
            }
        // rescale O
#pragma unroll
        for (int mt = 0; mt < 2; mt++)
#pragma unroll
            for (int nt = 0; nt < 4; nt++) {
                Oacc[mt][nt][0] *= fac[mt][0]; Oacc[mt][nt][1] *= fac[mt][0];
                Oacc[mt][nt][2] *= fac[mt][1]; Oacc[mt][nt][3] *= fac[mt][1];
            }

        // ---- PV MMA: O[i][d] += P[i][j] * V[j][d] ----
#pragma unroll 4
        for (int ks = 0; ks < 128; ks += 8) {
            uint32_t af[2][4], bf[4][2];
#pragma unroll
            for (int mt = 0; mt < 2; mt++) {
                int m = wm + mt * 16;
                af[mt][0] = __float_as_uint(Ps[(ks + tig) * 136 + m + g]);
                af[mt][1] = __float_as_uint(Ps[(ks + tig) * 136 + m + g + 8]);
                af[mt][2] = __float_as_uint(Ps[(ks + tig + 4) * 136 + m + g]);
                af[mt][3] = __float_as_uint(Ps[(ks + tig + 4) * 136 + m + g + 8]);
            }
#pragma unroll
            for (int nt = 0; nt < 4; nt++) {
                int dcol = wd + nt * 8 + g;
                bf[nt][0] = __float_as_uint(Vs[(ks + tig) * 72 + dcol]);
                bf[nt][1] = __float_as_uint(Vs[(ks + tig + 4) * 72 + dcol]);
            }
#pragma unroll
            for (int mt = 0; mt < 2; mt++)
#pragma unroll
                for (int nt = 0; nt < 4; nt++)
                    mma8(Oacc[mt][nt], af[mt], bf[nt]);
        }
        __syncthreads();   // done with Ks/Vs/Ps before next tile
    }

    // finalize: out[d][i] = tf32(O / l)
    float* Ob = g_att + (size_t)z * D * L;
#pragma unroll
    for (int mt = 0; mt < 2; mt++) {
        float r0 = 1.0f / l_run[mt][0];
        float r1 = 1.0f / l_run[mt][1];
        int irow = i0 + wm + mt * 16 + g;
#pragma unroll
        for (int nt = 0; nt < 4; nt++) {
            int dcol = wd + nt * 8 + tig * 2;
            Ob[(size_t)dcol * L + irow] = tf32v(Oacc[mt][nt][0] * r0);
            Ob[(size_t)(dcol + 1) * L + irow] = tf32v(Oacc[mt][nt][1] * r0);
            Ob[(size_t)dcol * L + irow + 8] = tf32v(Oacc[mt][nt][2] * r1);
            Ob[(size_t)(dcol + 1) * L + irow + 8] = tf32v(Oacc[mt][nt][3] * r1);
        }
    }
}

// ---------------------------------------------------------------------------
// Launch
// ---------------------------------------------------------------------------
extern "C" void kernel_launch(void* const* d_in, const int* in_sizes, int n_in,
                              void* d_out, int out_size) {
    const float* x        = (const float*)d_in[0];
    const float* xorg     = (const float*)d_in[1];
    const float* abspos   = (const float*)d_in[2];
    const float* mask     = (const float*)d_in[3];
    const float* norm     = (const float*)d_in[4];
    const float* qkpos    = (const float*)d_in[5];
    const float* qkorg    = (const float*)d_in[6];
    const float* vorg     = (const float*)d_in[7];
    const float* relpos   = (const float*)d_in[8];
    const float* gate_w   = (const float*)d_in[9];
    const float* gate_b   = (const float*)d_in[10];
    const float* q_w      = (const float*)d_in[11];
    const float* k_w      = (const float*)d_in[12];
    const float* v_w      = (const float*)d_in[13];
    const float* dense_w  = (const float*)d_in[14];
    const float* dense_b  = (const float*)d_in[15];
    float* out = (float*)d_out;

    cudaFuncSetAttribute(flash_attn, cudaFuncAttributeMaxDynamicSharedMemorySize, FA_BYTES);

    int total = NB * C * L;
    prep_kernel<<<(total + 255) / 256, 256>>>(x, xorg, abspos, qkpos, qkorg, vorg);
    transpose4<<<dim3(16, 16, 4), dim3(32, 8)>>>(q_w, k_w, v_w, dense_w);

    gate_kernel<<<dim3(3, NB), 128>>>(x, gate_w, gate_b);

    qkv_gemm<<<dim3(4, 3, NB * 3), 256>>>();

    flash_attn<<<dim3(3, NB * H), 256, FA_BYTES>>>(relpos, mask, norm);

    dense_gemm<<<dim3(4, 3, NB), 256>>>(out, dense_b);
}

// round 8
// speedup vs baseline: 3.5172x; 1.5184x over previous
#include <cuda_runtime.h>
#include <cuda_fp16.h>
#include <math.h>
#include <stdint.h>

constexpr int NB = 16, C = 512, L = 384, H = 8, D = 64, ME = 384;

__device__ __half g_x0T[NB * L * C];
__device__ __half g_x1T[NB * L * C];
__device__ __half g_wqh[C * C], g_wkh[C * C], g_wvh[C * C], g_wdh[C * C];
__device__ __half g_qh[NB * C * L], g_kh[NB * C * L], g_vh[NB * C * L];
__device__ __half g_qT[NB * C * L], g_kT[NB * C * L];
__device__ __half g_attT[NB * L * C];
__device__ float g_gate[NB * H * L];

// ---------------------------------------------------------------------------
// helpers
// ---------------------------------------------------------------------------
__device__ __forceinline__ uint32_t h2pack(float lo, float hi) {
    uint32_t u;
    asm("cvt.rn.f16x2.f32 %0, %1, %2;" : "=r"(u) : "f"(hi), "f"(lo));
    return u;
}

__device__ __forceinline__ void mma16(float* c, const uint32_t* a, const uint32_t* b) {
    asm("mma.sync.aligned.m16n8k16.row.col.f32.f16.f16.f32 "
        "{%0,%1,%2,%3}, {%4,%5,%6,%7}, {%8,%9}, {%0,%1,%2,%3};"
        : "+f"(c[0]), "+f"(c[1]), "+f"(c[2]), "+f"(c[3])
        : "r"(a[0]), "r"(a[1]), "r"(a[2]), "r"(a[3]), "r"(b[0]), "r"(b[1]));
}

// ---------------------------------------------------------------------------
// 1) Fused preprocess + transpose: x0T/x1T[n][l][c] (half)
// ---------------------------------------------------------------------------
__global__ void __launch_bounds__(256) prep_t(const float* __restrict__ x,
                                              const float* __restrict__ xorg,
                                              const float* __restrict__ abspos,
                                              const float* __restrict__ qkpos,
                                              const float* __restrict__ qkorg,
                                              const float* __restrict__ vorg) {
    __shared__ float t0[32][33], t1[32][33];
    int n = blockIdx.z, ct = blockIdx.y, lt = blockIdx.x;
    int tx = threadIdx.x, ty = threadIdx.y;
#pragma unroll
    for (int s = 0; s < 4; s++) {
        int c = ct * 32 + ty + 8 * s;
        int l = lt * 32 + tx;
        size_t idx = ((size_t)n * C + c) * L + l;
        int gg = c >> 3;
        float xv = x[idx], xo = xorg[idx], ap = abspos[idx];
        t0[ty + 8 * s][tx] = xv + xo * vorg[gg];
        t1[ty + 8 * s][tx] = xv + xo * qkorg[gg] + ap * qkpos[gg];
    }
    __syncthreads();
#pragma unroll
    for (int s = 0; s < 4; s++) {
        int l = lt * 32 + ty + 8 * s;
        int c = ct * 32 + tx;
        size_t o = ((size_t)n * L + l) * C + c;
        g_x0T[o] = __float2half_rn(t0[tx][ty + 8 * s]);
        g_x1T[o] = __float2half_rn(t1[tx][ty + 8 * s]);
    }
}

// 1b) round weights to half, natural [out][in] layout
__global__ void round_w_h(const float* __restrict__ q, const float* __restrict__ k,
                          const float* __restrict__ v, const float* __restrict__ d) {
    int i = blockIdx.x * blockDim.x + threadIdx.x;   // 131072 threads
    int mat = i >> 15;
    int j = (i & 32767) * 8;
    const float* s = mat == 0 ? q : mat == 1 ? k : mat == 2 ? v : d;
    __half* dst = mat == 0 ? g_wqh : mat == 1 ? g_wkh : mat == 2 ? g_wvh : g_wdh;
    float4 f0 = *(const float4*)(s + j);
    float4 f1 = *(const float4*)(s + j + 4);
    uint4 o;
    o.x = h2pack(f0.x, f0.y); o.y = h2pack(f0.z, f0.w);
    o.z = h2pack(f1.x, f1.y); o.w = h2pack(f1.z, f1.w);
    *(uint4*)(dst + j) = o;
}

// ---------------------------------------------------------------------------
// f16 GEMM core: Out[m][l] = sum_k A[m][k] * B[l][k]  (both k-contiguous)
//   BM=BN=128, BK=32, 256 threads, 8 warps (4x2), warp tile 32x64.
// ---------------------------------------------------------------------------
template <bool TOHALF>
__device__ __forceinline__ void gemm_h(const __half* __restrict__ A,
                                       const __half* __restrict__ Bx,
                                       void* Obv, const float* __restrict__ bias,
                                       int m0, int n0) {
    __shared__ __half As[2][128][40];
    __shared__ __half Bs[2][128][40];
    int t = threadIdx.x;
    int ar = t >> 1, ac = (t & 1) * 16;
    const __half* Ap = A + (size_t)(m0 + ar) * C + ac;
    const __half* Bp = Bx + (size_t)(n0 + ar) * C + ac;
    int w = t >> 5, lane = t & 31;
    int wm = (w >> 1) * 32, wn = (w & 1) * 64;
    int g = lane >> 2, tg2 = (lane & 3) * 2;

    float acc[2][8][4] = {};
    uint4 a0, a1, b0, b1;
    a0 = *(const uint4*)Ap; a1 = *(const uint4*)(Ap + 8);
    b0 = *(const uint4*)Bp; b1 = *(const uint4*)(Bp + 8);

    int buf = 0;
    *(uint4*)&As[0][ar][ac] = a0; *(uint4*)&As[0][ar][ac + 8] = a1;
    *(uint4*)&Bs[0][ar][ac] = b0; *(uint4*)&Bs[0][ar][ac + 8] = b1;
    __syncthreads();

    for (int k0 = 0; k0 < C; k0 += 32) {
        bool nxt = (k0 + 32) < C;
        if (nxt) {
            a0 = *(const uint4*)(Ap + k0 + 32); a1 = *(const uint4*)(Ap + k0 + 40);
            b0 = *(const uint4*)(Bp + k0 + 32); b1 = *(const uint4*)(Bp + k0 + 40);
        }
#pragma unroll
        for (int ks = 0; ks < 32; ks += 16) {
            uint32_t af[2][4], bf[8][2];
#pragma unroll
            for (int mt = 0; mt < 2; mt++) {
                int m = wm + mt * 16;
                af[mt][0] = *(const uint32_t*)&As[buf][m + g][ks + tg2];
                af[mt][1] = *(const uint32_t*)&As[buf][m + g + 8][ks + tg2];
                af[mt][2] = *(const uint32_t*)&As[buf][m + g][ks + tg2 + 8];
                af[mt][3] = *(const uint32_t*)&As[buf][m + g + 8][ks + tg2 + 8];
            }
#pragma unroll
            for (int nt = 0; nt < 8; nt++) {
                bf[nt][0] = *(const uint32_t*)&Bs[buf][wn + nt * 8 + g][ks + tg2];
                bf[nt][1] = *(const uint32_t*)&Bs[buf][wn + nt * 8 + g][ks + tg2 + 8];
            }
#pragma unroll
            for (int mt = 0; mt < 2; mt++)
#pragma unroll
                for (int nt = 0; nt < 8; nt++)
                    mma16(acc[mt][nt], af[mt], bf[nt]);
        }
        if (nxt) {
            buf ^= 1;
            *(uint4*)&As[buf][ar][ac] = a0; *(uint4*)&As[buf][ar][ac + 8] = a1;
            *(uint4*)&Bs[buf][ar][ac] = b0; *(uint4*)&Bs[buf][ar][ac + 8] = b1;
            __syncthreads();
        }
    }
#pragma unroll
    for (int mt = 0; mt < 2; mt++) {
        int mrow = m0 + wm + mt * 16 + g;
        if (TOHALF) {
            __half* Ob = (__half*)Obv;
#pragma unroll
            for (int nt = 0; nt < 8; nt++) {
                int col = n0 + wn + nt * 8 + tg2;
                *(uint32_t*)(Ob + (size_t)mrow * L + col) = h2pack(acc[mt][nt][0], acc[mt][nt][1]);
                *(uint32_t*)(Ob + (size_t)(mrow + 8) * L + col) = h2pack(acc[mt][nt][2], acc[mt][nt][3]);
            }
        } else {
            float* Ob = (float*)Obv;
            float bv0 = bias[mrow], bv1 = bias[mrow + 8];
#pragma unroll
            for (int nt = 0; nt < 8; nt++) {
                int col = n0 + wn + nt * 8 + tg2;
                *(float2*)(Ob + (size_t)mrow * L + col) =
                    make_float2(acc[mt][nt][0] + bv0, acc[mt][nt][1] + bv0);
                *(float2*)(Ob + (size_t)(mrow + 8) * L + col) =
                    make_float2(acc[mt][nt][2] + bv1, acc[mt][nt][3] + bv1);
            }
        }
    }
}

__global__ void __launch_bounds__(256) qkv_h() {
    int z = blockIdx.z;
    int b = z / 3, which = z - 3 * b;
    const __half* A = which == 0 ? g_wqh : which == 1 ? g_wkh : g_wvh;
    const __half* Bx = (which == 2 ? g_x0T : g_x1T) + (size_t)b * L * C;
    __half* Ob = (which == 0 ? g_qh : which == 1 ? g_kh : g_vh) + (size_t)b * C * L;
    gemm_h<true>(A, Bx, Ob, nullptr, blockIdx.x * 128, blockIdx.y * 128);
}

__global__ void __launch_bounds__(256) dense_h(float* __restrict__ Out,
                                               const float* __restrict__ bias) {
    int b = blockIdx.z;
    gemm_h<false>(g_wdh, g_attT + (size_t)b * L * C, Out + (size_t)b * C * L,
                  bias, blockIdx.x * 128, blockIdx.y * 128);
}

// ---------------------------------------------------------------------------
// 2b) Transpose q,k: [z][d][l] -> [z][l][d] (half)
// ---------------------------------------------------------------------------
__global__ void __launch_bounds__(256) tr_qk() {
    __shared__ __half tile[32][40];
    int lt = blockIdx.x, by = blockIdx.y, z = blockIdx.z;
    int mat = by >> 1, dt = (by & 1) * 32;
    const __half* src = (mat ? g_kh : g_qh) + (size_t)z * D * L;
    __half* dst = (mat ? g_kT : g_qT) + (size_t)z * L * D;
    int tx = threadIdx.x, ty = threadIdx.y;
#pragma unroll
    for (int s = 0; s < 4; s++)
        tile[ty + 8 * s][tx] = src[(size_t)(dt + ty + 8 * s) * L + lt * 32 + tx];
    __syncthreads();
#pragma unroll
    for (int s = 0; s < 4; s++)
        dst[(size_t)(lt * 32 + ty + 8 * s) * D + dt + tx] = tile[tx][ty + 8 * s];
}

// ---------------------------------------------------------------------------
// 3) Gate (f32, exact)
// ---------------------------------------------------------------------------
__global__ void __launch_bounds__(128) gate_kernel(const float* __restrict__ x,
                                                   const float* __restrict__ gate_w,
                                                   const float* __restrict__ gate_b) {
    __shared__ float ws[H * C];
    int n = blockIdx.y;
    int l = blockIdx.x * 128 + threadIdx.x;
    int t = threadIdx.x;
#pragma unroll
    for (int i = 0; i < H * C / (128 * 4); i++)
        *(float4*)&ws[(i * 128 + t) * 4] = *(const float4*)&gate_w[(i * 128 + t) * 4];
    __syncthreads();

    const float* xb = x + (size_t)n * C * L + l;
    float acc[H];
#pragma unroll
    for (int h = 0; h < H; h++) acc[h] = gate_b[h];
    for (int c = 0; c < C; c++) {
        float xv = xb[(size_t)c * L];
#pragma unroll
        for (int h = 0; h < H; h++)
            acc[h] = fmaf(ws[h * C + c], xv, acc[h]);
    }
#pragma unroll
    for (int h = 0; h < H; h++)
        g_gate[((size_t)n * H + h) * L + l] = acc[h];
}

// ---------------------------------------------------------------------------
// 4) Fused flash attention (f16 MMA, f32 softmax). Writes attT[n][l][c] half.
// ---------------------------------------------------------------------------
constexpr int FQS = 0;          // [128][72] half
constexpr int FKS = 18432;      // [128][72] half
constexpr int FVS = 36864;      // [64][136] half
constexpr int FPS = 54272;      // [128][136] half
constexpr int FREL = 89088;     // 256 f32
constexpr int FGM = 90112;      // 128 f32
constexpr int FBM = 90624;      // 256 f32
constexpr int FBS = 91648;      // 256 f32
constexpr int FA_B = 92672;

__global__ void __launch_bounds__(256) flash_h(const float* __restrict__ relpos,
                                               const float* __restrict__ mask,
                                               const float* __restrict__ norm) {
    extern __shared__ char sm[];
    __half* Qs = (__half*)(sm + FQS);
    __half* Ks = (__half*)(sm + FKS);
    __half* Vs = (__half*)(sm + FVS);
    __half* Ps = (__half*)(sm + FPS);
    float* rel_s = (float*)(sm + FREL);
    float* gm_s = (float*)(sm + FGM);
    float* bufM = (float*)(sm + FBM);
    float* bufS = (float*)(sm + FBS);

    int i0 = blockIdx.x * 128;
    int z = blockIdx.y;
    int n = z / H, h = z - n * H;
    const __half* Qb = g_qT + (size_t)z * L * D;
    const __half* Kb = g_kT + (size_t)z * L * D;
    const __half* Vb = g_vh + (size_t)z * D * L;
    float inv = 1.0f / norm[n];

    int t = threadIdx.x, w = t >> 5, lane = t & 31;
    int wm = (w >> 1) * 32, wn = (w & 1) * 64, wd = (w & 1) * 32;
    int g = lane >> 2, tg2 = (lane & 3) * 2;

    // Q tile: [i][d]
    {
        int r = t >> 1, cc = (t & 1) * 32;
        const uint4* s = (const uint4*)(Qb + (size_t)(i0 + r) * D + cc);
        uint4* dq = (uint4*)(Qs + r * 72 + cc);
        dq[0] = s[0]; dq[1] = s[1]; dq[2] = s[2]; dq[3] = s[3];
    }

    float Oacc[2][4][4] = {};
    float m_pr[2][2] = {{-1e30f, -1e30f}, {-1e30f, -1e30f}};
    float l_run[2][2] = {{0.f, 0.f}, {0.f, 0.f}};

    for (int jt = 0; jt < 3; jt++) {
        int j0 = jt * 128;
        {
            int r = t >> 1, cc = (t & 1) * 32;
            const uint4* s = (const uint4*)(Kb + (size_t)(j0 + r) * D + cc);
            uint4* dk = (uint4*)(Ks + r * 72 + cc);
            dk[0] = s[0]; dk[1] = s[1]; dk[2] = s[2]; dk[3] = s[3];
        }
        {
            int dd = t >> 2, cc = (t & 3) * 32;
            const uint4* s = (const uint4*)(Vb + (size_t)dd * L + j0 + cc);
            uint4* dv = (uint4*)(Vs + dd * 136 + cc);
            dv[0] = s[0]; dv[1] = s[1]; dv[2] = s[2]; dv[3] = s[3];
        }
        if (t < 128)
            gm_s[t] = g_gate[(size_t)z * L + j0 + t] + mask[(size_t)n * L + j0 + t];
        rel_s[t] = relpos[min(257 + j0 - i0 + t, 2 * ME - 2)];
        __syncthreads();

        // ---- QK MMA (k = d = 64) ----
        float acc[2][8][4] = {};
#pragma unroll
        for (int ks = 0; ks < 64; ks += 16) {
            uint32_t af[2][4], bf[8][2];
#pragma unroll
            for (int mt = 0; mt < 2; mt++) {
                int m = wm + mt * 16;
                af[mt][0] = *(const uint32_t*)&Qs[(m + g) * 72 + ks + tg2];
                af[mt][1] = *(const uint32_t*)&Qs[(m + g + 8) * 72 + ks + tg2];
                af[mt][2] = *(const uint32_t*)&Qs[(m + g) * 72 + ks + tg2 + 8];
                af[mt][3] = *(const uint32_t*)&Qs[(m + g + 8) * 72 + ks + tg2 + 8];
            }
#pragma unroll
            for (int nt = 0; nt < 8; nt++) {
                bf[nt][0] = *(const uint32_t*)&Ks[(wn + nt * 8 + g) * 72 + ks + tg2];
                bf[nt][1] = *(const uint32_t*)&Ks[(wn + nt * 8 + g) * 72 + ks + tg2 + 8];
            }
#pragma unroll
            for (int mt = 0; mt < 2; mt++)
#pragma unroll
                for (int nt = 0; nt < 8; nt++)
                    mma16(acc[mt][nt], af[mt], bf[nt]);
        }

        // ---- bias + per-slot max ----
        float rmax[2][2];
#pragma unroll
        for (int mt = 0; mt < 2; mt++) {
            rmax[mt][0] = -1e30f; rmax[mt][1] = -1e30f;
            int rbase = wm + mt * 16 + g;
            int idx0 = 127 - rbase;
#pragma unroll
            for (int nt = 0; nt < 8; nt++) {
                int c0 = wn + nt * 8 + tg2;
                float gm0 = gm_s[c0], gm1 = gm_s[c0 + 1];
                float s00 = (acc[mt][nt][0] + rel_s[idx0 + c0] + gm0) * inv;
                float s01 = (acc[mt][nt][1] + rel_s[idx0 + c0 + 1] + gm1) * inv;
                float s10 = (acc[mt][nt][2] + rel_s[idx0 - 8 + c0] + gm0) * inv;
                float s11 = (acc[mt][nt][3] + rel_s[idx0 - 8 + c0 + 1] + gm1) * inv;
                acc[mt][nt][0] = s00; acc[mt][nt][1] = s01;
                acc[mt][nt][2] = s10; acc[mt][nt][3] = s11;
                rmax[mt][0] = fmaxf(rmax[mt][0], fmaxf(s00, s01));
                rmax[mt][1] = fmaxf(rmax[mt][1], fmaxf(s10, s11));
            }
        }
#pragma unroll
        for (int mt = 0; mt < 2; mt++)
#pragma unroll
            for (int hh = 0; hh < 2; hh++) {
                float v = rmax[mt][hh];
                v = fmaxf(v, __shfl_xor_sync(0xffffffff, v, 1));
                v = fmaxf(v, __shfl_xor_sync(0xffffffff, v, 2));
                rmax[mt][hh] = v;
            }
        if ((lane & 3) == 0) {
#pragma unroll
            for (int mt = 0; mt < 2; mt++)
#pragma unroll
                for (int hh = 0; hh < 2; hh++)
                    bufM[(w & 1) * 128 + wm + mt * 16 + g + hh * 8] = rmax[mt][hh];
        }
        __syncthreads();

        float fac[2][2], mnew[2][2];
#pragma unroll
        for (int mt = 0; mt < 2; mt++)
#pragma unroll
            for (int hh = 0; hh < 2; hh++) {
                int r = wm + mt * 16 + g + hh * 8;
                float tm = fmaxf(bufM[r], bufM[128 + r]);
                float mn = fmaxf(m_pr[mt][hh], tm);
                fac[mt][hh] = __expf(m_pr[mt][hh] - mn);
                mnew[mt][hh] = mn;
            }

        // ---- P = exp(S - m) -> Ps[i][j] half, partial sums ----
        float rsum[2][2] = {{0.f, 0.f}, {0.f, 0.f}};
#pragma unroll
        for (int mt = 0; mt < 2; mt++) {
            int rbase = wm + mt * 16 + g;
#pragma unroll
            for (int nt = 0; nt < 8; nt++) {
                int c0 = wn + nt * 8 + tg2;
                float p00 = __expf(acc[mt][nt][0] - mnew[mt][0]);
                float p01 = __expf(acc[mt][nt][1] - mnew[mt][0]);
                float p10 = __expf(acc[mt][nt][2] - mnew[mt][1]);
                float p11 = __expf(acc[mt][nt][3] - mnew[mt][1]);
                rsum[mt][0] += p00 + p01;
                rsum[mt][1] += p10 + p11;
                *(uint32_t*)&Ps[rbase * 136 + c0] = h2pack(p00, p01);
                *(uint32_t*)&Ps[(rbase + 8) * 136 + c0] = h2pack(p10, p11);
            }
        }
#pragma unroll
        for (int mt = 0; mt < 2; mt++)
#pragma unroll
            for (int hh = 0; hh < 2; hh++) {
                float v = rsum[mt][hh];
                v += __shfl_xor_sync(0xffffffff, v, 1);
                v += __shfl_xor_sync(0xffffffff, v, 2);
                rsum[mt][hh] = v;
            }
        if ((lane & 3) == 0) {
#pragma unroll
            for (int mt = 0; mt < 2; mt++)
#pragma unroll
                for (int hh = 0; hh < 2; hh++)
                    bufS[(w & 1) * 128 + wm + mt * 16 + g + hh * 8] = rsum[mt][hh];
        }
        __syncthreads();

#pragma unroll
        for (int mt = 0; mt < 2; mt++)
#pragma unroll
            for (int hh = 0; hh < 2; hh++) {
                int r = wm + mt * 16 + g + hh * 8;
                float ts = bufS[r] + bufS[128 + r];
                l_run[mt][hh] = l_run[mt][hh] * fac[mt][hh] + ts;
                m_pr[mt][hh] = mnew[mt][hh];
            }
#pragma unroll
        for (int mt = 0; mt < 2; mt++)
#pragma unroll
            for (int nt = 0; nt < 4; nt++) {
                Oacc[mt][nt][0] *= fac[mt][0]; Oacc[mt][nt][1] *= fac[mt][0];
                Oacc[mt][nt][2] *= fac[mt][1]; Oacc[mt][nt][3] *= fac[mt][1];
            }

        // ---- PV MMA: O[i][d] += P[i][j] V[j][d], k = j = 128 ----
#pragma unroll
        for (int ks = 0; ks < 128; ks += 16) {
            uint32_t af[2][4], bf[4][2];
#pragma unroll
            for (int mt = 0; mt < 2; mt++) {
                int m = wm + mt * 16;
                af[mt][0] = *(const uint32_t*)&Ps[(m + g) * 136 + ks + tg2];
                af[mt][1] = *(const uint32_t*)&Ps[(m + g + 8) * 136 + ks + tg2];
                af[mt][2] = *(const uint32_t*)&Ps[(m + g) * 136 + ks + tg2 + 8];
                af[mt][3] = *(const uint32_t*)&Ps[(m + g + 8) * 136 + ks + tg2 + 8];
            }
#pragma unroll
            for (int nt = 0; nt < 4; nt++) {
                int dc = wd + nt * 8 + g;
                bf[nt][0] = *(const uint32_t*)&Vs[dc * 136 + ks + tg2];
                bf[nt][1] = *(const uint32_t*)&Vs[dc * 136 + ks + tg2 + 8];
            }
#pragma unroll
            for (int mt = 0; mt < 2; mt++)
#pragma unroll
                for (int nt = 0; nt < 4; nt++)
                    mma16(Oacc[mt][nt], af[mt], bf[nt]);
        }
        __syncthreads();
    }

    // finalize: attT[n][i][h*64 + d] = half(O / l)
    __half* Ob = g_attT + (size_t)n * L * C;
#pragma unroll
    for (int mt = 0; mt < 2; mt++) {
        float r0 = 1.0f / l_run[mt][0];
        float r1 = 1.0f / l_run[mt][1];
        int irow = i0 + wm + mt * 16 + g;
#pragma unroll
        for (int nt = 0; nt < 4; nt++) {
            int dc = h * 64 + wd + nt * 8 + tg2;
            *(uint32_t*)(Ob + (size_t)irow * C + dc) =
                h2pack(Oacc[mt][nt][0] * r0, Oacc[mt][nt][1] * r0);
            *(uint32_t*)(Ob + (size_t)(irow + 8) * C + dc) =
                h2pack(Oacc[mt][nt][2] * r1, Oacc[mt][nt][3] * r1);
        }
    }
}

// ---------------------------------------------------------------------------
// Launch
// ---------------------------------------------------------------------------
extern "C" void kernel_launch(void* const* d_in, const int* in_sizes, int n_in,
                              void* d_out, int out_size) {
    const float* x        = (const float*)d_in[0];
    const float* xorg     = (const float*)d_in[1];
    const float* abspos   = (const float*)d_in[2];
    const float* mask     = (const float*)d_in[3];
    const float* norm     = (const float*)d_in[4];
    const float* qkpos    = (const float*)d_in[5];
    const float* qkorg    = (const float*)d_in[6];
    const float* vorg     = (const float*)d_in[7];
    const float* relpos   = (const float*)d_in[8];
    const float* gate_w   = (const float*)d_in[9];
    const float* gate_b   = (const float*)d_in[10];
    const float* q_w      = (const float*)d_in[11];
    const float* k_w      = (const float*)d_in[12];
    const float* v_w      = (const float*)d_in[13];
    const float* dense_w  = (const float*)d_in[14];
    const float* dense_b  = (const float*)d_in[15];
    float* out = (float*)d_out;

    cudaFuncSetAttribute(flash_h, cudaFuncAttributeMaxDynamicSharedMemorySize, FA_B);

    prep_t<<<dim3(12, 16, NB), dim3(32, 8)>>>(x, xorg, abspos, qkpos, qkorg, vorg);
    round_w_h<<<512, 256>>>(q_w, k_w, v_w, dense_w);

    gate_kernel<<<dim3(3, NB), 128>>>(x, gate_w, gate_b);

    qkv_h<<<dim3(4, 3, NB * 3), 256>>>();

    tr_qk<<<dim3(12, 4, NB * H), dim3(32, 8)>>>();

    flash_h<<<dim3(3, NB * H), 256, FA_B>>>(relpos, mask, norm);

    dense_h<<<dim3(4, 3, NB), 256>>>(out, dense_b);
}

// round 9
// speedup vs baseline: 3.6587x; 1.0402x over previous
#include <cuda_runtime.h>
#include <cuda_fp16.h>
#include <math.h>
#include <stdint.h>

constexpr int NB = 16, C = 512, L = 384, H = 8, D = 64, ME = 384;

__device__ __half g_x0T[NB * L * C];
__device__ __half g_x1T[NB * L * C];
__device__ __half g_wqh[C * C], g_wkh[C * C], g_wvh[C * C], g_wdh[C * C];
__device__ __half g_qh[NB * C * L], g_kh[NB * C * L], g_vh[NB * C * L];
__device__ __half g_attT[NB * L * C];
__device__ float g_gate[NB * H * L];

// ---------------------------------------------------------------------------
// helpers
// ---------------------------------------------------------------------------
__device__ __forceinline__ uint32_t h2pack(float lo, float hi) {
    uint32_t u;
    asm("cvt.rn.f16x2.f32 %0, %1, %2;" : "=r"(u) : "f"(hi), "f"(lo));
    return u;
}

__device__ __forceinline__ void mma16(float* c, const uint32_t* a, const uint32_t* b) {
    asm("mma.sync.aligned.m16n8k16.row.col.f32.f16.f16.f32 "
        "{%0,%1,%2,%3}, {%4,%5,%6,%7}, {%8,%9}, {%0,%1,%2,%3};"
        : "+f"(c[0]), "+f"(c[1]), "+f"(c[2]), "+f"(c[3])
        : "r"(a[0]), "r"(a[1]), "r"(a[2]), "r"(a[3]), "r"(b[0]), "r"(b[1]));
}

__device__ __forceinline__ uint32_t smaddr(const void* p) {
    return (uint32_t)__cvta_generic_to_shared(p);
}
__device__ __forceinline__ void ldsm4(uint32_t* r, uint32_t a) {
    asm volatile("ldmatrix.sync.aligned.m8n8.x4.shared.b16 {%0,%1,%2,%3}, [%4];"
                 : "=r"(r[0]), "=r"(r[1]), "=r"(r[2]), "=r"(r[3]) : "r"(a));
}
__device__ __forceinline__ void ldsm4t(uint32_t* r, uint32_t a) {
    asm volatile("ldmatrix.sync.aligned.m8n8.x4.trans.shared.b16 {%0,%1,%2,%3}, [%4];"
                 : "=r"(r[0]), "=r"(r[1]), "=r"(r[2]), "=r"(r[3]) : "r"(a));
}

// ---------------------------------------------------------------------------
// 1) Fused preprocess + transpose: x0T/x1T[n][l][c] (half)
// ---------------------------------------------------------------------------
__global__ void __launch_bounds__(256) prep_t(const float* __restrict__ x,
                                              const float* __restrict__ xorg,
                                              const float* __restrict__ abspos,
                                              const float* __restrict__ qkpos,
                                              const float* __restrict__ qkorg,
                                              const float* __restrict__ vorg) {
    __shared__ float t0[32][33], t1[32][33];
    int n = blockIdx.z, ct = blockIdx.y, lt = blockIdx.x;
    int tx = threadIdx.x, ty = threadIdx.y;
#pragma unroll
    for (int s = 0; s < 4; s++) {
        int c = ct * 32 + ty + 8 * s;
        int l = lt * 32 + tx;
        size_t idx = ((size_t)n * C + c) * L + l;
        int gg = c >> 3;
        float xv = x[idx], xo = xorg[idx], ap = abspos[idx];
        t0[ty + 8 * s][tx] = xv + xo * vorg[gg];
        t1[ty + 8 * s][tx] = xv + xo * qkorg[gg] + ap * qkpos[gg];
    }
    __syncthreads();
#pragma unroll
    for (int s = 0; s < 4; s++) {
        int l = lt * 32 + ty + 8 * s;
        int c = ct * 32 + tx;
        size_t o = ((size_t)n * L + l) * C + c;
        g_x0T[o] = __float2half_rn(t0[tx][ty + 8 * s]);
        g_x1T[o] = __float2half_rn(t1[tx][ty + 8 * s]);
    }
}

// 1b) round weights to half
__global__ void round_w_h(const float* __restrict__ q, const float* __restrict__ k,
                          const float* __restrict__ v, const float* __restrict__ d) {
    int i = blockIdx.x * blockDim.x + threadIdx.x;
    int mat = i >> 15;
    int j = (i & 32767) * 8;
    const float* s = mat == 0 ? q : mat == 1 ? k : mat == 2 ? v : d;
    __half* dst = mat == 0 ? g_wqh : mat == 1 ? g_wkh : mat == 2 ? g_wvh : g_wdh;
    float4 f0 = *(const float4*)(s + j);
    float4 f1 = *(const float4*)(s + j + 4);
    uint4 o;
    o.x = h2pack(f0.x, f0.y); o.y = h2pack(f0.z, f0.w);
    o.z = h2pack(f1.x, f1.y); o.w = h2pack(f1.z, f1.w);
    *(uint4*)(dst + j) = o;
}

// ---------------------------------------------------------------------------
// f16 GEMM core (ldmatrix): Out[m][l] = sum_k A[m][k] * B[l][k]
// ---------------------------------------------------------------------------
template <bool TOHALF>
__device__ __forceinline__ void gemm_h(const __half* __restrict__ A,
                                       const __half* __restrict__ Bx,
                                       void* Obv, const float* __restrict__ bias,
                                       int m0, int n0) {
    __shared__ __half As[2][128][40];
    __shared__ __half Bs[2][128][40];
    int t = threadIdx.x;
    int ar = t >> 1, ac = (t & 1) * 16;
    const __half* Ap = A + (size_t)(m0 + ar) * C + ac;
    const __half* Bp = Bx + (size_t)(n0 + ar) * C + ac;
    int w = t >> 5, lane = t & 31;
    int wm = (w >> 1) * 32, wn = (w & 1) * 64;
    int g = lane >> 2, tg2 = (lane & 3) * 2;

    float acc[2][8][4] = {};
    uint4 a0, a1, b0, b1;
    a0 = *(const uint4*)Ap; a1 = *(const uint4*)(Ap + 8);
    b0 = *(const uint4*)Bp; b1 = *(const uint4*)(Bp + 8);

    int buf = 0;
    *(uint4*)&As[0][ar][ac] = a0; *(uint4*)&As[0][ar][ac + 8] = a1;
    *(uint4*)&Bs[0][ar][ac] = b0; *(uint4*)&Bs[0][ar][ac + 8] = b1;
    __syncthreads();

    // ldmatrix lane address components
    int a_row = (lane & 15), a_col = (lane >> 4) * 8;
    int b_row = ((lane >> 4) & 1) * 8 + (lane & 7), b_col = ((lane >> 3) & 1) * 8;

    for (int k0 = 0; k0 < C; k0 += 32) {
        bool nxt = (k0 + 32) < C;
        if (nxt) {
            a0 = *(const uint4*)(Ap + k0 + 32); a1 = *(const uint4*)(Ap + k0 + 40);
            b0 = *(const uint4*)(Bp + k0 + 32); b1 = *(const uint4*)(Bp + k0 + 40);
        }
#pragma unroll
        for (int ks = 0; ks < 32; ks += 16) {
            uint32_t af[2][4], bf[8][2];
#pragma unroll
            for (int mt = 0; mt < 2; mt++)
                ldsm4(af[mt], smaddr(&As[buf][wm + mt * 16 + a_row][ks + a_col]));
#pragma unroll
            for (int ntp = 0; ntp < 4; ntp++) {
                uint32_t rr[4];
                ldsm4(rr, smaddr(&Bs[buf][wn + ntp * 16 + b_row][ks + b_col]));
                bf[2 * ntp][0] = rr[0]; bf[2 * ntp][1] = rr[1];
                bf[2 * ntp + 1][0] = rr[2]; bf[2 * ntp + 1][1] = rr[3];
            }
#pragma unroll
            for (int mt = 0; mt < 2; mt++)
#pragma unroll
                for (int nt = 0; nt < 8; nt++)
                    mma16(acc[mt][nt], af[mt], bf[nt]);
        }
        if (nxt) {
            buf ^= 1;
            *(uint4*)&As[buf][ar][ac] = a0; *(uint4*)&As[buf][ar][ac + 8] = a1;
            *(uint4*)&Bs[buf][ar][ac] = b0; *(uint4*)&Bs[buf][ar][ac + 8] = b1;
            __syncthreads();
        }
    }
#pragma unroll
    for (int mt = 0; mt < 2; mt++) {
        int mrow = m0 + wm + mt * 16 + g;
        if (TOHALF) {
            __half* Ob = (__half*)Obv;
#pragma unroll
            for (int nt = 0; nt < 8; nt++) {
                int col = n0 + wn + nt * 8 + tg2;
                *(uint32_t*)(Ob + (size_t)mrow * L + col) = h2pack(acc[mt][nt][0], acc[mt][nt][1]);
                *(uint32_t*)(Ob + (size_t)(mrow + 8) * L + col) = h2pack(acc[mt][nt][2], acc[mt][nt][3]);
            }
        } else {
            float* Ob = (float*)Obv;
            float bv0 = bias[mrow], bv1 = bias[mrow + 8];
#pragma unroll
            for (int nt = 0; nt < 8; nt++) {
                int col = n0 + wn + nt * 8 + tg2;
                *(float2*)(Ob + (size_t)mrow * L + col) =
                    make_float2(acc[mt][nt][0] + bv0, acc[mt][nt][1] + bv0);
                *(float2*)(Ob + (size_t)(mrow + 8) * L + col) =
                    make_float2(acc[mt][nt][2] + bv1, acc[mt][nt][3] + bv1);
            }
        }
    }
}

__global__ void __launch_bounds__(256) qkv_h() {
    int z = blockIdx.z;
    int b = z / 3, which = z - 3 * b;
    const __half* A = which == 0 ? g_wqh : which == 1 ? g_wkh : g_wvh;
    const __half* Bx = (which == 2 ? g_x0T : g_x1T) + (size_t)b * L * C;
    __half* Ob = (which == 0 ? g_qh : which == 1 ? g_kh : g_vh) + (size_t)b * C * L;
    gemm_h<true>(A, Bx, Ob, nullptr, blockIdx.x * 128, blockIdx.y * 128);
}

__global__ void __launch_bounds__(256) dense_h(float* __restrict__ Out,
                                               const float* __restrict__ bias) {
    int b = blockIdx.z;
    gemm_h<false>(g_wdh, g_attT + (size_t)b * L * C, Out + (size_t)b * C * L,
                  bias, blockIdx.x * 128, blockIdx.y * 128);
}

// ---------------------------------------------------------------------------
// 3) Gate (f32, exact)
// ---------------------------------------------------------------------------
__global__ void __launch_bounds__(128) gate_kernel(const float* __restrict__ x,
                                                   const float* __restrict__ gate_w,
                                                   const float* __restrict__ gate_b) {
    __shared__ float ws[H * C];
    int n = blockIdx.y;
    int l = blockIdx.x * 128 + threadIdx.x;
    int t = threadIdx.x;
#pragma unroll
    for (int i = 0; i < H * C / (128 * 4); i++)
        *(float4*)&ws[(i * 128 + t) * 4] = *(const float4*)&gate_w[(i * 128 + t) * 4];
    __syncthreads();

    const float* xb = x + (size_t)n * C * L + l;
    float acc[H];
#pragma unroll
    for (int h = 0; h < H; h++) acc[h] = gate_b[h];
    for (int c = 0; c < C; c++) {
        float xv = xb[(size_t)c * L];
#pragma unroll
        for (int h = 0; h < H; h++)
            acc[h] = fmaf(ws[h * C + c], xv, acc[h]);
    }
#pragma unroll
    for (int h = 0; h < H; h++)
        g_gate[((size_t)n * H + h) * L + l] = acc[h];
}

// ---------------------------------------------------------------------------
// 4) Fused flash attention: Q/K/V consumed in natural [d][l] layout.
//    QK: A/B fragments via ldmatrix.trans. PV: non-trans.
// ---------------------------------------------------------------------------
constexpr int FQS = 0;          // [64][136] half
constexpr int FKS = 17408;      // [64][136]
constexpr int FVS = 34816;      // [64][136]
constexpr int FPS = 52224;      // [128][136]
constexpr int FREL = 87040;     // 256 f32
constexpr int FGM = 88064;      // 128 f32
constexpr int FBM = 88576;      // 256 f32
constexpr int FBS = 89600;      // 256 f32
constexpr int FA_B = 90624;

__global__ void __launch_bounds__(256) flash_h(const float* __restrict__ relpos,
                                               const float* __restrict__ mask,
                                               const float* __restrict__ norm) {
    extern __shared__ char sm[];
    __half* Qs = (__half*)(sm + FQS);
    __half* Ks = (__half*)(sm + FKS);
    __half* Vs = (__half*)(sm + FVS);
    __half* Ps = (__half*)(sm + FPS);
    float* rel_s = (float*)(sm + FREL);
    float* gm_s = (float*)(sm + FGM);
    float* bufM = (float*)(sm + FBM);
    float* bufS = (float*)(sm + FBS);

    int i0 = blockIdx.x * 128;
    int z = blockIdx.y;
    int n = z / H, h = z - n * H;
    const __half* Qb = g_qh + ((size_t)n * C + h * D) * L;
    const __half* Kb = g_kh + ((size_t)n * C + h * D) * L;
    const __half* Vb = g_vh + ((size_t)n * C + h * D) * L;
    float inv = 1.0f / norm[n];

    int t = threadIdx.x, w = t >> 5, lane = t & 31;
    int wm = (w >> 1) * 32, wn = (w & 1) * 64, wd = (w & 1) * 32;
    int g = lane >> 2, tg2 = (lane & 3) * 2;

    // ldmatrix lane address components
    int at_row = ((lane >> 4) & 1) * 8 + (lane & 7), at_col = ((lane >> 3) & 1) * 8;  // trans A
    int bt_row = ((lane >> 3) & 1) * 8 + (lane & 7), bt_col = ((lane >> 4) & 1) * 8;  // trans B
    int a_row = (lane & 15), a_col = (lane >> 4) * 8;                                  // plain A
    int b_row = ((lane >> 4) & 1) * 8 + (lane & 7), b_col = ((lane >> 3) & 1) * 8;     // plain B

    // Q tile [d][i]
    {
        int dd = t >> 2, cc = (t & 3) * 32;
        const uint4* s = (const uint4*)(Qb + (size_t)dd * L + i0 + cc);
        uint4* dq = (uint4*)(Qs + dd * 136 + cc);
        dq[0] = s[0]; dq[1] = s[1]; dq[2] = s[2]; dq[3] = s[3];
    }

    float Oacc[2][4][4] = {};
    float m_pr[2][2] = {{-1e30f, -1e30f}, {-1e30f, -1e30f}};
    float l_run[2][2] = {{0.f, 0.f}, {0.f, 0.f}};

    for (int jt = 0; jt < 3; jt++) {
        int j0 = jt * 128;
        {
            int dd = t >> 2, cc = (t & 3) * 32;
            const uint4* s = (const uint4*)(Kb + (size_t)dd * L + j0 + cc);
            uint4* dk = (uint4*)(Ks + dd * 136 + cc);
            dk[0] = s[0]; dk[1] = s[1]; dk[2] = s[2]; dk[3] = s[3];
            const uint4* sv = (const uint4*)(Vb + (size_t)dd * L + j0 + cc);
            uint4* dv = (uint4*)(Vs + dd * 136 + cc);
            dv[0] = sv[0]; dv[1] = sv[1]; dv[2] = sv[2]; dv[3] = sv[3];
        }
        if (t < 128)
            gm_s[t] = g_gate[(size_t)z * L + j0 + t] + mask[(size_t)n * L + j0 + t];
        rel_s[t] = relpos[min(257 + j0 - i0 + t, 2 * ME - 2)];
        __syncthreads();

        // ---- QK MMA (trans fragments from [d][*] tiles) ----
        float acc[2][8][4] = {};
#pragma unroll
        for (int ks = 0; ks < 64; ks += 16) {
            uint32_t af[2][4], bf[8][2];
#pragma unroll
            for (int mt = 0; mt < 2; mt++)
                ldsm4t(af[mt], smaddr(&Qs[(ks + at_row) * 136 + wm + mt * 16 + at_col]));
#pragma unroll
            for (int ntp = 0; ntp < 4; ntp++) {
                uint32_t rr[4];
                ldsm4t(rr, smaddr(&Ks[(ks + bt_row) * 136 + wn + ntp * 16 + bt_col]));
                bf[2 * ntp][0] = rr[0]; bf[2 * ntp][1] = rr[1];
                bf[2 * ntp + 1][0] = rr[2]; bf[2 * ntp + 1][1] = rr[3];
            }
#pragma unroll
            for (int mt = 0; mt < 2; mt++)
#pragma unroll
                for (int nt = 0; nt < 8; nt++)
                    mma16(acc[mt][nt], af[mt], bf[nt]);
        }

        // ---- bias + per-slot max ----
        float rmax[2][2];
#pragma unroll
        for (int mt = 0; mt < 2; mt++) {
            rmax[mt][0] = -1e30f; rmax[mt][1] = -1e30f;
            int rbase = wm + mt * 16 + g;
            int idx0 = 127 - rbase;
#pragma unroll
            for (int nt = 0; nt < 8; nt++) {
                int c0 = wn + nt * 8 + tg2;
                float gm0 = gm_s[c0], gm1 = gm_s[c0 + 1];
                float s00 = (acc[mt][nt][0] + rel_s[idx0 + c0] + gm0) * inv;
                float s01 = (acc[mt][nt][1] + rel_s[idx0 + c0 + 1] + gm1) * inv;
                float s10 = (acc[mt][nt][2] + rel_s[idx0 - 8 + c0] + gm0) * inv;
                float s11 = (acc[mt][nt][3] + rel_s[idx0 - 8 + c0 + 1] + gm1) * inv;
                acc[mt][nt][0] = s00; acc[mt][nt][1] = s01;
                acc[mt][nt][2] = s10; acc[mt][nt][3] = s11;
                rmax[mt][0] = fmaxf(rmax[mt][0], fmaxf(s00, s01));
                rmax[mt][1] = fmaxf(rmax[mt][1], fmaxf(s10, s11));
            }
        }
#pragma unroll
        for (int mt = 0; mt < 2; mt++)
#pragma unroll
            for (int hh = 0; hh < 2; hh++) {
                float v = rmax[mt][hh];
                v = fmaxf(v, __shfl_xor_sync(0xffffffff, v, 1));
                v = fmaxf(v, __shfl_xor_sync(0xffffffff, v, 2));
                rmax[mt][hh] = v;
            }
        if ((lane & 3) == 0) {
#pragma unroll
            for (int mt = 0; mt < 2; mt++)
#pragma unroll
                for (int hh = 0; hh < 2; hh++)
                    bufM[(w & 1) * 128 + wm + mt * 16 + g + hh * 8] = rmax[mt][hh];
        }
        __syncthreads();

        float fac[2][2], mnew[2][2];
#pragma unroll
        for (int mt = 0; mt < 2; mt++)
#pragma unroll
            for (int hh = 0; hh < 2; hh++) {
                int r = wm + mt * 16 + g + hh * 8;
                float tm = fmaxf(bufM[r], bufM[128 + r]);
                float mn = fmaxf(m_pr[mt][hh], tm);
                fac[mt][hh] = __expf(m_pr[mt][hh] - mn);
                mnew[mt][hh] = mn;
            }

        // ---- P = exp(S - m) -> Ps[i][j] half, partial sums ----
        float rsum[2][2] = {{0.f, 0.f}, {0.f, 0.f}};
#pragma unroll
        for (int mt = 0; mt < 2; mt++) {
            int rbase = wm + mt * 16 + g;
#pragma unroll
            for (int nt = 0; nt < 8; nt++) {
                int c0 = wn + nt * 8 + tg2;
                float p00 = __expf(acc[mt][nt][0] - mnew[mt][0]);
                float p01 = __expf(acc[mt][nt][1] - mnew[mt][0]);
                float p10 = __expf(acc[mt][nt][2] - mnew[mt][1]);
                float p11 = __expf(acc[mt][nt][3] - mnew[mt][1]);
                rsum[mt][0] += p00 + p01;
                rsum[mt][1] += p10 + p11;
                *(uint32_t*)&Ps[rbase * 136 + c0] = h2pack(p00, p01);
                *(uint32_t*)&Ps[(rbase + 8) * 136 + c0] = h2pack(p10, p11);
            }
        }
#pragma unroll
        for (int mt = 0; mt < 2; mt++)
#pragma unroll
            for (int hh = 0; hh < 2; hh++) {
                float v = rsum[mt][hh];
                v += __shfl_xor_sync(0xffffffff, v, 1);
                v += __shfl_xor_sync(0xffffffff, v, 2);
                rsum[mt][hh] = v;
            }
        if ((lane & 3) == 0) {
#pragma unroll
            for (int mt = 0; mt < 2; mt++)
#pragma unroll
                for (int hh = 0; hh < 2; hh++)
                    bufS[(w & 1) * 128 + wm + mt * 16 + g + hh * 8] = rsum[mt][hh];
        }
        __syncthreads();

#pragma unroll
        for (int mt = 0; mt < 2; mt++)
#pragma unroll
            for (int hh = 0; hh < 2; hh++) {
                int r = wm + mt * 16 + g + hh * 8;
                float ts = bufS[r] + bufS[128 + r];
                l_run[mt][hh] = l_run[mt][hh] * fac[mt][hh] + ts;
                m_pr[mt][hh] = mnew[mt][hh];
            }
#pragma unroll
        for (int mt = 0; mt < 2; mt++)
#pragma unroll
            for (int nt = 0; nt < 4; nt++) {
                Oacc[mt][nt][0] *= fac[mt][0]; Oacc[mt][nt][1] *= fac[mt][0];
                Oacc[mt][nt][2] *= fac[mt][1]; Oacc[mt][nt][3] *= fac[mt][1];
            }

        // ---- PV MMA: A = Ps[i][j] (plain), B = Vs[d][j] (plain) ----
#pragma unroll
        for (int ks = 0; ks < 128; ks += 16) {
            uint32_t af[2][4], bf[4][2];
#pragma unroll
            for (int mt = 0; mt < 2; mt++)
                ldsm4(af[mt], smaddr(&Ps[(wm + mt * 16 + a_row) * 136 + ks + a_col]));
#pragma unroll
            for (int ntp = 0; ntp < 2; ntp++) {
                uint32_t rr[4];
                ldsm4(rr, smaddr(&Vs[(wd + ntp * 16 + b_row) * 136 + ks + b_col]));
                bf[2 * ntp][0] = rr[0]; bf[2 * ntp][1] = rr[1];
                bf[2 * ntp + 1][0] = rr[2]; bf[2 * ntp + 1][1] = rr[3];
            }
#pragma unroll
            for (int mt = 0; mt < 2; mt++)
#pragma unroll
                for (int nt = 0; nt < 4; nt++)
                    mma16(Oacc[mt][nt], af[mt], bf[nt]);
        }
        __syncthreads();
    }

    // finalize: attT[n][i][h*64 + d] = half(O / l)
    __half* Ob = g_attT + (size_t)n * L * C;
#pragma unroll
    for (int mt = 0; mt < 2; mt++) {
        float r0 = 1.0f / l_run[mt][0];
        float r1 = 1.0f / l_run[mt][1];
        int irow = i0 + wm + mt * 16 + g;
#pragma unroll
        for (int nt = 0; nt < 4; nt++) {
            int dc = h * 64 + wd + nt * 8 + tg2;
            *(uint32_t*)(Ob + (size_t)irow * C + dc) =
                h2pack(Oacc[mt][nt][0] * r0, Oacc[mt][nt][1] * r0);
            *(uint32_t*)(Ob + (size_t)(irow + 8) * C + dc) =
                h2pack(Oacc[mt][nt][2] * r1, Oacc[mt][nt][3] * r1);
        }
    }
}

// ---------------------------------------------------------------------------
// Launch
// ---------------------------------------------------------------------------
extern "C" void kernel_launch(void* const* d_in, const int* in_sizes, int n_in,
                              void* d_out, int out_size) {
    const float* x        = (const float*)d_in[0];
    const float* xorg     = (const float*)d_in[1];
    const float* abspos   = (const float*)d_in[2];
    const float* mask     = (const float*)d_in[3];
    const float* norm     = (const float*)d_in[4];
    const float* qkpos    = (const float*)d_in[5];
    const float* qkorg    = (const float*)d_in[6];
    const float* vorg     = (const float*)d_in[7];
    const float* relpos   = (const float*)d_in[8];
    const float* gate_w   = (const float*)d_in[9];
    const float* gate_b   = (const float*)d_in[10];
    const float* q_w      = (const float*)d_in[11];
    const float* k_w      = (const float*)d_in[12];
    const float* v_w      = (const float*)d_in[13];
    const float* dense_w  = (const float*)d_in[14];
    const float* dense_b  = (const float*)d_in[15];
    float* out = (float*)d_out;

    cudaFuncSetAttribute(flash_h, cudaFuncAttributeMaxDynamicSharedMemorySize, FA_B);

    prep_t<<<dim3(12, 16, NB), dim3(32, 8)>>>(x, xorg, abspos, qkpos, qkorg, vorg);
    round_w_h<<<512, 256>>>(q_w, k_w, v_w, dense_w);

    gate_kernel<<<dim3(3, NB), 128>>>(x, gate_w, gate_b);

    qkv_h<<<dim3(4, 3, NB * 3), 256>>>();

    flash_h<<<dim3(3, NB * H), 256, FA_B>>>(relpos, mask, norm);

    dense_h<<<dim3(4, 3, NB), 256>>>(out, dense_b);
}

// round 10
// speedup vs baseline: 4.1400x; 1.1316x over previous
#include <cuda_runtime.h>
#include <cuda_fp16.h>
#include <math.h>
#include <stdint.h>

constexpr int NB = 16, C = 512, L = 384, H = 8, D = 64, ME = 384;

__device__ __half g_x0T[NB * L * C];
__device__ __half g_x1T[NB * L * C];
__device__ __half g_wqh[C * C], g_wkh[C * C], g_wvh[C * C], g_wdh[C * C];
__device__ __half g_qh[NB * C * L], g_kh[NB * C * L], g_vh[NB * C * L];
__device__ __half g_attT[NB * L * C];
__device__ float g_gate[NB * H * L];

// ---------------------------------------------------------------------------
// helpers
// ---------------------------------------------------------------------------
__device__ __forceinline__ uint32_t h2pack(float lo, float hi) {
    uint32_t u;
    asm("cvt.rn.f16x2.f32 %0, %1, %2;" : "=r"(u) : "f"(hi), "f"(lo));
    return u;
}

__device__ __forceinline__ void mma16(float* c, const uint32_t* a, const uint32_t* b) {
    asm("mma.sync.aligned.m16n8k16.row.col.f32.f16.f16.f32 "
        "{%0,%1,%2,%3}, {%4,%5,%6,%7}, {%8,%9}, {%0,%1,%2,%3};"
        : "+f"(c[0]), "+f"(c[1]), "+f"(c[2]), "+f"(c[3])
        : "r"(a[0]), "r"(a[1]), "r"(a[2]), "r"(a[3]), "r"(b[0]), "r"(b[1]));
}

__device__ __forceinline__ uint32_t smaddr(const void* p) {
    return (uint32_t)__cvta_generic_to_shared(p);
}
__device__ __forceinline__ void ldsm4(uint32_t* r, uint32_t a) {
    asm volatile("ldmatrix.sync.aligned.m8n8.x4.shared.b16 {%0,%1,%2,%3}, [%4];"
                 : "=r"(r[0]), "=r"(r[1]), "=r"(r[2]), "=r"(r[3]) : "r"(a));
}
__device__ __forceinline__ void ldsm4t(uint32_t* r, uint32_t a) {
    asm volatile("ldmatrix.sync.aligned.m8n8.x4.trans.shared.b16 {%0,%1,%2,%3}, [%4];"
                 : "=r"(r[0]), "=r"(r[1]), "=r"(r[2]), "=r"(r[3]) : "r"(a));
}
__device__ __forceinline__ void cpa16(uint32_t dst, const void* src) {
    asm volatile("cp.async.cg.shared.global [%0], [%1], 16;" :: "r"(dst), "l"(src));
}
__device__ __forceinline__ void cpa_commit() { asm volatile("cp.async.commit_group;"); }
__device__ __forceinline__ void cpa_wait0() {
    asm volatile("cp.async.wait_group 0;" ::: "memory");
}

// ---------------------------------------------------------------------------
// 1) Fused preprocess + transpose: x0T/x1T[n][l][c] (half)
// ---------------------------------------------------------------------------
__global__ void __launch_bounds__(256) prep_t(const float* __restrict__ x,
                                              const float* __restrict__ xorg,
                                              const float* __restrict__ abspos,
                                              const float* __restrict__ qkpos,
                                              const float* __restrict__ qkorg,
                                              const float* __restrict__ vorg) {
    __shared__ float t0[32][33], t1[32][33];
    int n = blockIdx.z, ct = blockIdx.y, lt = blockIdx.x;
    int tx = threadIdx.x, ty = threadIdx.y;
#pragma unroll
    for (int s = 0; s < 4; s++) {
        int c = ct * 32 + ty + 8 * s;
        int l = lt * 32 + tx;
        size_t idx = ((size_t)n * C + c) * L + l;
        int gg = c >> 3;
        float xv = x[idx], xo = xorg[idx], ap = abspos[idx];
        t0[ty + 8 * s][tx] = xv + xo * vorg[gg];
        t1[ty + 8 * s][tx] = xv + xo * qkorg[gg] + ap * qkpos[gg];
    }
    __syncthreads();
#pragma unroll
    for (int s = 0; s < 4; s++) {
        int l = lt * 32 + ty + 8 * s;
        int c = ct * 32 + tx;
        size_t o = ((size_t)n * L + l) * C + c;
        g_x0T[o] = __float2half_rn(t0[tx][ty + 8 * s]);
        g_x1T[o] = __float2half_rn(t1[tx][ty + 8 * s]);
    }
}

// 1b) round weights to half
__global__ void round_w_h(const float* __restrict__ q, const float* __restrict__ k,
                          const float* __restrict__ v, const float* __restrict__ d) {
    int i = blockIdx.x * blockDim.x + threadIdx.x;
    int mat = i >> 15;
    int j = (i & 32767) * 8;
    const float* s = mat == 0 ? q : mat == 1 ? k : mat == 2 ? v : d;
    __half* dst = mat == 0 ? g_wqh : mat == 1 ? g_wkh : mat == 2 ? g_wvh : g_wdh;
    float4 f0 = *(const float4*)(s + j);
    float4 f1 = *(const float4*)(s + j + 4);
    uint4 o;
    o.x = h2pack(f0.x, f0.y); o.y = h2pack(f0.z, f0.w);
    o.z = h2pack(f1.x, f1.y); o.w = h2pack(f1.z, f1.w);
    *(uint4*)(dst + j) = o;
}

// ---------------------------------------------------------------------------
// f16 GEMM core (ldmatrix + cp.async): Out[m][l] = sum_k A[m][k] * B[l][k]
// ---------------------------------------------------------------------------
template <bool TOHALF>
__device__ __forceinline__ void gemm_h(const __half* __restrict__ A,
                                       const __half* __restrict__ Bx,
                                       void* Obv, const float* __restrict__ bias,
                                       int m0, int n0) {
    __shared__ __half As[2][128][40];
    __shared__ __half Bs[2][128][40];
    int t = threadIdx.x;
    int ar = t >> 1, ac = (t & 1) * 16;
    const __half* Ap = A + (size_t)(m0 + ar) * C + ac;
    const __half* Bp = Bx + (size_t)(n0 + ar) * C + ac;
    int w = t >> 5, lane = t & 31;
    int wm = (w >> 1) * 32, wn = (w & 1) * 64;
    int g = lane >> 2, tg2 = (lane & 3) * 2;

    float acc[2][8][4] = {};

    // issue slab 0
    {
        uint32_t ad = smaddr(&As[0][ar][ac]);
        uint32_t bd = smaddr(&Bs[0][ar][ac]);
        cpa16(ad, Ap); cpa16(ad + 16, Ap + 8);
        cpa16(bd, Bp); cpa16(bd + 16, Bp + 8);
        cpa_commit();
    }

    int a_row = (lane & 15), a_col = (lane >> 4) * 8;
    int b_row = ((lane >> 4) & 1) * 8 + (lane & 7), b_col = ((lane >> 3) & 1) * 8;

    int buf = 0;
    for (int k0 = 0; k0 < C; k0 += 32) {
        cpa_wait0();
        __syncthreads();           // slab resident + all warps done with buf^1
        if (k0 + 32 < C) {
            uint32_t ad = smaddr(&As[buf ^ 1][ar][ac]);
            uint32_t bd = smaddr(&Bs[buf ^ 1][ar][ac]);
            cpa16(ad, Ap + k0 + 32); cpa16(ad + 16, Ap + k0 + 40);
            cpa16(bd, Bp + k0 + 32); cpa16(bd + 16, Bp + k0 + 40);
            cpa_commit();
        }
#pragma unroll
        for (int ks = 0; ks < 32; ks += 16) {
            uint32_t af[2][4], bf[8][2];
#pragma unroll
            for (int mt = 0; mt < 2; mt++)
                ldsm4(af[mt], smaddr(&As[buf][wm + mt * 16 + a_row][ks + a_col]));
#pragma unroll
            for (int ntp = 0; ntp < 4; ntp++) {
                uint32_t rr[4];
                ldsm4(rr, smaddr(&Bs[buf][wn + ntp * 16 + b_row][ks + b_col]));
                bf[2 * ntp][0] = rr[0]; bf[2 * ntp][1] = rr[1];
                bf[2 * ntp + 1][0] = rr[2]; bf[2 * ntp + 1][1] = rr[3];
            }
#pragma unroll
            for (int mt = 0; mt < 2; mt++)
#pragma unroll
                for (int nt = 0; nt < 8; nt++)
                    mma16(acc[mt][nt], af[mt], bf[nt]);
        }
        buf ^= 1;
    }
#pragma unroll
    for (int mt = 0; mt < 2; mt++) {
        int mrow = m0 + wm + mt * 16 + g;
        if (TOHALF) {
            __half* Ob = (__half*)Obv;
#pragma unroll
            for (int nt = 0; nt < 8; nt++) {
                int col = n0 + wn + nt * 8 + tg2;
                *(uint32_t*)(Ob + (size_t)mrow * L + col) = h2pack(acc[mt][nt][0], acc[mt][nt][1]);
                *(uint32_t*)(Ob + (size_t)(mrow + 8) * L + col) = h2pack(acc[mt][nt][2], acc[mt][nt][3]);
            }
        } else {
            float* Ob = (float*)Obv;
            float bv0 = bias[mrow], bv1 = bias[mrow + 8];
#pragma unroll
            for (int nt = 0; nt < 8; nt++) {
                int col = n0 + wn + nt * 8 + tg2;
                *(float2*)(Ob + (size_t)mrow * L + col) =
                    make_float2(acc[mt][nt][0] + bv0, acc[mt][nt][1] + bv0);
                *(float2*)(Ob + (size_t)(mrow + 8) * L + col) =
                    make_float2(acc[mt][nt][2] + bv1, acc[mt][nt][3] + bv1);
            }
        }
    }
}

__global__ void __launch_bounds__(256, 2) qkv_h() {
    int z = blockIdx.z;
    int b = z / 3, which = z - 3 * b;
    const __half* A = which == 0 ? g_wqh : which == 1 ? g_wkh : g_wvh;
    const __half* Bx = (which == 2 ? g_x0T : g_x1T) + (size_t)b * L * C;
    __half* Ob = (which == 0 ? g_qh : which == 1 ? g_kh : g_vh) + (size_t)b * C * L;
    gemm_h<true>(A, Bx, Ob, nullptr, blockIdx.x * 128, blockIdx.y * 128);
}

__global__ void __launch_bounds__(256, 2) dense_h(float* __restrict__ Out,
                                                  const float* __restrict__ bias) {
    int b = blockIdx.z;
    gemm_h<false>(g_wdh, g_attT + (size_t)b * L * C, Out + (size_t)b * C * L,
                  bias, blockIdx.x * 128, blockIdx.y * 128);
}

// ---------------------------------------------------------------------------
// 3) Gate (f32, exact)
// ---------------------------------------------------------------------------
__global__ void __launch_bounds__(128) gate_kernel(const float* __restrict__ x,
                                                   const float* __restrict__ gate_w,
                                                   const float* __restrict__ gate_b) {
    __shared__ float ws[H * C];
    int n = blockIdx.y;
    int l = blockIdx.x * 128 + threadIdx.x;
    int t = threadIdx.x;
#pragma unroll
    for (int i = 0; i < H * C / (128 * 4); i++)
        *(float4*)&ws[(i * 128 + t) * 4] = *(const float4*)&gate_w[(i * 128 + t) * 4];
    __syncthreads();

    const float* xb = x + (size_t)n * C * L + l;
    float acc[H];
#pragma unroll
    for (int h = 0; h < H; h++) acc[h] = gate_b[h];
    for (int c = 0; c < C; c++) {
        float xv = xb[(size_t)c * L];
#pragma unroll
        for (int h = 0; h < H; h++)
            acc[h] = fmaf(ws[h * C + c], xv, acc[h]);
    }
#pragma unroll
    for (int h = 0; h < H; h++)
        g_gate[((size_t)n * H + h) * L + l] = acc[h];
}

// ---------------------------------------------------------------------------
// 4) Fused flash attention
// ---------------------------------------------------------------------------
constexpr int FQS = 0;          // [64][136] half
constexpr int FKS = 17408;
constexpr int FVS = 34816;
constexpr int FPS = 52224;      // [128][136]
constexpr int FREL = 87040;
constexpr int FGM = 88064;
constexpr int FBM = 88576;
constexpr int FBS = 89600;
constexpr int FA_B = 90624;

__global__ void __launch_bounds__(256) flash_h(const float* __restrict__ relpos,
                                               const float* __restrict__ mask,
                                               const float* __restrict__ norm) {
    extern __shared__ char sm[];
    __half* Qs = (__half*)(sm + FQS);
    __half* Ks = (__half*)(sm + FKS);
    __half* Vs = (__half*)(sm + FVS);
    __half* Ps = (__half*)(sm + FPS);
    float* rel_s = (float*)(sm + FREL);
    float* gm_s = (float*)(sm + FGM);
    float* bufM = (float*)(sm + FBM);
    float* bufS = (float*)(sm + FBS);

    int i0 = blockIdx.x * 128;
    int z = blockIdx.y;
    int n = z / H, h = z - n * H;
    const __half* Qb = g_qh + ((size_t)n * C + h * D) * L;
    const __half* Kb = g_kh + ((size_t)n * C + h * D) * L;
    const __half* Vb = g_vh + ((size_t)n * C + h * D) * L;
    float inv = 1.0f / norm[n];

    int t = threadIdx.x, w = t >> 5, lane = t & 31;
    int wm = (w >> 1) * 32, wn = (w & 1) * 64, wd = (w & 1) * 32;
    int g = lane >> 2, tg2 = (lane & 3) * 2;

    int at_row = ((lane >> 4) & 1) * 8 + (lane & 7), at_col = ((lane >> 3) & 1) * 8;
    int bt_row = ((lane >> 3) & 1) * 8 + (lane & 7), bt_col = ((lane >> 4) & 1) * 8;
    int a_row = (lane & 15), a_col = (lane >> 4) * 8;
    int b_row = ((lane >> 4) & 1) * 8 + (lane & 7), b_col = ((lane >> 3) & 1) * 8;

    {
        int dd = t >> 2, cc = (t & 3) * 32;
        uint32_t dq = smaddr(Qs + dd * 136 + cc);
        const __half* s = Qb + (size_t)dd * L + i0 + cc;
        cpa16(dq, s); cpa16(dq + 16, s + 8);
        cpa16(dq + 32, s + 16); cpa16(dq + 48, s + 24);
        cpa_commit();
    }

    float Oacc[2][4][4] = {};
    float m_pr[2][2] = {{-1e30f, -1e30f}, {-1e30f, -1e30f}};
    float l_run[2][2] = {{0.f, 0.f}, {0.f, 0.f}};

    for (int jt = 0; jt < 3; jt++) {
        int j0 = jt * 128;
        {
            int dd = t >> 2, cc = (t & 3) * 32;
            uint32_t dk = smaddr(Ks + dd * 136 + cc);
            const __half* s = Kb + (size_t)dd * L + j0 + cc;
            cpa16(dk, s); cpa16(dk + 16, s + 8);
            cpa16(dk + 32, s + 16); cpa16(dk + 48, s + 24);
            uint32_t dv = smaddr(Vs + dd * 136 + cc);
            const __half* sv = Vb + (size_t)dd * L + j0 + cc;
            cpa16(dv, sv); cpa16(dv + 16, sv + 8);
            cpa16(dv + 32, sv + 16); cpa16(dv + 48, sv + 24);
            cpa_commit();
        }
        if (t < 128)
            gm_s[t] = g_gate[(size_t)z * L + j0 + t] + mask[(size_t)n * L + j0 + t];
        rel_s[t] = relpos[min(257 + j0 - i0 + t, 2 * ME - 2)];
        cpa_wait0();
        __syncthreads();

        // ---- QK MMA ----
        float acc[2][8][4] = {};
#pragma unroll
        for (int ks = 0; ks < 64; ks += 16) {
            uint32_t af[2][4], bf[8][2];
#pragma unroll
            for (int mt = 0; mt < 2; mt++)
                ldsm4t(af[mt], smaddr(&Qs[(ks + at_row) * 136 + wm + mt * 16 + at_col]));
#pragma unroll
            for (int ntp = 0; ntp < 4; ntp++) {
                uint32_t rr[4];
                ldsm4t(rr, smaddr(&Ks[(ks + bt_row) * 136 + wn + ntp * 16 + bt_col]));
                bf[2 * ntp][0] = rr[0]; bf[2 * ntp][1] = rr[1];
                bf[2 * ntp + 1][0] = rr[2]; bf[2 * ntp + 1][1] = rr[3];
            }
#pragma unroll
            for (int mt = 0; mt < 2; mt++)
#pragma unroll
                for (int nt = 0; nt < 8; nt++)
                    mma16(acc[mt][nt], af[mt], bf[nt]);
        }

        // ---- bias + per-slot max ----
        float rmax[2][2];
#pragma unroll
        for (int mt = 0; mt < 2; mt++) {
            rmax[mt][0] = -1e30f; rmax[mt][1] = -1e30f;
            int rbase = wm + mt * 16 + g;
            int idx0 = 127 - rbase;
#pragma unroll
            for (int nt = 0; nt < 8; nt++) {
                int c0 = wn + nt * 8 + tg2;
                float gm0 = gm_s[c0], gm1 = gm_s[c0 + 1];
                float s00 = (acc[mt][nt][0] + rel_s[idx0 + c0] + gm0) * inv;
                float s01 = (acc[mt][nt][1] + rel_s[idx0 + c0 + 1] + gm1) * inv;
                float s10 = (acc[mt][nt][2] + rel_s[idx0 - 8 + c0] + gm0) * inv;
                float s11 = (acc[mt][nt][3] + rel_s[idx0 - 8 + c0 + 1] + gm1) * inv;
                acc[mt][nt][0] = s00; acc[mt][nt][1] = s01;
                acc[mt][nt][2] = s10; acc[mt][nt][3] = s11;
                rmax[mt][0] = fmaxf(rmax[mt][0], fmaxf(s00, s01));
                rmax[mt][1] = fmaxf(rmax[mt][1], fmaxf(s10, s11));
            }
        }
#pragma unroll
        for (int mt = 0; mt < 2; mt++)
#pragma unroll
            for (int hh = 0; hh < 2; hh++) {
                float v = rmax[mt][hh];
                v = fmaxf(v, __shfl_xor_sync(0xffffffff, v, 1));
                v = fmaxf(v, __shfl_xor_sync(0xffffffff, v, 2));
                rmax[mt][hh] = v;
            }
        if ((lane & 3) == 0) {
#pragma unroll
            for (int mt = 0; mt < 2; mt++)
#pragma unroll
                for (int hh = 0; hh < 2; hh++)
                    bufM[(w & 1) * 128 + wm + mt * 16 + g + hh * 8] = rmax[mt][hh];
        }
        __syncthreads();

        float fac[2][2], mnew[2][2];
#pragma unroll
        for (int mt = 0; mt < 2; mt++)
#pragma unroll
            for (int hh = 0; hh < 2; hh++) {
                int r = wm + mt * 16 + g + hh * 8;
                float tm = fmaxf(bufM[r], bufM[128 + r]);
                float mn = fmaxf(m_pr[mt][hh], tm);
                fac[mt][hh] = __expf(m_pr[mt][hh] - mn);
                mnew[mt][hh] = mn;
            }

        // ---- P = exp(S - m) -> Ps, partial sums ----
        float rsum[2][2] = {{0.f, 0.f}, {0.f, 0.f}};
#pragma unroll
        for (int mt = 0; mt < 2; mt++) {
            int rbase = wm + mt * 16 + g;
#pragma unroll
            for (int nt = 0; nt < 8; nt++) {
                int c0 = wn + nt * 8 + tg2;
                float p00 = __expf(acc[mt][nt][0] - mnew[mt][0]);
                float p01 = __expf(acc[mt][nt][1] - mnew[mt][0]);
                float p10 = __expf(acc[mt][nt][2] - mnew[mt][1]);
                float p11 = __expf(acc[mt][nt][3] - mnew[mt][1]);
                rsum[mt][0] += p00 + p01;
                rsum[mt][1] += p10 + p11;
                *(uint32_t*)&Ps[rbase * 136 + c0] = h2pack(p00, p01);
                *(uint32_t*)&Ps[(rbase + 8) * 136 + c0] = h2pack(p10, p11);
            }
        }
#pragma unroll
        for (int mt = 0; mt < 2; mt++)
#pragma unroll
            for (int hh = 0; hh < 2; hh++) {
                float v = rsum[mt][hh];
                v += __shfl_xor_sync(0xffffffff, v, 1);
                v += __shfl_xor_sync(0xffffffff, v, 2);
                rsum[mt][hh] = v;
            }
        if ((lane & 3) == 0) {
#pragma unroll
            for (int mt = 0; mt < 2; mt++)
#pragma unroll
                for (int hh = 0; hh < 2; hh++)
                    bufS[(w & 1) * 128 + wm + mt * 16 + g + hh * 8] = rsum[mt][hh];
        }
        __syncthreads();

#pragma unroll
        for (int mt = 0; mt < 2; mt++)
#pragma unroll
            for (int hh = 0; hh < 2; hh++) {
                int r = wm + mt * 16 + g + hh * 8;
                float ts = bufS[r] + bufS[128 + r];
                l_run[mt][hh] = l_run[mt][hh] * fac[mt][hh] + ts;
                m_pr[mt][hh] = mnew[mt][hh];
            }
#pragma unroll
        for (int mt = 0; mt < 2; mt++)
#pragma unroll
            for (int nt = 0; nt < 4; nt++) {
                Oacc[mt][nt][0] *= fac[mt][0]; Oacc[mt][nt][1] *= fac[mt][0];
                Oacc[mt][nt][2] *= fac[mt][1]; Oacc[mt][nt][3] *= fac[mt][1];
            }

        // ---- PV MMA ----
#pragma unroll
        for (int ks = 0; ks < 128; ks += 16) {
            uint32_t af[2][4], bf[4][2];
#pragma unroll
            for (int mt = 0; mt < 2; mt++)
                ldsm4(af[mt], smaddr(&Ps[(wm + mt * 16 + a_row) * 136 + ks + a_col]));
#pragma unroll
            for (int ntp = 0; ntp < 2; ntp++) {
                uint32_t rr[4];
                ldsm4(rr, smaddr(&Vs[(wd + ntp * 16 + b_row) * 136 + ks + b_col]));
                bf[2 * ntp][0] = rr[0]; bf[2 * ntp][1] = rr[1];
                bf[2 * ntp + 1][0] = rr[2]; bf[2 * ntp + 1][1] = rr[3];
            }
#pragma unroll
            for (int mt = 0; mt < 2; mt++)
#pragma unroll
                for (int nt = 0; nt < 4; nt++)
                    mma16(Oacc[mt][nt], af[mt], bf[nt]);
        }
        __syncthreads();
    }

    __half* Ob = g_attT + (size_t)n * L * C;
#pragma unroll
    for (int mt = 0; mt < 2; mt++) {
        float r0 = 1.0f / l_run[mt][0];
        float r1 = 1.0f / l_run[mt][1];
        int irow = i0 + wm + mt * 16 + g;
#pragma unroll
        for (int nt = 0; nt < 4; nt++) {
            int dc = h * 64 + wd + nt * 8 + tg2;
            *(uint32_t*)(Ob + (size_t)irow * C + dc) =
                h2pack(Oacc[mt][nt][0] * r0, Oacc[mt][nt][1] * r0);
            *(uint32_t*)(Ob + (size_t)(irow + 8) * C + dc) =
                h2pack(Oacc[mt][nt][2] * r1, Oacc[mt][nt][3] * r1);
        }
    }
}

// ---------------------------------------------------------------------------
// Launch
// ---------------------------------------------------------------------------
extern "C" void kernel_launch(void* const* d_in, const int* in_sizes, int n_in,
                              void* d_out, int out_size) {
    const float* x        = (const float*)d_in[0];
    const float* xorg     = (const float*)d_in[1];
    const float* abspos   = (const float*)d_in[2];
    const float* mask     = (const float*)d_in[3];
    const float* norm     = (const float*)d_in[4];
    const float* qkpos    = (const float*)d_in[5];
    const float* qkorg    = (const float*)d_in[6];
    const float* vorg     = (const float*)d_in[7];
    const float* relpos   = (const float*)d_in[8];
    const float* gate_w   = (const float*)d_in[9];
    const float* gate_b   = (const float*)d_in[10];
    const float* q_w      = (const float*)d_in[11];
    const float* k_w      = (const float*)d_in[12];
    const float* v_w      = (const float*)d_in[13];
    const float* dense_w  = (const float*)d_in[14];
    const float* dense_b  = (const float*)d_in[15];
    float* out = (float*)d_out;

    cudaFuncSetAttribute(flash_h, cudaFuncAttributeMaxDynamicSharedMemorySize, FA_B);

    prep_t<<<dim3(12, 16, NB), dim3(32, 8)>>>(x, xorg, abspos, qkpos, qkorg, vorg);
    round_w_h<<<512, 256>>>(q_w, k_w, v_w, dense_w);

    gate_kernel<<<dim3(3, NB), 128>>>(x, gate_w, gate_b);

    qkv_h<<<dim3(4, 3, NB * 3), 256>>>();

    flash_h<<<dim3(3, NB * H), 256, FA_B>>>(relpos, mask, norm);

    dense_h<<<dim3(4, 3, NB), 256>>>(out, dense_b);
}